// round 1
// baseline (speedup 1.0000x reference)
#include <cuda_runtime.h>
#include <math.h>

// Problem constants
#define BB 2
#define SS 2048
#define HH 2048
#define NH 16
#define NKV 4
#define HD 128
#define NREP (NH / NKV)
#define M_TOK (BB * SS)          // 4096 tokens
#define SCALE_F 0.08838834764831845f  // 1/sqrt(128)

// Scratch (static __device__ allocations are allowed)
__device__ float g_q[M_TOK * NH * HD];    // [M, NH, HD]  33.5 MB
__device__ float g_k[M_TOK * NKV * HD];   // [M, NKV, HD]  8.4 MB
__device__ float g_v[M_TOK * NKV * HD];   //               8.4 MB
__device__ float g_ao[M_TOK * NH * HD];   // attention out 33.5 MB

// ---------------------------------------------------------------------------
// SGEMM: C[M,N] = A[M,K] @ W[N,K]^T (+ bias[N])
// 128x128 tile, BK=16, 256 threads, 8x8 per-thread microtile.
// M, N, K must be multiples of 128/128/16 (true for all calls here).
// ---------------------------------------------------------------------------
__global__ __launch_bounds__(256) void sgemm_bias_kernel(
    const float* __restrict__ A, const float* __restrict__ W,
    const float* __restrict__ bias, float* __restrict__ C,
    int M, int N, int K)
{
    __shared__ float As[16][132];
    __shared__ float Ws[16][132];

    const int tid = threadIdx.x;
    const int tx = tid & 15;      // 0..15 -> N direction
    const int ty = tid >> 4;      // 0..15 -> M direction
    const int row0 = blockIdx.y * 128;
    const int col0 = blockIdx.x * 128;

    const int lr = tid >> 2;          // 0..63   load row
    const int lc = (tid & 3) << 2;    // 0,4,8,12 load col (k)

    const float* Aptr = A + (row0 + lr) * K + lc;
    const float* Wptr = W + (col0 + lr) * K + lc;

    float acc[8][8];
#pragma unroll
    for (int i = 0; i < 8; i++)
#pragma unroll
        for (int j = 0; j < 8; j++) acc[i][j] = 0.0f;

    for (int k0 = 0; k0 < K; k0 += 16) {
        float4 a0 = *(const float4*)(Aptr + k0);
        float4 a1 = *(const float4*)(Aptr + 64 * K + k0);
        float4 w0 = *(const float4*)(Wptr + k0);
        float4 w1 = *(const float4*)(Wptr + 64 * K + k0);

        __syncthreads();   // previous iteration's compute done
        As[lc + 0][lr] = a0.x; As[lc + 1][lr] = a0.y;
        As[lc + 2][lr] = a0.z; As[lc + 3][lr] = a0.w;
        As[lc + 0][lr + 64] = a1.x; As[lc + 1][lr + 64] = a1.y;
        As[lc + 2][lr + 64] = a1.z; As[lc + 3][lr + 64] = a1.w;
        Ws[lc + 0][lr] = w0.x; Ws[lc + 1][lr] = w0.y;
        Ws[lc + 2][lr] = w0.z; Ws[lc + 3][lr] = w0.w;
        Ws[lc + 0][lr + 64] = w1.x; Ws[lc + 1][lr + 64] = w1.y;
        Ws[lc + 2][lr + 64] = w1.z; Ws[lc + 3][lr + 64] = w1.w;
        __syncthreads();

#pragma unroll
        for (int k = 0; k < 16; k++) {
            float4 aA = *(const float4*)&As[k][ty * 8];
            float4 aB = *(const float4*)&As[k][ty * 8 + 4];
            float4 wA = *(const float4*)&Ws[k][tx * 8];
            float4 wB = *(const float4*)&Ws[k][tx * 8 + 4];
            float ar[8] = {aA.x, aA.y, aA.z, aA.w, aB.x, aB.y, aB.z, aB.w};
            float wr[8] = {wA.x, wA.y, wA.z, wA.w, wB.x, wB.y, wB.z, wB.w};
#pragma unroll
            for (int i = 0; i < 8; i++)
#pragma unroll
                for (int j = 0; j < 8; j++)
                    acc[i][j] = fmaf(ar[i], wr[j], acc[i][j]);
        }
    }

    float bb[8];
#pragma unroll
    for (int j = 0; j < 8; j++)
        bb[j] = bias ? bias[col0 + tx * 8 + j] : 0.0f;

#pragma unroll
    for (int i = 0; i < 8; i++) {
        int r = row0 + ty * 8 + i;
#pragma unroll
        for (int j = 0; j < 8; j += 4) {
            float4 v;
            v.x = acc[i][j + 0] + bb[j + 0];
            v.y = acc[i][j + 1] + bb[j + 1];
            v.z = acc[i][j + 2] + bb[j + 2];
            v.w = acc[i][j + 3] + bb[j + 3];
            *(float4*)&C[r * N + col0 + tx * 8 + j] = v;
        }
    }
}

// ---------------------------------------------------------------------------
// RoPE in place on x: [M_TOK, nheads, HD]. cos/sin: [M_TOK, HD].
// One thread per (token, head, d<64) pair; writes both halves.
// ---------------------------------------------------------------------------
__global__ void rope_kernel(float* __restrict__ x,
                            const float* __restrict__ cosp,
                            const float* __restrict__ sinp,
                            int nheads, int total)
{
    int i = blockIdx.x * blockDim.x + threadIdx.x;
    if (i >= total) return;
    int d   = i & 63;
    int t2  = i >> 6;
    int hh  = t2 % nheads;
    int tok = t2 / nheads;
    float* p = x + (tok * nheads + hh) * HD;
    float x1 = p[d];
    float x2 = p[d + 64];
    const float* cp = cosp + tok * HD;
    const float* sp = sinp + tok * HD;
    float c1 = cp[d], s1 = sp[d];
    float c2 = cp[d + 64], s2 = sp[d + 64];
    p[d]      = x1 * c1 - x2 * s1;
    p[d + 64] = x2 * c2 + x1 * s2;
}

// ---------------------------------------------------------------------------
// Flash attention (causal, GQA). fp32 SIMT.
// Block: 256 threads handles BQ=64 query rows for one (b, h).
// KV tiles of 64, K and V share one smem buffer.
// ---------------------------------------------------------------------------
#define BQ 64
#define BKV 64
#define QSTR 132   // row stride (floats) for Qs/KVs
#define PSTR 68    // row stride for Ps

extern __shared__ float fsm[];

__global__ __launch_bounds__(256) void flash_kernel(
    const float* __restrict__ Qg, const float* __restrict__ Kg,
    const float* __restrict__ Vg, float* __restrict__ Og)
{
    float* Qs   = fsm;                       // 64*132
    float* KVs  = Qs  + BQ * QSTR;           // 64*132
    float* Ps   = KVs + BKV * QSTR;          // 64*68
    float* sm_m = Ps  + BQ * PSTR;           // 64
    float* sm_l = sm_m + BQ;                 // 64
    float* sm_a = sm_l + BQ;                 // 64

    const int it = blockIdx.x;     // query tile index
    const int h  = blockIdx.y;
    const int b  = blockIdx.z;
    const int g  = h / NREP;
    const int tid = threadIdx.x;
    const int i0 = it * BQ;
    const int m0 = b * SS + i0;

    // Load Q tile (pre-scaled)
    for (int idx = tid; idx < BQ * 32; idx += 256) {
        int r = idx >> 5, c = (idx & 31) << 2;
        float4 v = *(const float4*)&Qg[((m0 + r) * NH + h) * HD + c];
        v.x *= SCALE_F; v.y *= SCALE_F; v.z *= SCALE_F; v.w *= SCALE_F;
        *(float4*)&Qs[r * QSTR + c] = v;
    }
    if (tid < BQ) { sm_m[tid] = -1e30f; sm_l[tid] = 0.0f; }

    float acc[32];
#pragma unroll
    for (int i = 0; i < 32; i++) acc[i] = 0.0f;

    const int r_own = tid >> 2;          // 0..63 : owned query row
    const int part  = tid & 3;           // 0..3
    const int d0    = part * 32;         // owned dim slice
    const int ti    = tid >> 4;          // 0..15 score-tile row group
    const int tj    = tid & 15;          // 0..15 score-tile col group

    const int ntiles = it + 1;           // causal: only tiles <= diagonal
    for (int jt = 0; jt < ntiles; jt++) {
        const int j0 = jt * BKV;
        __syncthreads();   // prior PV reads of KVs/Ps done

        // Load K tile
        for (int idx = tid; idx < BKV * 32; idx += 256) {
            int r = idx >> 5, c = (idx & 31) << 2;
            *(float4*)&KVs[r * QSTR + c] =
                *(const float4*)&Kg[((b * SS + j0 + r) * NKV + g) * HD + c];
        }
        __syncthreads();

        // Scores: 4x4 per thread; rows i = ti*4+ii, cols j = tj + jj*16
        float sc[4][4];
#pragma unroll
        for (int ii = 0; ii < 4; ii++)
#pragma unroll
            for (int jj = 0; jj < 4; jj++) sc[ii][jj] = 0.0f;

#pragma unroll 4
        for (int k = 0; k < HD; k += 4) {
            float4 a[4], bv[4];
#pragma unroll
            for (int ii = 0; ii < 4; ii++)
                a[ii] = *(const float4*)&Qs[(ti * 4 + ii) * QSTR + k];
#pragma unroll
            for (int jj = 0; jj < 4; jj++)
                bv[jj] = *(const float4*)&KVs[(tj + jj * 16) * QSTR + k];
#pragma unroll
            for (int ii = 0; ii < 4; ii++)
#pragma unroll
                for (int jj = 0; jj < 4; jj++) {
                    sc[ii][jj] = fmaf(a[ii].x, bv[jj].x, sc[ii][jj]);
                    sc[ii][jj] = fmaf(a[ii].y, bv[jj].y, sc[ii][jj]);
                    sc[ii][jj] = fmaf(a[ii].z, bv[jj].z, sc[ii][jj]);
                    sc[ii][jj] = fmaf(a[ii].w, bv[jj].w, sc[ii][jj]);
                }
        }

        const bool diag = (jt == it);
#pragma unroll
        for (int ii = 0; ii < 4; ii++) {
            int irow = ti * 4 + ii;
#pragma unroll
            for (int jj = 0; jj < 4; jj++) {
                int jcol = tj + jj * 16;
                float s = sc[ii][jj];
                if (diag && (jcol > irow)) s = -1e30f;
                Ps[irow * PSTR + jcol] = s;
            }
        }
        __syncthreads();

        // Online softmax for owned row (4 threads cooperate via shfl)
        {
            float mloc = -1e30f;
#pragma unroll
            for (int jj = 0; jj < 16; jj++)
                mloc = fmaxf(mloc, Ps[r_own * PSTR + part * 16 + jj]);
            mloc = fmaxf(mloc, __shfl_xor_sync(0xffffffffu, mloc, 1));
            mloc = fmaxf(mloc, __shfl_xor_sync(0xffffffffu, mloc, 2));
            float mold = sm_m[r_own];
            float mnew = fmaxf(mold, mloc);
            float ssum = 0.0f;
#pragma unroll
            for (int jj = 0; jj < 16; jj++) {
                float p = __expf(Ps[r_own * PSTR + part * 16 + jj] - mnew);
                Ps[r_own * PSTR + part * 16 + jj] = p;
                ssum += p;
            }
            ssum += __shfl_xor_sync(0xffffffffu, ssum, 1);
            ssum += __shfl_xor_sync(0xffffffffu, ssum, 2);
            if (part == 0) {
                float al = __expf(mold - mnew);
                sm_a[r_own] = al;
                sm_m[r_own] = mnew;
                sm_l[r_own] = sm_l[r_own] * al + ssum;
            }
        }

        // Load V tile over K (K fully consumed above)
        for (int idx = tid; idx < BKV * 32; idx += 256) {
            int r = idx >> 5, c = (idx & 31) << 2;
            *(float4*)&KVs[r * QSTR + c] =
                *(const float4*)&Vg[((b * SS + j0 + r) * NKV + g) * HD + c];
        }
        __syncthreads();

        // Rescale accumulators + PV
        float al = sm_a[r_own];
#pragma unroll
        for (int dd = 0; dd < 32; dd++) acc[dd] *= al;

#pragma unroll 4
        for (int j = 0; j < BKV; j++) {
            float p = Ps[r_own * PSTR + j];
#pragma unroll
            for (int dd = 0; dd < 32; dd += 4) {
                float4 v = *(const float4*)&KVs[j * QSTR + d0 + dd];
                acc[dd + 0] = fmaf(p, v.x, acc[dd + 0]);
                acc[dd + 1] = fmaf(p, v.y, acc[dd + 1]);
                acc[dd + 2] = fmaf(p, v.z, acc[dd + 2]);
                acc[dd + 3] = fmaf(p, v.w, acc[dd + 3]);
            }
        }
    }

    // Epilogue
    float inv = 1.0f / sm_l[r_own];
#pragma unroll
    for (int dd = 0; dd < 32; dd += 4) {
        float4 v;
        v.x = acc[dd + 0] * inv; v.y = acc[dd + 1] * inv;
        v.z = acc[dd + 2] * inv; v.w = acc[dd + 3] * inv;
        *(float4*)&Og[((m0 + r_own) * NH + h) * HD + d0 + dd] = v;
    }
}

// ---------------------------------------------------------------------------
// Launcher
// ---------------------------------------------------------------------------
extern "C" void kernel_launch(void* const* d_in, const int* in_sizes, int n_in,
                              void* d_out, int out_size)
{
    const float* hidden = (const float*)d_in[0];
    const float* cosp   = (const float*)d_in[1];
    const float* sinp   = (const float*)d_in[2];
    // d_in[3] = attention_mask (pure causal; applied analytically)
    const float* q_w = (const float*)d_in[4];
    const float* q_b = (const float*)d_in[5];
    const float* k_w = (const float*)d_in[6];
    const float* k_b = (const float*)d_in[7];
    const float* v_w = (const float*)d_in[8];
    const float* v_b = (const float*)d_in[9];
    const float* o_w = (const float*)d_in[10];
    float* out = (float*)d_out;

    float *qp, *kp, *vp, *aop;
    cudaGetSymbolAddress((void**)&qp, g_q);
    cudaGetSymbolAddress((void**)&kp, g_k);
    cudaGetSymbolAddress((void**)&vp, g_v);
    cudaGetSymbolAddress((void**)&aop, g_ao);

    dim3 blk(256);

    // QKV projections
    sgemm_bias_kernel<<<dim3(2048 / 128, M_TOK / 128), blk>>>(
        hidden, q_w, q_b, qp, M_TOK, 2048, 2048);
    sgemm_bias_kernel<<<dim3(512 / 128, M_TOK / 128), blk>>>(
        hidden, k_w, k_b, kp, M_TOK, 512, 2048);
    sgemm_bias_kernel<<<dim3(512 / 128, M_TOK / 128), blk>>>(
        hidden, v_w, v_b, vp, M_TOK, 512, 2048);

    // RoPE
    {
        int nq = M_TOK * NH * 64;
        rope_kernel<<<(nq + 255) / 256, 256>>>(qp, cosp, sinp, NH, nq);
        int nk = M_TOK * NKV * 64;
        rope_kernel<<<(nk + 255) / 256, 256>>>(kp, cosp, sinp, NKV, nk);
    }

    // Flash attention
    {
        size_t fsm_bytes = (size_t)(2 * BQ * QSTR + BQ * PSTR + 3 * BQ) * sizeof(float);
        cudaFuncSetAttribute(flash_kernel,
                             cudaFuncAttributeMaxDynamicSharedMemorySize,
                             (int)fsm_bytes);
        flash_kernel<<<dim3(SS / BQ, NH, BB), 256, fsm_bytes>>>(qp, kp, vp, aop);
    }

    // Output projection (no bias)
    sgemm_bias_kernel<<<dim3(2048 / 128, M_TOK / 128), blk>>>(
        aop, o_w, (const float*)nullptr, out, M_TOK, 2048, 2048);
}

// round 3
// speedup vs baseline: 1.2028x; 1.2028x over previous
#include <cuda_runtime.h>
#include <cuda_bf16.h>
#include <math.h>
#include <stdint.h>

// Problem constants
#define BB 2
#define SS 2048
#define HH 2048
#define NH 16
#define NKV 4
#define HD 128
#define NREP (NH / NKV)
#define M_TOK (BB * SS)          // 4096 tokens
#define SCALE_F 0.08838834764831845f  // 1/sqrt(128)

// ---------------------------------------------------------------------------
// Scratch
// ---------------------------------------------------------------------------
__device__ float g_q[M_TOK * NH * HD];
__device__ float g_k[M_TOK * NKV * HD];
__device__ float g_v[M_TOK * NKV * HD];
__device__ float g_ao[M_TOK * NH * HD];

// bf16 split buffers (hi + lo)
__device__ __nv_bfloat16 g_h_hi[M_TOK * HH],  g_h_lo[M_TOK * HH];
__device__ __nv_bfloat16 g_qw_hi[NH * HD * HH], g_qw_lo[NH * HD * HH];
__device__ __nv_bfloat16 g_kw_hi[NKV * HD * HH], g_kw_lo[NKV * HD * HH];
__device__ __nv_bfloat16 g_vw_hi[NKV * HD * HH], g_vw_lo[NKV * HD * HH];
__device__ __nv_bfloat16 g_ow_hi[HH * NH * HD], g_ow_lo[HH * NH * HD];
__device__ __nv_bfloat16 g_ao_hi[M_TOK * NH * HD], g_ao_lo[M_TOK * NH * HD];

// ---------------------------------------------------------------------------
// Warp MMA helpers (valid on base sm_100 target: ldmatrix + mma.sync)
// ---------------------------------------------------------------------------
__device__ __forceinline__ uint32_t smem_u32(const void* p) {
    uint32_t a;
    asm("{ .reg .u64 t; cvta.to.shared.u64 t, %1; cvt.u32.u64 %0, t; }"
        : "=r"(a) : "l"(p));
    return a;
}
__device__ __forceinline__ void ldsm_x4(uint32_t* r, uint32_t addr) {
    asm volatile("ldmatrix.sync.aligned.m8n8.x4.shared.b16 {%0,%1,%2,%3}, [%4];"
                 : "=r"(r[0]), "=r"(r[1]), "=r"(r[2]), "=r"(r[3]) : "r"(addr));
}
__device__ __forceinline__ void ldsm_x2(uint32_t* r, uint32_t addr) {
    asm volatile("ldmatrix.sync.aligned.m8n8.x2.shared.b16 {%0,%1}, [%2];"
                 : "=r"(r[0]), "=r"(r[1]) : "r"(addr));
}
__device__ __forceinline__ void mma_bf16(float* c, const uint32_t* a, const uint32_t* b) {
    asm volatile(
        "mma.sync.aligned.m16n8k16.row.col.f32.bf16.bf16.f32 "
        "{%0,%1,%2,%3}, {%4,%5,%6,%7}, {%8,%9}, {%0,%1,%2,%3};"
        : "+f"(c[0]), "+f"(c[1]), "+f"(c[2]), "+f"(c[3])
        : "r"(a[0]), "r"(a[1]), "r"(a[2]), "r"(a[3]), "r"(b[0]), "r"(b[1]));
}

// ---------------------------------------------------------------------------
// Split fp32 -> bf16 hi/lo
// ---------------------------------------------------------------------------
__global__ void split_kernel(const float* __restrict__ x,
                             __nv_bfloat16* __restrict__ hi,
                             __nv_bfloat16* __restrict__ lo, int n)
{
    int i = (blockIdx.x * blockDim.x + threadIdx.x) << 2;
    if (i >= n) return;
    float4 v = *(const float4*)(x + i);
    float vv[4] = {v.x, v.y, v.z, v.w};
    unsigned short h[4], l[4];
#pragma unroll
    for (int j = 0; j < 4; j++) {
        __nv_bfloat16 hb = __float2bfloat16(vv[j]);
        __nv_bfloat16 lb = __float2bfloat16(vv[j] - __bfloat162float(hb));
        h[j] = __bfloat16_as_ushort(hb);
        l[j] = __bfloat16_as_ushort(lb);
    }
    uint2 hp, lp;
    hp.x = (uint32_t)h[0] | ((uint32_t)h[1] << 16);
    hp.y = (uint32_t)h[2] | ((uint32_t)h[3] << 16);
    lp.x = (uint32_t)l[0] | ((uint32_t)l[1] << 16);
    lp.y = (uint32_t)l[2] | ((uint32_t)l[3] << 16);
    *(uint2*)(hi + i) = hp;
    *(uint2*)(lo + i) = lp;
}

// ---------------------------------------------------------------------------
// Split-bf16 tensor-core GEMM: C[M,N] = A[M,K] @ W[N,K]^T (+bias)
// Block tile 128x128, BK=32, 8 warps (4x2), warp tile 32x64.
// D += Ahi*Bhi + Ahi*Blo + Alo*Bhi   (fp32 accumulate)
// ---------------------------------------------------------------------------
#define SSTR 40   // smem row stride in bf16 (80 bytes, conflict-free LDSM)

__global__ __launch_bounds__(256) void gemm_mma_kernel(
    const __nv_bfloat16* __restrict__ Ahi, const __nv_bfloat16* __restrict__ Alo,
    const __nv_bfloat16* __restrict__ Bhi, const __nv_bfloat16* __restrict__ Blo,
    const float* __restrict__ bias, float* __restrict__ C,
    int M, int N, int K)
{
    __shared__ __nv_bfloat16 sAh[128 * SSTR], sAl[128 * SSTR];
    __shared__ __nv_bfloat16 sBh[128 * SSTR], sBl[128 * SSTR];

    const int tid  = threadIdx.x;
    const int wid  = tid >> 5;
    const int lane = tid & 31;
    const int wm   = (wid >> 1) * 32;   // warp m offset in tile
    const int wn   = (wid & 1) * 64;    // warp n offset in tile
    const int row0 = blockIdx.y * 128;
    const int col0 = blockIdx.x * 128;

    float acc[2][8][4];
#pragma unroll
    for (int mt = 0; mt < 2; mt++)
#pragma unroll
        for (int nt = 0; nt < 8; nt++)
#pragma unroll
            for (int j = 0; j < 4; j++) acc[mt][nt][j] = 0.0f;

    // Copy-chunk geometry: tile = 128 rows x 32 bf16 -> 512 uint4 chunks.
    const int r0c = tid >> 2;                 // chunk rows for j=0 (0..63)... actually:
    // chunk = tid + j*256; row = chunk>>2 ; col = (chunk&3)*8
    const uint32_t aAh = smem_u32(sAh), aAl = smem_u32(sAl);
    const uint32_t aBh = smem_u32(sBh), aBl = smem_u32(sBl);

    // LDSM base addressing
    // A: row = wm + mt*16 + (lane&7) + ((lane>>3)&1)*8 ; col = ks*16 + (lane>>4)*8
    const int a_r = wm + (lane & 7) + ((lane >> 3) & 1) * 8;
    const int a_c = (lane >> 4) * 8;
    // B: row = wn + nt*8 + (lane&7) ; col = ks*16 + ((lane>>3)&1)*8   (lanes 0..15 used)
    const int b_r = wn + (lane & 7);
    const int b_c = ((lane >> 3) & 1) * 8;

    uint4 pAh[2], pAl[2], pBh[2], pBl[2];

    // prefetch k0 = 0
#pragma unroll
    for (int j = 0; j < 2; j++) {
        int ch = tid + j * 256;
        int r = ch >> 2, c = (ch & 3) * 8;
        long ga = (long)(row0 + r) * K + c;
        long gb = (long)(col0 + r) * K + c;
        pAh[j] = *(const uint4*)(Ahi + ga);
        pAl[j] = *(const uint4*)(Alo + ga);
        pBh[j] = *(const uint4*)(Bhi + gb);
        pBl[j] = *(const uint4*)(Blo + gb);
    }

    for (int k0 = 0; k0 < K; k0 += 32) {
        // store prefetched chunks into smem
#pragma unroll
        for (int j = 0; j < 2; j++) {
            int ch = tid + j * 256;
            int r = ch >> 2, c = (ch & 3) * 8;
            int off = r * SSTR + c;
            *(uint4*)&sAh[off] = pAh[j];
            *(uint4*)&sAl[off] = pAl[j];
            *(uint4*)&sBh[off] = pBh[j];
            *(uint4*)&sBl[off] = pBl[j];
        }
        __syncthreads();

        // prefetch next k-tile while computing
        if (k0 + 32 < K) {
#pragma unroll
            for (int j = 0; j < 2; j++) {
                int ch = tid + j * 256;
                int r = ch >> 2, c = (ch & 3) * 8;
                long ga = (long)(row0 + r) * K + k0 + 32 + c;
                long gb = (long)(col0 + r) * K + k0 + 32 + c;
                pAh[j] = *(const uint4*)(Ahi + ga);
                pAl[j] = *(const uint4*)(Alo + ga);
                pBh[j] = *(const uint4*)(Bhi + gb);
                pBl[j] = *(const uint4*)(Blo + gb);
            }
        }

#pragma unroll
        for (int ks = 0; ks < 2; ks++) {
            uint32_t ah[2][4], al[2][4];
#pragma unroll
            for (int mt = 0; mt < 2; mt++) {
                uint32_t off = (uint32_t)((a_r + mt * 16) * SSTR + ks * 16 + a_c) * 2;
                ldsm_x4(ah[mt], aAh + off);
                ldsm_x4(al[mt], aAl + off);
            }
#pragma unroll
            for (int nt = 0; nt < 8; nt++) {
                uint32_t boff = (uint32_t)((b_r + nt * 8) * SSTR + ks * 16 + b_c) * 2;
                uint32_t bh[2], bl[2];
                ldsm_x2(bh, aBh + boff);
                ldsm_x2(bl, aBl + boff);
#pragma unroll
                for (int mt = 0; mt < 2; mt++) {
                    mma_bf16(acc[mt][nt], ah[mt], bh);
                    mma_bf16(acc[mt][nt], ah[mt], bl);
                    mma_bf16(acc[mt][nt], al[mt], bh);
                }
            }
        }
        __syncthreads();
    }

    // Epilogue
    const int em = row0 + wm + (lane >> 2);
    const int en = col0 + wn + (lane & 3) * 2;
#pragma unroll
    for (int mt = 0; mt < 2; mt++) {
#pragma unroll
        for (int nt = 0; nt < 8; nt++) {
            int n = en + nt * 8;
            float b0 = bias ? bias[n] : 0.0f;
            float b1 = bias ? bias[n + 1] : 0.0f;
            float2 v0, v1;
            v0.x = acc[mt][nt][0] + b0; v0.y = acc[mt][nt][1] + b1;
            v1.x = acc[mt][nt][2] + b0; v1.y = acc[mt][nt][3] + b1;
            *(float2*)&C[(long)(em + mt * 16) * N + n] = v0;
            *(float2*)&C[(long)(em + mt * 16 + 8) * N + n] = v1;
        }
    }
}

// ---------------------------------------------------------------------------
// RoPE in place on x: [M_TOK, nheads, HD]. cos/sin: [M_TOK, HD].
// ---------------------------------------------------------------------------
__global__ void rope_kernel(float* __restrict__ x,
                            const float* __restrict__ cosp,
                            const float* __restrict__ sinp,
                            int nheads, int total)
{
    int i = blockIdx.x * blockDim.x + threadIdx.x;
    if (i >= total) return;
    int d   = i & 63;
    int t2  = i >> 6;
    int hh  = t2 % nheads;
    int tok = t2 / nheads;
    float* p = x + (tok * nheads + hh) * HD;
    float x1 = p[d];
    float x2 = p[d + 64];
    const float* cp = cosp + tok * HD;
    const float* sp = sinp + tok * HD;
    float c1 = cp[d], s1 = sp[d];
    float c2 = cp[d + 64], s2 = sp[d + 64];
    p[d]      = x1 * c1 - x2 * s1;
    p[d + 64] = x2 * c2 + x1 * s2;
}

// ---------------------------------------------------------------------------
// Flash attention (causal, GQA). fp32 SIMT.
// ---------------------------------------------------------------------------
#define BQ 64
#define BKV 64
#define QSTR 132
#define PSTR 68

extern __shared__ float fsm[];

__global__ __launch_bounds__(256) void flash_kernel(
    const float* __restrict__ Qg, const float* __restrict__ Kg,
    const float* __restrict__ Vg, float* __restrict__ Og)
{
    float* Qs   = fsm;
    float* KVs  = Qs  + BQ * QSTR;
    float* Ps   = KVs + BKV * QSTR;
    float* sm_m = Ps  + BQ * PSTR;
    float* sm_l = sm_m + BQ;
    float* sm_a = sm_l + BQ;

    const int it = blockIdx.x;
    const int h  = blockIdx.y;
    const int b  = blockIdx.z;
    const int g  = h / NREP;
    const int tid = threadIdx.x;
    const int i0 = it * BQ;
    const int m0 = b * SS + i0;

    for (int idx = tid; idx < BQ * 32; idx += 256) {
        int r = idx >> 5, c = (idx & 31) << 2;
        float4 v = *(const float4*)&Qg[((m0 + r) * NH + h) * HD + c];
        v.x *= SCALE_F; v.y *= SCALE_F; v.z *= SCALE_F; v.w *= SCALE_F;
        *(float4*)&Qs[r * QSTR + c] = v;
    }
    if (tid < BQ) { sm_m[tid] = -1e30f; sm_l[tid] = 0.0f; }

    float acc[32];
#pragma unroll
    for (int i = 0; i < 32; i++) acc[i] = 0.0f;

    const int r_own = tid >> 2;
    const int part  = tid & 3;
    const int d0    = part * 32;
    const int ti    = tid >> 4;
    const int tj    = tid & 15;

    const int ntiles = it + 1;
    for (int jt = 0; jt < ntiles; jt++) {
        const int j0 = jt * BKV;
        __syncthreads();

        for (int idx = tid; idx < BKV * 32; idx += 256) {
            int r = idx >> 5, c = (idx & 31) << 2;
            *(float4*)&KVs[r * QSTR + c] =
                *(const float4*)&Kg[((b * SS + j0 + r) * NKV + g) * HD + c];
        }
        __syncthreads();

        float sc[4][4];
#pragma unroll
        for (int ii = 0; ii < 4; ii++)
#pragma unroll
            for (int jj = 0; jj < 4; jj++) sc[ii][jj] = 0.0f;

#pragma unroll 4
        for (int k = 0; k < HD; k += 4) {
            float4 a[4], bv[4];
#pragma unroll
            for (int ii = 0; ii < 4; ii++)
                a[ii] = *(const float4*)&Qs[(ti * 4 + ii) * QSTR + k];
#pragma unroll
            for (int jj = 0; jj < 4; jj++)
                bv[jj] = *(const float4*)&KVs[(tj + jj * 16) * QSTR + k];
#pragma unroll
            for (int ii = 0; ii < 4; ii++)
#pragma unroll
                for (int jj = 0; jj < 4; jj++) {
                    sc[ii][jj] = fmaf(a[ii].x, bv[jj].x, sc[ii][jj]);
                    sc[ii][jj] = fmaf(a[ii].y, bv[jj].y, sc[ii][jj]);
                    sc[ii][jj] = fmaf(a[ii].z, bv[jj].z, sc[ii][jj]);
                    sc[ii][jj] = fmaf(a[ii].w, bv[jj].w, sc[ii][jj]);
                }
        }

        const bool diag = (jt == it);
#pragma unroll
        for (int ii = 0; ii < 4; ii++) {
            int irow = ti * 4 + ii;
#pragma unroll
            for (int jj = 0; jj < 4; jj++) {
                int jcol = tj + jj * 16;
                float s = sc[ii][jj];
                if (diag && (jcol > irow)) s = -1e30f;
                Ps[irow * PSTR + jcol] = s;
            }
        }
        __syncthreads();

        {
            float mloc = -1e30f;
#pragma unroll
            for (int jj = 0; jj < 16; jj++)
                mloc = fmaxf(mloc, Ps[r_own * PSTR + part * 16 + jj]);
            mloc = fmaxf(mloc, __shfl_xor_sync(0xffffffffu, mloc, 1));
            mloc = fmaxf(mloc, __shfl_xor_sync(0xffffffffu, mloc, 2));
            float mold = sm_m[r_own];
            float mnew = fmaxf(mold, mloc);
            float ssum = 0.0f;
#pragma unroll
            for (int jj = 0; jj < 16; jj++) {
                float p = __expf(Ps[r_own * PSTR + part * 16 + jj] - mnew);
                Ps[r_own * PSTR + part * 16 + jj] = p;
                ssum += p;
            }
            ssum += __shfl_xor_sync(0xffffffffu, ssum, 1);
            ssum += __shfl_xor_sync(0xffffffffu, ssum, 2);
            if (part == 0) {
                float al = __expf(mold - mnew);
                sm_a[r_own] = al;
                sm_m[r_own] = mnew;
                sm_l[r_own] = sm_l[r_own] * al + ssum;
            }
        }

        for (int idx = tid; idx < BKV * 32; idx += 256) {
            int r = idx >> 5, c = (idx & 31) << 2;
            *(float4*)&KVs[r * QSTR + c] =
                *(const float4*)&Vg[((b * SS + j0 + r) * NKV + g) * HD + c];
        }
        __syncthreads();

        float al = sm_a[r_own];
#pragma unroll
        for (int dd = 0; dd < 32; dd++) acc[dd] *= al;

#pragma unroll 4
        for (int j = 0; j < BKV; j++) {
            float p = Ps[r_own * PSTR + j];
#pragma unroll
            for (int dd = 0; dd < 32; dd += 4) {
                float4 v = *(const float4*)&KVs[j * QSTR + d0 + dd];
                acc[dd + 0] = fmaf(p, v.x, acc[dd + 0]);
                acc[dd + 1] = fmaf(p, v.y, acc[dd + 1]);
                acc[dd + 2] = fmaf(p, v.z, acc[dd + 2]);
                acc[dd + 3] = fmaf(p, v.w, acc[dd + 3]);
            }
        }
    }

    float inv = 1.0f / sm_l[r_own];
#pragma unroll
    for (int dd = 0; dd < 32; dd += 4) {
        float4 v;
        v.x = acc[dd + 0] * inv; v.y = acc[dd + 1] * inv;
        v.z = acc[dd + 2] * inv; v.w = acc[dd + 3] * inv;
        *(float4*)&Og[((m0 + r_own) * NH + h) * HD + d0 + dd] = v;
    }
}

// ---------------------------------------------------------------------------
// Launcher
// ---------------------------------------------------------------------------
static void run_split(const float* x, __nv_bfloat16* hi, __nv_bfloat16* lo, int n)
{
    int nthr = n / 4;
    split_kernel<<<(nthr + 255) / 256, 256>>>(x, hi, lo, n);
}

extern "C" void kernel_launch(void* const* d_in, const int* in_sizes, int n_in,
                              void* d_out, int out_size)
{
    const float* hidden = (const float*)d_in[0];
    const float* cosp   = (const float*)d_in[1];
    const float* sinp   = (const float*)d_in[2];
    // d_in[3] = attention_mask (pure causal; applied analytically)
    const float* q_w = (const float*)d_in[4];
    const float* q_b = (const float*)d_in[5];
    const float* k_w = (const float*)d_in[6];
    const float* k_b = (const float*)d_in[7];
    const float* v_w = (const float*)d_in[8];
    const float* v_b = (const float*)d_in[9];
    const float* o_w = (const float*)d_in[10];
    float* out = (float*)d_out;

    float *qp, *kp, *vp, *aop;
    cudaGetSymbolAddress((void**)&qp, g_q);
    cudaGetSymbolAddress((void**)&kp, g_k);
    cudaGetSymbolAddress((void**)&vp, g_v);
    cudaGetSymbolAddress((void**)&aop, g_ao);

    __nv_bfloat16 *h_hi, *h_lo, *qw_hi, *qw_lo, *kw_hi, *kw_lo;
    __nv_bfloat16 *vw_hi, *vw_lo, *ow_hi, *ow_lo, *ao_hi, *ao_lo;
    cudaGetSymbolAddress((void**)&h_hi, g_h_hi);
    cudaGetSymbolAddress((void**)&h_lo, g_h_lo);
    cudaGetSymbolAddress((void**)&qw_hi, g_qw_hi);
    cudaGetSymbolAddress((void**)&qw_lo, g_qw_lo);
    cudaGetSymbolAddress((void**)&kw_hi, g_kw_hi);
    cudaGetSymbolAddress((void**)&kw_lo, g_kw_lo);
    cudaGetSymbolAddress((void**)&vw_hi, g_vw_hi);
    cudaGetSymbolAddress((void**)&vw_lo, g_vw_lo);
    cudaGetSymbolAddress((void**)&ow_hi, g_ow_hi);
    cudaGetSymbolAddress((void**)&ow_lo, g_ow_lo);
    cudaGetSymbolAddress((void**)&ao_hi, g_ao_hi);
    cudaGetSymbolAddress((void**)&ao_lo, g_ao_lo);

    // Split conversions
    run_split(hidden, h_hi, h_lo, M_TOK * HH);
    run_split(q_w, qw_hi, qw_lo, NH * HD * HH);
    run_split(k_w, kw_hi, kw_lo, NKV * HD * HH);
    run_split(v_w, vw_hi, vw_lo, NKV * HD * HH);
    run_split(o_w, ow_hi, ow_lo, HH * NH * HD);

    // QKV projections (tensor cores)
    gemm_mma_kernel<<<dim3((NH * HD) / 128, M_TOK / 128), 256>>>(
        h_hi, h_lo, qw_hi, qw_lo, q_b, qp, M_TOK, NH * HD, HH);
    gemm_mma_kernel<<<dim3((NKV * HD) / 128, M_TOK / 128), 256>>>(
        h_hi, h_lo, kw_hi, kw_lo, k_b, kp, M_TOK, NKV * HD, HH);
    gemm_mma_kernel<<<dim3((NKV * HD) / 128, M_TOK / 128), 256>>>(
        h_hi, h_lo, vw_hi, vw_lo, v_b, vp, M_TOK, NKV * HD, HH);

    // RoPE
    {
        int nq = M_TOK * NH * 64;
        rope_kernel<<<(nq + 255) / 256, 256>>>(qp, cosp, sinp, NH, nq);
        int nk = M_TOK * NKV * 64;
        rope_kernel<<<(nk + 255) / 256, 256>>>(kp, cosp, sinp, NKV, nk);
    }

    // Flash attention
    {
        size_t fsm_bytes = (size_t)(2 * BQ * QSTR + BQ * PSTR + 3 * BQ) * sizeof(float);
        cudaFuncSetAttribute(flash_kernel,
                             cudaFuncAttributeMaxDynamicSharedMemorySize,
                             (int)fsm_bytes);
        flash_kernel<<<dim3(SS / BQ, NH, BB), 256, fsm_bytes>>>(qp, kp, vp, aop);
    }

    // Output projection (tensor cores, no bias)
    run_split(aop, ao_hi, ao_lo, M_TOK * NH * HD);
    gemm_mma_kernel<<<dim3(HH / 128, M_TOK / 128), 256>>>(
        ao_hi, ao_lo, ow_hi, ow_lo, (const float*)nullptr, out, M_TOK, HH, NH * HD);
}

// round 4
// speedup vs baseline: 4.7645x; 3.9612x over previous
#include <cuda_runtime.h>
#include <cuda_bf16.h>
#include <math.h>
#include <stdint.h>

// Problem constants
#define BB 2
#define SS 2048
#define HH 2048
#define NH 16
#define NKV 4
#define HD 128
#define NREP (NH / NKV)
#define M_TOK (BB * SS)
#define SCALE_F 0.08838834764831845f

// ---------------------------------------------------------------------------
// Scratch
// ---------------------------------------------------------------------------
__device__ float g_q[M_TOK * NH * HD];
__device__ float g_k[M_TOK * NKV * HD];
__device__ float g_v[M_TOK * NKV * HD];
__device__ float g_ao[M_TOK * NH * HD];

// bf16 split buffers
__device__ __nv_bfloat16 g_h_hi[M_TOK * HH],  g_h_lo[M_TOK * HH];
__device__ __nv_bfloat16 g_qw_hi[NH * HD * HH], g_qw_lo[NH * HD * HH];
__device__ __nv_bfloat16 g_kw_hi[NKV * HD * HH], g_kw_lo[NKV * HD * HH];
__device__ __nv_bfloat16 g_vw_hi[NKV * HD * HH], g_vw_lo[NKV * HD * HH];
__device__ __nv_bfloat16 g_ow_hi[HH * NH * HD], g_ow_lo[HH * NH * HD];
__device__ __nv_bfloat16 g_ao_hi[M_TOK * NH * HD], g_ao_lo[M_TOK * NH * HD];
// attention operand splits
__device__ __nv_bfloat16 g_qh[M_TOK * NH * HD], g_ql[M_TOK * NH * HD];
__device__ __nv_bfloat16 g_kh[M_TOK * NKV * HD], g_kl[M_TOK * NKV * HD];
__device__ __nv_bfloat16 g_vh[M_TOK * NKV * HD], g_vl[M_TOK * NKV * HD];

// ---------------------------------------------------------------------------
// Warp MMA helpers (base sm_100-safe: ldmatrix + mma.sync)
// ---------------------------------------------------------------------------
__device__ __forceinline__ uint32_t smem_u32(const void* p) {
    uint32_t a;
    asm("{ .reg .u64 t; cvta.to.shared.u64 t, %1; cvt.u32.u64 %0, t; }"
        : "=r"(a) : "l"(p));
    return a;
}
__device__ __forceinline__ void ldsm_x4(uint32_t* r, uint32_t addr) {
    asm volatile("ldmatrix.sync.aligned.m8n8.x4.shared.b16 {%0,%1,%2,%3}, [%4];"
                 : "=r"(r[0]), "=r"(r[1]), "=r"(r[2]), "=r"(r[3]) : "r"(addr));
}
__device__ __forceinline__ void ldsm_x2(uint32_t* r, uint32_t addr) {
    asm volatile("ldmatrix.sync.aligned.m8n8.x2.shared.b16 {%0,%1}, [%2];"
                 : "=r"(r[0]), "=r"(r[1]) : "r"(addr));
}
__device__ __forceinline__ void ldsm_x4_t(uint32_t* r, uint32_t addr) {
    asm volatile("ldmatrix.sync.aligned.m8n8.x4.trans.shared.b16 {%0,%1,%2,%3}, [%4];"
                 : "=r"(r[0]), "=r"(r[1]), "=r"(r[2]), "=r"(r[3]) : "r"(addr));
}
__device__ __forceinline__ void mma_bf16(float* c, const uint32_t* a, const uint32_t* b) {
    asm volatile(
        "mma.sync.aligned.m16n8k16.row.col.f32.bf16.bf16.f32 "
        "{%0,%1,%2,%3}, {%4,%5,%6,%7}, {%8,%9}, {%0,%1,%2,%3};"
        : "+f"(c[0]), "+f"(c[1]), "+f"(c[2]), "+f"(c[3])
        : "r"(a[0]), "r"(a[1]), "r"(a[2]), "r"(a[3]), "r"(b[0]), "r"(b[1]));
}

// ---------------------------------------------------------------------------
// Split fp32 -> bf16 hi/lo (optionally scaled)
// ---------------------------------------------------------------------------
__global__ void split_kernel(const float* __restrict__ x,
                             __nv_bfloat16* __restrict__ hi,
                             __nv_bfloat16* __restrict__ lo, int n, float scale)
{
    int i = (blockIdx.x * blockDim.x + threadIdx.x) << 2;
    if (i >= n) return;
    float4 v = *(const float4*)(x + i);
    float vv[4] = {v.x * scale, v.y * scale, v.z * scale, v.w * scale};
    unsigned short h[4], l[4];
#pragma unroll
    for (int j = 0; j < 4; j++) {
        __nv_bfloat16 hb = __float2bfloat16(vv[j]);
        __nv_bfloat16 lb = __float2bfloat16(vv[j] - __bfloat162float(hb));
        h[j] = __bfloat16_as_ushort(hb);
        l[j] = __bfloat16_as_ushort(lb);
    }
    uint2 hp, lp;
    hp.x = (uint32_t)h[0] | ((uint32_t)h[1] << 16);
    hp.y = (uint32_t)h[2] | ((uint32_t)h[3] << 16);
    lp.x = (uint32_t)l[0] | ((uint32_t)l[1] << 16);
    lp.y = (uint32_t)l[2] | ((uint32_t)l[3] << 16);
    *(uint2*)(hi + i) = hp;
    *(uint2*)(lo + i) = lp;
}

// ---------------------------------------------------------------------------
// Split-bf16 tensor-core GEMM (unchanged from round 3)
// ---------------------------------------------------------------------------
#define SSTR 40

__global__ __launch_bounds__(256) void gemm_mma_kernel(
    const __nv_bfloat16* __restrict__ Ahi, const __nv_bfloat16* __restrict__ Alo,
    const __nv_bfloat16* __restrict__ Bhi, const __nv_bfloat16* __restrict__ Blo,
    const float* __restrict__ bias, float* __restrict__ C,
    int M, int N, int K)
{
    __shared__ __nv_bfloat16 sAh[128 * SSTR], sAl[128 * SSTR];
    __shared__ __nv_bfloat16 sBh[128 * SSTR], sBl[128 * SSTR];

    const int tid  = threadIdx.x;
    const int wid  = tid >> 5;
    const int lane = tid & 31;
    const int wm   = (wid >> 1) * 32;
    const int wn   = (wid & 1) * 64;
    const int row0 = blockIdx.y * 128;
    const int col0 = blockIdx.x * 128;

    float acc[2][8][4];
#pragma unroll
    for (int mt = 0; mt < 2; mt++)
#pragma unroll
        for (int nt = 0; nt < 8; nt++)
#pragma unroll
            for (int j = 0; j < 4; j++) acc[mt][nt][j] = 0.0f;

    const uint32_t aAh = smem_u32(sAh), aAl = smem_u32(sAl);
    const uint32_t aBh = smem_u32(sBh), aBl = smem_u32(sBl);

    const int a_r = wm + (lane & 7) + ((lane >> 3) & 1) * 8;
    const int a_c = (lane >> 4) * 8;
    const int b_r = wn + (lane & 7);
    const int b_c = ((lane >> 3) & 1) * 8;

    uint4 pAh[2], pAl[2], pBh[2], pBl[2];

#pragma unroll
    for (int j = 0; j < 2; j++) {
        int ch = tid + j * 256;
        int r = ch >> 2, c = (ch & 3) * 8;
        long ga = (long)(row0 + r) * K + c;
        long gb = (long)(col0 + r) * K + c;
        pAh[j] = *(const uint4*)(Ahi + ga);
        pAl[j] = *(const uint4*)(Alo + ga);
        pBh[j] = *(const uint4*)(Bhi + gb);
        pBl[j] = *(const uint4*)(Blo + gb);
    }

    for (int k0 = 0; k0 < K; k0 += 32) {
#pragma unroll
        for (int j = 0; j < 2; j++) {
            int ch = tid + j * 256;
            int r = ch >> 2, c = (ch & 3) * 8;
            int off = r * SSTR + c;
            *(uint4*)&sAh[off] = pAh[j];
            *(uint4*)&sAl[off] = pAl[j];
            *(uint4*)&sBh[off] = pBh[j];
            *(uint4*)&sBl[off] = pBl[j];
        }
        __syncthreads();

        if (k0 + 32 < K) {
#pragma unroll
            for (int j = 0; j < 2; j++) {
                int ch = tid + j * 256;
                int r = ch >> 2, c = (ch & 3) * 8;
                long ga = (long)(row0 + r) * K + k0 + 32 + c;
                long gb = (long)(col0 + r) * K + k0 + 32 + c;
                pAh[j] = *(const uint4*)(Ahi + ga);
                pAl[j] = *(const uint4*)(Alo + ga);
                pBh[j] = *(const uint4*)(Bhi + gb);
                pBl[j] = *(const uint4*)(Blo + gb);
            }
        }

#pragma unroll
        for (int ks = 0; ks < 2; ks++) {
            uint32_t ah[2][4], al[2][4];
#pragma unroll
            for (int mt = 0; mt < 2; mt++) {
                uint32_t off = (uint32_t)((a_r + mt * 16) * SSTR + ks * 16 + a_c) * 2;
                ldsm_x4(ah[mt], aAh + off);
                ldsm_x4(al[mt], aAl + off);
            }
#pragma unroll
            for (int nt = 0; nt < 8; nt++) {
                uint32_t boff = (uint32_t)((b_r + nt * 8) * SSTR + ks * 16 + b_c) * 2;
                uint32_t bh[2], bl[2];
                ldsm_x2(bh, aBh + boff);
                ldsm_x2(bl, aBl + boff);
#pragma unroll
                for (int mt = 0; mt < 2; mt++) {
                    mma_bf16(acc[mt][nt], ah[mt], bh);
                    mma_bf16(acc[mt][nt], ah[mt], bl);
                    mma_bf16(acc[mt][nt], al[mt], bh);
                }
            }
        }
        __syncthreads();
    }

    const int em = row0 + wm + (lane >> 2);
    const int en = col0 + wn + (lane & 3) * 2;
#pragma unroll
    for (int mt = 0; mt < 2; mt++) {
#pragma unroll
        for (int nt = 0; nt < 8; nt++) {
            int n = en + nt * 8;
            float b0 = bias ? bias[n] : 0.0f;
            float b1 = bias ? bias[n + 1] : 0.0f;
            float2 v0, v1;
            v0.x = acc[mt][nt][0] + b0; v0.y = acc[mt][nt][1] + b1;
            v1.x = acc[mt][nt][2] + b0; v1.y = acc[mt][nt][3] + b1;
            *(float2*)&C[(long)(em + mt * 16) * N + n] = v0;
            *(float2*)&C[(long)(em + mt * 16 + 8) * N + n] = v1;
        }
    }
}

// ---------------------------------------------------------------------------
// RoPE in place
// ---------------------------------------------------------------------------
__global__ void rope_kernel(float* __restrict__ x,
                            const float* __restrict__ cosp,
                            const float* __restrict__ sinp,
                            int nheads, int total)
{
    int i = blockIdx.x * blockDim.x + threadIdx.x;
    if (i >= total) return;
    int d   = i & 63;
    int t2  = i >> 6;
    int hh  = t2 % nheads;
    int tok = t2 / nheads;
    float* p = x + (tok * nheads + hh) * HD;
    float x1 = p[d];
    float x2 = p[d + 64];
    const float* cp = cosp + tok * HD;
    const float* sp = sinp + tok * HD;
    p[d]      = x1 * cp[d]      - x2 * sp[d];
    p[d + 64] = x2 * cp[d + 64] + x1 * sp[d + 64];
}

// ---------------------------------------------------------------------------
// Tensor-core flash attention (causal, GQA), split-bf16 everywhere.
// Block = 256 threads (8 warps), BQ=BKV=64.
// Warp wid: row group wm=(wid&3)*16, col group cg=wid>>2.
// ---------------------------------------------------------------------------
#define FQSTR 136   // bf16 row stride for Q/K/V tiles
#define FPSTR 72    // bf16 row stride for P tile

#define OQH 0u
#define OQL 17408u
#define OKH 34816u
#define OKL 52224u
#define OVH 69632u
#define OVL 87040u
#define OPH 104448u
#define OPL 113664u
#define OPM 122880u   // pm[2][64] fp32
#define OPS 123392u   // ps[2][64] fp32
#define OMS 123904u   // m_s[64]
#define OLS 124160u   // l_s[64]
#define FSM_BYTES 124416u

__global__ __launch_bounds__(256) void flash_mma_kernel(
    const __nv_bfloat16* __restrict__ Qh, const __nv_bfloat16* __restrict__ Ql,
    const __nv_bfloat16* __restrict__ Kh, const __nv_bfloat16* __restrict__ Kl,
    const __nv_bfloat16* __restrict__ Vh, const __nv_bfloat16* __restrict__ Vl,
    float* __restrict__ Og)
{
    extern __shared__ char fsm2[];
    __nv_bfloat16* sQh = (__nv_bfloat16*)(fsm2 + OQH);
    __nv_bfloat16* sQl = (__nv_bfloat16*)(fsm2 + OQL);
    __nv_bfloat16* sKh = (__nv_bfloat16*)(fsm2 + OKH);
    __nv_bfloat16* sKl = (__nv_bfloat16*)(fsm2 + OKL);
    __nv_bfloat16* sVh = (__nv_bfloat16*)(fsm2 + OVH);
    __nv_bfloat16* sVl = (__nv_bfloat16*)(fsm2 + OVL);
    __nv_bfloat16* sPh = (__nv_bfloat16*)(fsm2 + OPH);
    __nv_bfloat16* sPl = (__nv_bfloat16*)(fsm2 + OPL);
    float* pm  = (float*)(fsm2 + OPM);
    float* ps  = (float*)(fsm2 + OPS);
    float* m_s = (float*)(fsm2 + OMS);
    float* l_s = (float*)(fsm2 + OLS);

    const uint32_t aQh = smem_u32(sQh), aQl = smem_u32(sQl);
    const uint32_t aKh = smem_u32(sKh), aKl = smem_u32(sKl);
    const uint32_t aVh = smem_u32(sVh), aVl = smem_u32(sVl);
    const uint32_t aPh = smem_u32(sPh), aPl = smem_u32(sPl);

    const int it = blockIdx.x;
    const int h  = blockIdx.y;
    const int b  = blockIdx.z;
    const int g  = h / NREP;
    const int tid  = threadIdx.x;
    const int wid  = tid >> 5;
    const int lane = tid & 31;
    const int wm   = (wid & 3) * 16;
    const int cg   = wid >> 2;
    const int i0 = it * 64;
    const int m0 = b * SS + i0;

    // Load Q tile (hi/lo), rows are tokens m0..m0+63
    for (int i = tid; i < 1024; i += 256) {
        int r = i >> 4, c = (i & 15) * 8;
        long gi = (long)(m0 + r) * (NH * HD) + h * HD + c;
        *(uint4*)&sQh[r * FQSTR + c] = *(const uint4*)&Qh[gi];
        *(uint4*)&sQl[r * FQSTR + c] = *(const uint4*)&Ql[gi];
    }
    if (tid < 64) { m_s[tid] = -1e30f; l_s[tid] = 0.0f; }

    float out[8][4];
#pragma unroll
    for (int nt = 0; nt < 8; nt++)
#pragma unroll
        for (int j = 0; j < 4; j++) out[nt][j] = 0.0f;

    const int r0    = lane >> 2;
    const int qcol2 = (lane & 3) * 2;
    // ldsm A addressing (GEMM-verified formula)
    const int a_r = (lane & 7) + ((lane >> 3) & 1) * 8;
    const int a_c = (lane >> 4) * 8;
    // ldsm B (non-trans) addressing
    const int b_r = lane & 7;
    const int b_c = ((lane >> 3) & 1) * 8;
    // ldsm B (trans, V) addressing
    const int v_k = (lane & 7) + ((lane >> 3) & 1) * 8;
    const int v_n = (lane >> 4) * 8;

    for (int jt = 0; jt <= it; jt++) {
        const int j0 = jt * 64;
        __syncthreads();   // protect K/V/P smem from previous iteration readers

        // Load K and V tiles (hi/lo): 4 arrays x 1024 16B-chunks
        for (int i = tid; i < 1024; i += 256) {
            int r = i >> 4, c = (i & 15) * 8;
            long gi = (long)(b * SS + j0 + r) * (NKV * HD) + g * HD + c;
            int off = r * FQSTR + c;
            *(uint4*)&sKh[off] = *(const uint4*)&Kh[gi];
            *(uint4*)&sKl[off] = *(const uint4*)&Kl[gi];
            *(uint4*)&sVh[off] = *(const uint4*)&Vh[gi];
            *(uint4*)&sVl[off] = *(const uint4*)&Vl[gi];
        }
        __syncthreads();

        // ---- QK^T (split 3-term) ----
        float sc[4][4];
#pragma unroll
        for (int nt = 0; nt < 4; nt++)
#pragma unroll
            for (int j = 0; j < 4; j++) sc[nt][j] = 0.0f;

#pragma unroll
        for (int kg = 0; kg < 8; kg++) {
            uint32_t qh[4], ql[4];
            uint32_t aoff = (uint32_t)((wm + a_r) * FQSTR + kg * 16 + a_c) * 2;
            ldsm_x4(qh, aQh + aoff);
            ldsm_x4(ql, aQl + aoff);
#pragma unroll
            for (int nt = 0; nt < 4; nt++) {
                uint32_t boff =
                    (uint32_t)((cg * 32 + nt * 8 + b_r) * FQSTR + kg * 16 + b_c) * 2;
                uint32_t kh[2], kl[2];
                ldsm_x2(kh, aKh + boff);
                ldsm_x2(kl, aKl + boff);
                mma_bf16(sc[nt], qh, kh);
                mma_bf16(sc[nt], qh, kl);
                mma_bf16(sc[nt], ql, kh);
            }
        }

        // Causal mask on the diagonal tile
        if (jt == it) {
#pragma unroll
            for (int nt = 0; nt < 4; nt++) {
                int colb = j0 + cg * 32 + nt * 8 + qcol2;
                int rowa = i0 + wm + r0;
#pragma unroll
                for (int j = 0; j < 4; j++) {
                    int col = colb + (j & 1);
                    int row = rowa + (j >= 2 ? 8 : 0);
                    if (col > row) sc[nt][j] = -1e30f;
                }
            }
        }

        // Partial row max (this warp's 32 cols)
        float mx0 = -1e30f, mx1 = -1e30f;
#pragma unroll
        for (int nt = 0; nt < 4; nt++) {
            mx0 = fmaxf(mx0, fmaxf(sc[nt][0], sc[nt][1]));
            mx1 = fmaxf(mx1, fmaxf(sc[nt][2], sc[nt][3]));
        }
        mx0 = fmaxf(mx0, __shfl_xor_sync(0xffffffffu, mx0, 1));
        mx0 = fmaxf(mx0, __shfl_xor_sync(0xffffffffu, mx0, 2));
        mx1 = fmaxf(mx1, __shfl_xor_sync(0xffffffffu, mx1, 1));
        mx1 = fmaxf(mx1, __shfl_xor_sync(0xffffffffu, mx1, 2));
        if ((lane & 3) == 0) {
            pm[cg * 64 + wm + r0]     = mx0;
            pm[cg * 64 + wm + r0 + 8] = mx1;
        }
        __syncthreads();

        // Step A: softmax update in registers
        float mold0 = m_s[wm + r0], mold1 = m_s[wm + r0 + 8];
        float mn0 = fmaxf(mold0, fmaxf(pm[wm + r0], pm[64 + wm + r0]));
        float mn1 = fmaxf(mold1, fmaxf(pm[wm + r0 + 8], pm[64 + wm + r0 + 8]));
        float al0 = __expf(mold0 - mn0);
        float al1 = __expf(mold1 - mn1);
        float s0 = 0.0f, s1 = 0.0f;
#pragma unroll
        for (int nt = 0; nt < 4; nt++) {
            sc[nt][0] = __expf(sc[nt][0] - mn0);
            sc[nt][1] = __expf(sc[nt][1] - mn0);
            sc[nt][2] = __expf(sc[nt][2] - mn1);
            sc[nt][3] = __expf(sc[nt][3] - mn1);
            s0 += sc[nt][0] + sc[nt][1];
            s1 += sc[nt][2] + sc[nt][3];
        }
        s0 += __shfl_xor_sync(0xffffffffu, s0, 1);
        s0 += __shfl_xor_sync(0xffffffffu, s0, 2);
        s1 += __shfl_xor_sync(0xffffffffu, s1, 1);
        s1 += __shfl_xor_sync(0xffffffffu, s1, 2);
        if ((lane & 3) == 0) {
            ps[cg * 64 + wm + r0]     = s0;
            ps[cg * 64 + wm + r0 + 8] = s1;
        }

        // Rescale output accumulators (rows match score rows)
#pragma unroll
        for (int nt = 0; nt < 8; nt++) {
            out[nt][0] *= al0; out[nt][1] *= al0;
            out[nt][2] *= al1; out[nt][3] *= al1;
        }

        // Write P hi/lo to smem
#pragma unroll
        for (int nt = 0; nt < 4; nt++) {
            int col = cg * 32 + nt * 8 + qcol2;
            float p0 = sc[nt][0], p1 = sc[nt][1];
            float p2 = sc[nt][2], p3 = sc[nt][3];
            __nv_bfloat16 h0 = __float2bfloat16(p0);
            __nv_bfloat16 h1 = __float2bfloat16(p1);
            __nv_bfloat16 h2 = __float2bfloat16(p2);
            __nv_bfloat16 h3 = __float2bfloat16(p3);
            __nv_bfloat162 hp01; hp01.x = h0; hp01.y = h1;
            __nv_bfloat162 hp23; hp23.x = h2; hp23.y = h3;
            __nv_bfloat162 lp01, lp23;
            lp01.x = __float2bfloat16(p0 - __bfloat162float(h0));
            lp01.y = __float2bfloat16(p1 - __bfloat162float(h1));
            lp23.x = __float2bfloat16(p2 - __bfloat162float(h2));
            lp23.y = __float2bfloat16(p3 - __bfloat162float(h3));
            *(__nv_bfloat162*)&sPh[(wm + r0) * FPSTR + col]     = hp01;
            *(__nv_bfloat162*)&sPh[(wm + r0 + 8) * FPSTR + col] = hp23;
            *(__nv_bfloat162*)&sPl[(wm + r0) * FPSTR + col]     = lp01;
            *(__nv_bfloat162*)&sPl[(wm + r0 + 8) * FPSTR + col] = lp23;
        }
        __syncthreads();

        // Step B: m/l state update (one writer per row)
        if (cg == 0 && (lane & 3) == 0) {
            int rr = wm + r0;
            l_s[rr] = l_s[rr] * al0 + ps[rr] + ps[64 + rr];
            m_s[rr] = mn0;
            rr += 8;
            l_s[rr] = l_s[rr] * al1 + ps[rr] + ps[64 + rr];
            m_s[rr] = mn1;
        }

        // ---- P @ V (split 3-term), V via ldmatrix.trans ----
#pragma unroll
        for (int kg = 0; kg < 4; kg++) {
            uint32_t ph[4], pl[4];
            uint32_t aoff = (uint32_t)((wm + a_r) * FPSTR + kg * 16 + a_c) * 2;
            ldsm_x4(ph, aPh + aoff);
            ldsm_x4(pl, aPl + aoff);
#pragma unroll
            for (int ntp = 0; ntp < 4; ntp++) {
                int n0 = cg * 64 + ntp * 16;
                uint32_t voff =
                    (uint32_t)((kg * 16 + v_k) * FQSTR + n0 + v_n) * 2;
                uint32_t vh[4], vl[4];
                ldsm_x4_t(vh, aVh + voff);
                ldsm_x4_t(vl, aVl + voff);
                mma_bf16(out[2 * ntp],     ph, &vh[0]);
                mma_bf16(out[2 * ntp],     ph, &vl[0]);
                mma_bf16(out[2 * ntp],     pl, &vh[0]);
                mma_bf16(out[2 * ntp + 1], ph, &vh[2]);
                mma_bf16(out[2 * ntp + 1], ph, &vl[2]);
                mma_bf16(out[2 * ntp + 1], pl, &vh[2]);
            }
        }
    }

    __syncthreads();
    float inv0 = 1.0f / l_s[wm + r0];
    float inv1 = 1.0f / l_s[wm + r0 + 8];
#pragma unroll
    for (int nt = 0; nt < 8; nt++) {
        int col = cg * 64 + nt * 8 + qcol2;
        long ra = (long)(m0 + wm + r0) * (NH * HD) + h * HD + col;
        long rb = (long)(m0 + wm + r0 + 8) * (NH * HD) + h * HD + col;
        float2 v0, v1;
        v0.x = out[nt][0] * inv0; v0.y = out[nt][1] * inv0;
        v1.x = out[nt][2] * inv1; v1.y = out[nt][3] * inv1;
        *(float2*)&Og[ra] = v0;
        *(float2*)&Og[rb] = v1;
    }
}

// ---------------------------------------------------------------------------
// Launcher
// ---------------------------------------------------------------------------
static void run_split(const float* x, __nv_bfloat16* hi, __nv_bfloat16* lo,
                      int n, float scale = 1.0f)
{
    int nthr = n / 4;
    split_kernel<<<(nthr + 255) / 256, 256>>>(x, hi, lo, n, scale);
}

extern "C" void kernel_launch(void* const* d_in, const int* in_sizes, int n_in,
                              void* d_out, int out_size)
{
    const float* hidden = (const float*)d_in[0];
    const float* cosp   = (const float*)d_in[1];
    const float* sinp   = (const float*)d_in[2];
    const float* q_w = (const float*)d_in[4];
    const float* q_b = (const float*)d_in[5];
    const float* k_w = (const float*)d_in[6];
    const float* k_b = (const float*)d_in[7];
    const float* v_w = (const float*)d_in[8];
    const float* v_b = (const float*)d_in[9];
    const float* o_w = (const float*)d_in[10];
    float* out = (float*)d_out;

    float *qp, *kp, *vp, *aop;
    cudaGetSymbolAddress((void**)&qp, g_q);
    cudaGetSymbolAddress((void**)&kp, g_k);
    cudaGetSymbolAddress((void**)&vp, g_v);
    cudaGetSymbolAddress((void**)&aop, g_ao);

    __nv_bfloat16 *h_hi, *h_lo, *qw_hi, *qw_lo, *kw_hi, *kw_lo;
    __nv_bfloat16 *vw_hi, *vw_lo, *ow_hi, *ow_lo, *ao_hi, *ao_lo;
    __nv_bfloat16 *qh, *ql, *kh, *kl, *vh, *vl;
    cudaGetSymbolAddress((void**)&h_hi, g_h_hi);
    cudaGetSymbolAddress((void**)&h_lo, g_h_lo);
    cudaGetSymbolAddress((void**)&qw_hi, g_qw_hi);
    cudaGetSymbolAddress((void**)&qw_lo, g_qw_lo);
    cudaGetSymbolAddress((void**)&kw_hi, g_kw_hi);
    cudaGetSymbolAddress((void**)&kw_lo, g_kw_lo);
    cudaGetSymbolAddress((void**)&vw_hi, g_vw_hi);
    cudaGetSymbolAddress((void**)&vw_lo, g_vw_lo);
    cudaGetSymbolAddress((void**)&ow_hi, g_ow_hi);
    cudaGetSymbolAddress((void**)&ow_lo, g_ow_lo);
    cudaGetSymbolAddress((void**)&ao_hi, g_ao_hi);
    cudaGetSymbolAddress((void**)&ao_lo, g_ao_lo);
    cudaGetSymbolAddress((void**)&qh, g_qh);
    cudaGetSymbolAddress((void**)&ql, g_ql);
    cudaGetSymbolAddress((void**)&kh, g_kh);
    cudaGetSymbolAddress((void**)&kl, g_kl);
    cudaGetSymbolAddress((void**)&vh, g_vh);
    cudaGetSymbolAddress((void**)&vl, g_vl);

    // Input splits
    run_split(hidden, h_hi, h_lo, M_TOK * HH);
    run_split(q_w, qw_hi, qw_lo, NH * HD * HH);
    run_split(k_w, kw_hi, kw_lo, NKV * HD * HH);
    run_split(v_w, vw_hi, vw_lo, NKV * HD * HH);
    run_split(o_w, ow_hi, ow_lo, HH * NH * HD);

    // QKV projections (tensor cores)
    gemm_mma_kernel<<<dim3((NH * HD) / 128, M_TOK / 128), 256>>>(
        h_hi, h_lo, qw_hi, qw_lo, q_b, qp, M_TOK, NH * HD, HH);
    gemm_mma_kernel<<<dim3((NKV * HD) / 128, M_TOK / 128), 256>>>(
        h_hi, h_lo, kw_hi, kw_lo, k_b, kp, M_TOK, NKV * HD, HH);
    gemm_mma_kernel<<<dim3((NKV * HD) / 128, M_TOK / 128), 256>>>(
        h_hi, h_lo, vw_hi, vw_lo, v_b, vp, M_TOK, NKV * HD, HH);

    // RoPE
    {
        int nq = M_TOK * NH * 64;
        rope_kernel<<<(nq + 255) / 256, 256>>>(qp, cosp, sinp, NH, nq);
        int nk = M_TOK * NKV * 64;
        rope_kernel<<<(nk + 255) / 256, 256>>>(kp, cosp, sinp, NKV, nk);
    }

    // Attention operand splits (scale folded into Q)
    run_split(qp, qh, ql, M_TOK * NH * HD, SCALE_F);
    run_split(kp, kh, kl, M_TOK * NKV * HD);
    run_split(vp, vh, vl, M_TOK * NKV * HD);

    // Tensor-core flash attention
    cudaFuncSetAttribute(flash_mma_kernel,
                         cudaFuncAttributeMaxDynamicSharedMemorySize, FSM_BYTES);
    flash_mma_kernel<<<dim3(SS / 64, NH, BB), 256, FSM_BYTES>>>(
        qh, ql, kh, kl, vh, vl, aop);

    // Output projection
    run_split(aop, ao_hi, ao_lo, M_TOK * NH * HD);
    gemm_mma_kernel<<<dim3(HH / 128, M_TOK / 128), 256>>>(
        ao_hi, ao_lo, ow_hi, ow_lo, (const float*)nullptr, out, M_TOK, HH, NH * HD);
}

// round 5
// speedup vs baseline: 7.2432x; 1.5202x over previous
#include <cuda_runtime.h>
#include <cuda_fp16.h>
#include <math.h>
#include <stdint.h>

// Problem constants
#define BB 2
#define SS 2048
#define HH 2048
#define NH 16
#define NKV 4
#define HD 128
#define NREP (NH / NKV)
#define M_TOK (BB * SS)
#define SCALE_F 0.08838834764831845f

// ---------------------------------------------------------------------------
// Scratch (fp16 everywhere; no fp32 intermediates)
// ---------------------------------------------------------------------------
__device__ __half g_h_h[M_TOK * HH];                      // hidden hi
__device__ __half g_qw_h[NH * HD * HH],  g_qw_l[NH * HD * HH];
__device__ __half g_kw_h[NKV * HD * HH], g_kw_l[NKV * HD * HH];
__device__ __half g_vw_h[NKV * HD * HH], g_vw_l[NKV * HD * HH];
__device__ __half g_ow_h[HH * NH * HD],  g_ow_l[HH * NH * HD];
__device__ __half g_qh[M_TOK * NH * HD];                  // Q hi (scaled, roped)
__device__ __half g_kh[M_TOK * NKV * HD], g_kl[M_TOK * NKV * HD];
__device__ __half g_vh[M_TOK * NKV * HD], g_vl[M_TOK * NKV * HD];
__device__ __half g_ao_h[M_TOK * NH * HD];                // attention out hi

// ---------------------------------------------------------------------------
// Warp MMA helpers
// ---------------------------------------------------------------------------
__device__ __forceinline__ uint32_t smem_u32(const void* p) {
    uint32_t a;
    asm("{ .reg .u64 t; cvta.to.shared.u64 t, %1; cvt.u32.u64 %0, t; }"
        : "=r"(a) : "l"(p));
    return a;
}
__device__ __forceinline__ void ldsm_x4(uint32_t* r, uint32_t addr) {
    asm volatile("ldmatrix.sync.aligned.m8n8.x4.shared.b16 {%0,%1,%2,%3}, [%4];"
                 : "=r"(r[0]), "=r"(r[1]), "=r"(r[2]), "=r"(r[3]) : "r"(addr));
}
__device__ __forceinline__ void ldsm_x2(uint32_t* r, uint32_t addr) {
    asm volatile("ldmatrix.sync.aligned.m8n8.x2.shared.b16 {%0,%1}, [%2];"
                 : "=r"(r[0]), "=r"(r[1]) : "r"(addr));
}
__device__ __forceinline__ void ldsm_x4_t(uint32_t* r, uint32_t addr) {
    asm volatile("ldmatrix.sync.aligned.m8n8.x4.trans.shared.b16 {%0,%1,%2,%3}, [%4];"
                 : "=r"(r[0]), "=r"(r[1]), "=r"(r[2]), "=r"(r[3]) : "r"(addr));
}
__device__ __forceinline__ void mma_f16(float* c, const uint32_t* a, const uint32_t* b) {
    asm volatile(
        "mma.sync.aligned.m16n8k16.row.col.f32.f16.f16.f32 "
        "{%0,%1,%2,%3}, {%4,%5,%6,%7}, {%8,%9}, {%0,%1,%2,%3};"
        : "+f"(c[0]), "+f"(c[1]), "+f"(c[2]), "+f"(c[3])
        : "r"(a[0]), "r"(a[1]), "r"(a[2]), "r"(a[3]), "r"(b[0]), "r"(b[1]));
}

// ---------------------------------------------------------------------------
// fp32 -> fp16 splits (8 elems/thread, 2 independent float4 loads)
// ---------------------------------------------------------------------------
__device__ __forceinline__ uint32_t pack2h(float a, float b) {
    __half2 t = __floats2half2_rn(a, b);
    return *(uint32_t*)&t;
}

__global__ void split2_kernel(const float* __restrict__ x,
                              __half* __restrict__ hi, __half* __restrict__ lo,
                              int n)
{
    int i = (blockIdx.x * blockDim.x + threadIdx.x) << 3;
    if (i >= n) return;
    float4 a = *(const float4*)(x + i);
    float4 b = *(const float4*)(x + i + 4);
    float v[8] = {a.x, a.y, a.z, a.w, b.x, b.y, b.z, b.w};
    float hf[8], lf[8];
#pragma unroll
    for (int j = 0; j < 8; j++) {
        __half h = __float2half_rn(v[j]);
        hf[j] = __half2float(h);
        lf[j] = v[j] - hf[j];
    }
    uint4 uh, ul;
    uh.x = pack2h(hf[0], hf[1]); uh.y = pack2h(hf[2], hf[3]);
    uh.z = pack2h(hf[4], hf[5]); uh.w = pack2h(hf[6], hf[7]);
    ul.x = pack2h(lf[0], lf[1]); ul.y = pack2h(lf[2], lf[3]);
    ul.z = pack2h(lf[4], lf[5]); ul.w = pack2h(lf[6], lf[7]);
    *(uint4*)(hi + i) = uh;
    *(uint4*)(lo + i) = ul;
}

__global__ void split1_kernel(const float* __restrict__ x,
                              __half* __restrict__ hi, int n)
{
    int i = (blockIdx.x * blockDim.x + threadIdx.x) << 3;
    if (i >= n) return;
    float4 a = *(const float4*)(x + i);
    float4 b = *(const float4*)(x + i + 4);
    uint4 uh;
    uh.x = pack2h(a.x, a.y); uh.y = pack2h(a.z, a.w);
    uh.z = pack2h(b.x, b.y); uh.w = pack2h(b.z, b.w);
    *(uint4*)(hi + i) = uh;
}

// ---------------------------------------------------------------------------
// fp16 2-term tensor-core GEMM: C[M,N] = A[M,K] @ W[N,K]^T (+bias)
// C = Ah*Bh + Ah*Bl  (A activation hi-only; B weight hi+lo), fp32 accum.
// Block tile 128x128, BK=32, 8 warps (4x2 / m x n), warp tile 32x64.
// Epilogue modes: 0 = fp32 store, 1 = RoPE + fp16 split, 2 = fp16 split.
// ---------------------------------------------------------------------------
#define SSTR 40

__global__ __launch_bounds__(256) void gemm_mma_kernel(
    const __half* __restrict__ Ah,
    const __half* __restrict__ Bh, const __half* __restrict__ Bl,
    const float* __restrict__ bias,
    __half* __restrict__ Chi, __half* __restrict__ Clo,
    float* __restrict__ Cf,
    const float* __restrict__ cosp, const float* __restrict__ sinp,
    float scale, int M, int N, int K, int mode)
{
    __shared__ __align__(16) char smem_raw[33792];
    __half* sAh = (__half*)smem_raw;
    __half* sBh = (__half*)(smem_raw + 10240);
    __half* sBl = (__half*)(smem_raw + 20480);

    const int tid  = threadIdx.x;
    const int wid  = tid >> 5;
    const int lane = tid & 31;
    const int wm   = (wid >> 1) * 32;
    const int wn   = (wid & 1) * 64;
    const int row0 = blockIdx.y * 128;
    const int col0 = blockIdx.x * 128;

    float acc[2][8][4];
#pragma unroll
    for (int mt = 0; mt < 2; mt++)
#pragma unroll
        for (int nt = 0; nt < 8; nt++)
#pragma unroll
            for (int j = 0; j < 4; j++) acc[mt][nt][j] = 0.0f;

    const uint32_t aAh = smem_u32(sAh);
    const uint32_t aBh = smem_u32(sBh), aBl = smem_u32(sBl);

    const int a_r = wm + (lane & 7) + ((lane >> 3) & 1) * 8;
    const int a_c = (lane >> 4) * 8;
    const int b_r = wn + (lane & 7);
    const int b_c = ((lane >> 3) & 1) * 8;

    uint4 pA[2], pBh[2], pBl[2];
#pragma unroll
    for (int j = 0; j < 2; j++) {
        int ch = tid + j * 256;
        int r = ch >> 2, c = (ch & 3) * 8;
        long ga = (long)(row0 + r) * K + c;
        long gb = (long)(col0 + r) * K + c;
        pA[j]  = *(const uint4*)(Ah + ga);
        pBh[j] = *(const uint4*)(Bh + gb);
        pBl[j] = *(const uint4*)(Bl + gb);
    }

    for (int k0 = 0; k0 < K; k0 += 32) {
#pragma unroll
        for (int j = 0; j < 2; j++) {
            int ch = tid + j * 256;
            int r = ch >> 2, c = (ch & 3) * 8;
            int off = r * SSTR + c;
            *(uint4*)&sAh[off] = pA[j];
            *(uint4*)&sBh[off] = pBh[j];
            *(uint4*)&sBl[off] = pBl[j];
        }
        __syncthreads();

        if (k0 + 32 < K) {
#pragma unroll
            for (int j = 0; j < 2; j++) {
                int ch = tid + j * 256;
                int r = ch >> 2, c = (ch & 3) * 8;
                long ga = (long)(row0 + r) * K + k0 + 32 + c;
                long gb = (long)(col0 + r) * K + k0 + 32 + c;
                pA[j]  = *(const uint4*)(Ah + ga);
                pBh[j] = *(const uint4*)(Bh + gb);
                pBl[j] = *(const uint4*)(Bl + gb);
            }
        }

#pragma unroll
        for (int ks = 0; ks < 2; ks++) {
            uint32_t ah[2][4];
#pragma unroll
            for (int mt = 0; mt < 2; mt++) {
                uint32_t off = (uint32_t)((a_r + mt * 16) * SSTR + ks * 16 + a_c) * 2;
                ldsm_x4(ah[mt], aAh + off);
            }
#pragma unroll
            for (int nt = 0; nt < 8; nt++) {
                uint32_t boff = (uint32_t)((b_r + nt * 8) * SSTR + ks * 16 + b_c) * 2;
                uint32_t bh[2], bl[2];
                ldsm_x2(bh, aBh + boff);
                ldsm_x2(bl, aBl + boff);
#pragma unroll
                for (int mt = 0; mt < 2; mt++) {
                    mma_f16(acc[mt][nt], ah[mt], bh);
                    mma_f16(acc[mt][nt], ah[mt], bl);
                }
            }
        }
        __syncthreads();
    }

    // ---------------- Epilogues ----------------
    if (mode == 0) {
        const int em = row0 + wm + (lane >> 2);
        const int en = col0 + wn + (lane & 3) * 2;
#pragma unroll
        for (int mt = 0; mt < 2; mt++) {
#pragma unroll
            for (int nt = 0; nt < 8; nt++) {
                int n = en + nt * 8;
                float b0 = bias ? bias[n] : 0.0f;
                float b1 = bias ? bias[n + 1] : 0.0f;
                float2 v0, v1;
                v0.x = acc[mt][nt][0] + b0; v0.y = acc[mt][nt][1] + b1;
                v1.x = acc[mt][nt][2] + b0; v1.y = acc[mt][nt][3] + b1;
                *(float2*)&Cf[(long)(em + mt * 16) * N + n] = v0;
                *(float2*)&Cf[(long)(em + mt * 16 + 8) * N + n] = v1;
            }
        }
    } else if (mode == 2) {
        // direct fp16 split (V projection)
        const int em = row0 + wm + (lane >> 2);
        const int enl = wn + (lane & 3) * 2;
#pragma unroll
        for (int mt = 0; mt < 2; mt++) {
#pragma unroll
            for (int nt = 0; nt < 8; nt++) {
                int n = col0 + enl + nt * 8;
                float b0 = bias[n], b1 = bias[n + 1];
                float v00 = acc[mt][nt][0] + b0, v01 = acc[mt][nt][1] + b1;
                float v10 = acc[mt][nt][2] + b0, v11 = acc[mt][nt][3] + b1;
                long o0 = (long)(em + mt * 16) * N + n;
                long o1 = (long)(em + mt * 16 + 8) * N + n;
                __half h00 = __float2half_rn(v00), h01 = __float2half_rn(v01);
                __half h10 = __float2half_rn(v10), h11 = __float2half_rn(v11);
                *(uint32_t*)&Chi[o0] = pack2h(__half2float(h00), __half2float(h01));
                *(uint32_t*)&Chi[o1] = pack2h(__half2float(h10), __half2float(h11));
                *(uint32_t*)&Clo[o0] = pack2h(v00 - __half2float(h00), v01 - __half2float(h01));
                *(uint32_t*)&Clo[o1] = pack2h(v10 - __half2float(h10), v11 - __half2float(h11));
            }
        }
    } else {
        // mode 1: bias + RoPE + fp16 split via 64-row smem staging
        float* buf = (float*)smem_raw;   // 64 x 132 fp32
        const int r0l = lane >> 2;
        const int c0l = (lane & 3) * 2;
#pragma unroll
        for (int hf = 0; hf < 2; hf++) {
            __syncthreads();
            int slotA = (wid >> 1) * 16 + r0l;
#pragma unroll
            for (int nt = 0; nt < 8; nt++) {
                int cc = wn + nt * 8 + c0l;
                float b0 = bias[col0 + cc];
                float b1 = bias[col0 + cc + 1];
                buf[slotA * 132 + cc]           = acc[hf][nt][0] + b0;
                buf[slotA * 132 + cc + 1]       = acc[hf][nt][1] + b1;
                buf[(slotA + 8) * 132 + cc]     = acc[hf][nt][2] + b0;
                buf[(slotA + 8) * 132 + cc + 1] = acc[hf][nt][3] + b1;
            }
            __syncthreads();
            for (int i = tid; i < 4096; i += 256) {
                int slot = i >> 6, d = i & 63;
                int grow = row0 + (slot >> 4) * 32 + hf * 16 + (slot & 15);
                float x1 = buf[slot * 132 + d];
                float x2 = buf[slot * 132 + d + 64];
                long cb = (long)grow * HD;
                float c1 = cosp[cb + d],      s1 = sinp[cb + d];
                float c2 = cosp[cb + d + 64], s2 = sinp[cb + d + 64];
                float y1 = (x1 * c1 - x2 * s1) * scale;
                float y2 = (x2 * c2 + x1 * s2) * scale;
                long o1 = (long)grow * N + col0 + d;
                long o2 = o1 + 64;
                __half h1 = __float2half_rn(y1);
                __half h2 = __float2half_rn(y2);
                Chi[o1] = h1; Chi[o2] = h2;
                if (Clo) {
                    Clo[o1] = __float2half_rn(y1 - __half2float(h1));
                    Clo[o2] = __float2half_rn(y2 - __half2float(h2));
                }
            }
        }
    }
}

// ---------------------------------------------------------------------------
// fp16 tensor-core flash attention (causal, GQA).
// Q hi-only (pre-scaled, roped); K,V hi+lo; P hi-only; out fp16 hi-only.
// Block = 256 threads (8 warps), BQ=BKV=64.
// ---------------------------------------------------------------------------
#define FQSTR 136
#define FPSTR 72

#define OQH 0u
#define OKH 17408u
#define OKL 34816u
#define OVH 52224u
#define OVL 69632u
#define OPH 87040u
#define OPM 96256u
#define OPS 96768u
#define OMS 97280u
#define OLS 97536u
#define FSM_BYTES 97792u

__global__ __launch_bounds__(256) void flash_mma_kernel(
    const __half* __restrict__ Qh,
    const __half* __restrict__ Kh, const __half* __restrict__ Kl,
    const __half* __restrict__ Vh, const __half* __restrict__ Vl,
    __half* __restrict__ AOh)
{
    extern __shared__ char fsm2[];
    __half* sQh = (__half*)(fsm2 + OQH);
    __half* sKh = (__half*)(fsm2 + OKH);
    __half* sKl = (__half*)(fsm2 + OKL);
    __half* sVh = (__half*)(fsm2 + OVH);
    __half* sVl = (__half*)(fsm2 + OVL);
    __half* sPh = (__half*)(fsm2 + OPH);
    float* pm  = (float*)(fsm2 + OPM);
    float* ps  = (float*)(fsm2 + OPS);
    float* m_s = (float*)(fsm2 + OMS);
    float* l_s = (float*)(fsm2 + OLS);

    const uint32_t aQh = smem_u32(sQh);
    const uint32_t aKh = smem_u32(sKh), aKl = smem_u32(sKl);
    const uint32_t aVh = smem_u32(sVh), aVl = smem_u32(sVl);
    const uint32_t aPh = smem_u32(sPh);

    const int it = blockIdx.x;
    const int h  = blockIdx.y;
    const int b  = blockIdx.z;
    const int g  = h / NREP;
    const int tid  = threadIdx.x;
    const int wid  = tid >> 5;
    const int lane = tid & 31;
    const int wm   = (wid & 3) * 16;
    const int cg   = wid >> 2;
    const int i0 = it * 64;
    const int m0 = b * SS + i0;

    for (int i = tid; i < 1024; i += 256) {
        int r = i >> 4, c = (i & 15) * 8;
        long gi = (long)(m0 + r) * (NH * HD) + h * HD + c;
        *(uint4*)&sQh[r * FQSTR + c] = *(const uint4*)&Qh[gi];
    }
    if (tid < 64) { m_s[tid] = -1e30f; l_s[tid] = 0.0f; }

    float out[8][4];
#pragma unroll
    for (int nt = 0; nt < 8; nt++)
#pragma unroll
        for (int j = 0; j < 4; j++) out[nt][j] = 0.0f;

    const int r0    = lane >> 2;
    const int qcol2 = (lane & 3) * 2;
    const int a_r = (lane & 7) + ((lane >> 3) & 1) * 8;
    const int a_c = (lane >> 4) * 8;
    const int b_r = lane & 7;
    const int b_c = ((lane >> 3) & 1) * 8;
    const int v_k = (lane & 7) + ((lane >> 3) & 1) * 8;
    const int v_n = (lane >> 4) * 8;

    for (int jt = 0; jt <= it; jt++) {
        const int j0 = jt * 64;
        __syncthreads();

        for (int i = tid; i < 1024; i += 256) {
            int r = i >> 4, c = (i & 15) * 8;
            long gi = (long)(b * SS + j0 + r) * (NKV * HD) + g * HD + c;
            int off = r * FQSTR + c;
            *(uint4*)&sKh[off] = *(const uint4*)&Kh[gi];
            *(uint4*)&sKl[off] = *(const uint4*)&Kl[gi];
            *(uint4*)&sVh[off] = *(const uint4*)&Vh[gi];
            *(uint4*)&sVl[off] = *(const uint4*)&Vl[gi];
        }
        __syncthreads();

        // ---- QK^T: Qh*Kh + Qh*Kl ----
        float sc[4][4];
#pragma unroll
        for (int nt = 0; nt < 4; nt++)
#pragma unroll
            for (int j = 0; j < 4; j++) sc[nt][j] = 0.0f;

#pragma unroll
        for (int kg = 0; kg < 8; kg++) {
            uint32_t qh[4];
            uint32_t aoff = (uint32_t)((wm + a_r) * FQSTR + kg * 16 + a_c) * 2;
            ldsm_x4(qh, aQh + aoff);
#pragma unroll
            for (int nt = 0; nt < 4; nt++) {
                uint32_t boff =
                    (uint32_t)((cg * 32 + nt * 8 + b_r) * FQSTR + kg * 16 + b_c) * 2;
                uint32_t kh[2], kl[2];
                ldsm_x2(kh, aKh + boff);
                ldsm_x2(kl, aKl + boff);
                mma_f16(sc[nt], qh, kh);
                mma_f16(sc[nt], qh, kl);
            }
        }

        if (jt == it) {
#pragma unroll
            for (int nt = 0; nt < 4; nt++) {
                int colb = j0 + cg * 32 + nt * 8 + qcol2;
                int rowa = i0 + wm + r0;
#pragma unroll
                for (int j = 0; j < 4; j++) {
                    int col = colb + (j & 1);
                    int row = rowa + (j >= 2 ? 8 : 0);
                    if (col > row) sc[nt][j] = -1e30f;
                }
            }
        }

        float mx0 = -1e30f, mx1 = -1e30f;
#pragma unroll
        for (int nt = 0; nt < 4; nt++) {
            mx0 = fmaxf(mx0, fmaxf(sc[nt][0], sc[nt][1]));
            mx1 = fmaxf(mx1, fmaxf(sc[nt][2], sc[nt][3]));
        }
        mx0 = fmaxf(mx0, __shfl_xor_sync(0xffffffffu, mx0, 1));
        mx0 = fmaxf(mx0, __shfl_xor_sync(0xffffffffu, mx0, 2));
        mx1 = fmaxf(mx1, __shfl_xor_sync(0xffffffffu, mx1, 1));
        mx1 = fmaxf(mx1, __shfl_xor_sync(0xffffffffu, mx1, 2));
        if ((lane & 3) == 0) {
            pm[cg * 64 + wm + r0]     = mx0;
            pm[cg * 64 + wm + r0 + 8] = mx1;
        }
        __syncthreads();

        float mold0 = m_s[wm + r0], mold1 = m_s[wm + r0 + 8];
        float mn0 = fmaxf(mold0, fmaxf(pm[wm + r0], pm[64 + wm + r0]));
        float mn1 = fmaxf(mold1, fmaxf(pm[wm + r0 + 8], pm[64 + wm + r0 + 8]));
        float al0 = __expf(mold0 - mn0);
        float al1 = __expf(mold1 - mn1);
        float s0 = 0.0f, s1 = 0.0f;
#pragma unroll
        for (int nt = 0; nt < 4; nt++) {
            sc[nt][0] = __expf(sc[nt][0] - mn0);
            sc[nt][1] = __expf(sc[nt][1] - mn0);
            sc[nt][2] = __expf(sc[nt][2] - mn1);
            sc[nt][3] = __expf(sc[nt][3] - mn1);
            s0 += sc[nt][0] + sc[nt][1];
            s1 += sc[nt][2] + sc[nt][3];
        }
        s0 += __shfl_xor_sync(0xffffffffu, s0, 1);
        s0 += __shfl_xor_sync(0xffffffffu, s0, 2);
        s1 += __shfl_xor_sync(0xffffffffu, s1, 1);
        s1 += __shfl_xor_sync(0xffffffffu, s1, 2);
        if ((lane & 3) == 0) {
            ps[cg * 64 + wm + r0]     = s0;
            ps[cg * 64 + wm + r0 + 8] = s1;
        }

#pragma unroll
        for (int nt = 0; nt < 8; nt++) {
            out[nt][0] *= al0; out[nt][1] *= al0;
            out[nt][2] *= al1; out[nt][3] *= al1;
        }

        // P hi to smem
#pragma unroll
        for (int nt = 0; nt < 4; nt++) {
            int col = cg * 32 + nt * 8 + qcol2;
            *(uint32_t*)&sPh[(wm + r0) * FPSTR + col]     = pack2h(sc[nt][0], sc[nt][1]);
            *(uint32_t*)&sPh[(wm + r0 + 8) * FPSTR + col] = pack2h(sc[nt][2], sc[nt][3]);
        }
        __syncthreads();

        if (cg == 0 && (lane & 3) == 0) {
            int rr = wm + r0;
            l_s[rr] = l_s[rr] * al0 + ps[rr] + ps[64 + rr];
            m_s[rr] = mn0;
            rr += 8;
            l_s[rr] = l_s[rr] * al1 + ps[rr] + ps[64 + rr];
            m_s[rr] = mn1;
        }

        // ---- P @ V: Ph*Vh + Ph*Vl ----
#pragma unroll
        for (int kg = 0; kg < 4; kg++) {
            uint32_t ph[4];
            uint32_t aoff = (uint32_t)((wm + a_r) * FPSTR + kg * 16 + a_c) * 2;
            ldsm_x4(ph, aPh + aoff);
#pragma unroll
            for (int ntp = 0; ntp < 4; ntp++) {
                int n0 = cg * 64 + ntp * 16;
                uint32_t voff = (uint32_t)((kg * 16 + v_k) * FQSTR + n0 + v_n) * 2;
                uint32_t vh[4], vl[4];
                ldsm_x4_t(vh, aVh + voff);
                ldsm_x4_t(vl, aVl + voff);
                mma_f16(out[2 * ntp],     ph, &vh[0]);
                mma_f16(out[2 * ntp],     ph, &vl[0]);
                mma_f16(out[2 * ntp + 1], ph, &vh[2]);
                mma_f16(out[2 * ntp + 1], ph, &vl[2]);
            }
        }
    }

    __syncthreads();
    float inv0 = 1.0f / l_s[wm + r0];
    float inv1 = 1.0f / l_s[wm + r0 + 8];
#pragma unroll
    for (int nt = 0; nt < 8; nt++) {
        int col = cg * 64 + nt * 8 + qcol2;
        long ra = (long)(m0 + wm + r0) * (NH * HD) + h * HD + col;
        long rb = (long)(m0 + wm + r0 + 8) * (NH * HD) + h * HD + col;
        *(uint32_t*)&AOh[ra] = pack2h(out[nt][0] * inv0, out[nt][1] * inv0);
        *(uint32_t*)&AOh[rb] = pack2h(out[nt][2] * inv1, out[nt][3] * inv1);
    }
}

// ---------------------------------------------------------------------------
// Launcher
// ---------------------------------------------------------------------------
extern "C" void kernel_launch(void* const* d_in, const int* in_sizes, int n_in,
                              void* d_out, int out_size)
{
    const float* hidden = (const float*)d_in[0];
    const float* cosp   = (const float*)d_in[1];
    const float* sinp   = (const float*)d_in[2];
    const float* q_w = (const float*)d_in[4];
    const float* q_b = (const float*)d_in[5];
    const float* k_w = (const float*)d_in[6];
    const float* k_b = (const float*)d_in[7];
    const float* v_w = (const float*)d_in[8];
    const float* v_b = (const float*)d_in[9];
    const float* o_w = (const float*)d_in[10];
    float* out = (float*)d_out;

    __half *h_h, *qw_h, *qw_l, *kw_h, *kw_l, *vw_h, *vw_l, *ow_h, *ow_l;
    __half *qh, *kh, *kl, *vh, *vl, *ao_h;
    cudaGetSymbolAddress((void**)&h_h, g_h_h);
    cudaGetSymbolAddress((void**)&qw_h, g_qw_h);
    cudaGetSymbolAddress((void**)&qw_l, g_qw_l);
    cudaGetSymbolAddress((void**)&kw_h, g_kw_h);
    cudaGetSymbolAddress((void**)&kw_l, g_kw_l);
    cudaGetSymbolAddress((void**)&vw_h, g_vw_h);
    cudaGetSymbolAddress((void**)&vw_l, g_vw_l);
    cudaGetSymbolAddress((void**)&ow_h, g_ow_h);
    cudaGetSymbolAddress((void**)&ow_l, g_ow_l);
    cudaGetSymbolAddress((void**)&qh, g_qh);
    cudaGetSymbolAddress((void**)&kh, g_kh);
    cudaGetSymbolAddress((void**)&kl, g_kl);
    cudaGetSymbolAddress((void**)&vh, g_vh);
    cudaGetSymbolAddress((void**)&vl, g_vl);
    cudaGetSymbolAddress((void**)&ao_h, g_ao_h);

    // Splits (weights hi+lo; hidden hi only)
    {
        int n;
        n = M_TOK * HH;
        split1_kernel<<<n / 8 / 256, 256>>>(hidden, h_h, n);
        n = NH * HD * HH;
        split2_kernel<<<n / 8 / 256, 256>>>(q_w, qw_h, qw_l, n);
        n = NKV * HD * HH;
        split2_kernel<<<n / 8 / 256, 256>>>(k_w, kw_h, kw_l, n);
        split2_kernel<<<n / 8 / 256, 256>>>(v_w, vw_h, vw_l, n);
        n = HH * NH * HD;
        split2_kernel<<<n / 8 / 256, 256>>>(o_w, ow_h, ow_l, n);
    }

    // Q projection: bias + RoPE + scale, fp16 hi only
    gemm_mma_kernel<<<dim3((NH * HD) / 128, M_TOK / 128), 256>>>(
        h_h, qw_h, qw_l, q_b, qh, (__half*)nullptr, (float*)nullptr,
        cosp, sinp, SCALE_F, M_TOK, NH * HD, HH, 1);
    // K projection: bias + RoPE, fp16 hi+lo
    gemm_mma_kernel<<<dim3((NKV * HD) / 128, M_TOK / 128), 256>>>(
        h_h, kw_h, kw_l, k_b, kh, kl, (float*)nullptr,
        cosp, sinp, 1.0f, M_TOK, NKV * HD, HH, 1);
    // V projection: bias, fp16 hi+lo
    gemm_mma_kernel<<<dim3((NKV * HD) / 128, M_TOK / 128), 256>>>(
        h_h, vw_h, vw_l, v_b, vh, vl, (float*)nullptr,
        (const float*)nullptr, (const float*)nullptr, 1.0f,
        M_TOK, NKV * HD, HH, 2);

    // Flash attention (fp16 tensor cores), writes fp16 hi
    cudaFuncSetAttribute(flash_mma_kernel,
                         cudaFuncAttributeMaxDynamicSharedMemorySize, FSM_BYTES);
    flash_mma_kernel<<<dim3(SS / 64, NH, BB), 256, FSM_BYTES>>>(
        qh, kh, kl, vh, vl, ao_h);

    // Output projection: fp32 out, no bias
    gemm_mma_kernel<<<dim3(HH / 128, M_TOK / 128), 256>>>(
        ao_h, ow_h, ow_l, (const float*)nullptr,
        (__half*)nullptr, (__half*)nullptr, out,
        (const float*)nullptr, (const float*)nullptr, 1.0f,
        M_TOK, HH, NH * HD, 0);
}

// round 6
// speedup vs baseline: 7.6225x; 1.0524x over previous
#include <cuda_runtime.h>
#include <cuda_fp16.h>
#include <math.h>
#include <stdint.h>

// Problem constants
#define BB 2
#define SS 2048
#define HH 2048
#define NH 16
#define NKV 4
#define HD 128
#define NREP (NH / NKV)
#define M_TOK (BB * SS)
#define SCALE_F 0.08838834764831845f

// ---------------------------------------------------------------------------
// Scratch (fp16 everywhere)
// ---------------------------------------------------------------------------
__device__ __half g_h_h[M_TOK * HH];
__device__ __half g_qw_h[NH * HD * HH],  g_qw_l[NH * HD * HH];
__device__ __half g_kw_h[NKV * HD * HH], g_kw_l[NKV * HD * HH];
__device__ __half g_vw_h[NKV * HD * HH], g_vw_l[NKV * HD * HH];
__device__ __half g_ow_h[HH * NH * HD],  g_ow_l[HH * NH * HD];
__device__ __half g_qh[M_TOK * NH * HD];
__device__ __half g_kh[M_TOK * NKV * HD], g_kl[M_TOK * NKV * HD];
__device__ __half g_vh[M_TOK * NKV * HD], g_vl[M_TOK * NKV * HD];
__device__ __half g_ao_h[M_TOK * NH * HD];

// ---------------------------------------------------------------------------
// Helpers
// ---------------------------------------------------------------------------
__device__ __forceinline__ uint32_t smem_u32(const void* p) {
    uint32_t a;
    asm("{ .reg .u64 t; cvta.to.shared.u64 t, %1; cvt.u32.u64 %0, t; }"
        : "=r"(a) : "l"(p));
    return a;
}
__device__ __forceinline__ void ldsm_x4(uint32_t* r, uint32_t addr) {
    asm volatile("ldmatrix.sync.aligned.m8n8.x4.shared.b16 {%0,%1,%2,%3}, [%4];"
                 : "=r"(r[0]), "=r"(r[1]), "=r"(r[2]), "=r"(r[3]) : "r"(addr));
}
__device__ __forceinline__ void ldsm_x2(uint32_t* r, uint32_t addr) {
    asm volatile("ldmatrix.sync.aligned.m8n8.x2.shared.b16 {%0,%1}, [%2];"
                 : "=r"(r[0]), "=r"(r[1]) : "r"(addr));
}
__device__ __forceinline__ void ldsm_x4_t(uint32_t* r, uint32_t addr) {
    asm volatile("ldmatrix.sync.aligned.m8n8.x4.trans.shared.b16 {%0,%1,%2,%3}, [%4];"
                 : "=r"(r[0]), "=r"(r[1]), "=r"(r[2]), "=r"(r[3]) : "r"(addr));
}
__device__ __forceinline__ void mma_f16(float* c, const uint32_t* a, const uint32_t* b) {
    asm volatile(
        "mma.sync.aligned.m16n8k16.row.col.f32.f16.f16.f32 "
        "{%0,%1,%2,%3}, {%4,%5,%6,%7}, {%8,%9}, {%0,%1,%2,%3};"
        : "+f"(c[0]), "+f"(c[1]), "+f"(c[2]), "+f"(c[3])
        : "r"(a[0]), "r"(a[1]), "r"(a[2]), "r"(a[3]), "r"(b[0]), "r"(b[1]));
}
__device__ __forceinline__ void cp_async16(uint32_t dst, const void* src) {
    asm volatile("cp.async.cg.shared.global [%0], [%1], 16;"
                 :: "r"(dst), "l"(src));
}
__device__ __forceinline__ void cp_commit() {
    asm volatile("cp.async.commit_group;" ::: "memory");
}
template <int N> __device__ __forceinline__ void cp_wait() {
    asm volatile("cp.async.wait_group %0;" :: "n"(N) : "memory");
}
__device__ __forceinline__ uint32_t pack2h(float a, float b) {
    __half2 t = __floats2half2_rn(a, b);
    return *(uint32_t*)&t;
}

// ---------------------------------------------------------------------------
// fp32 -> fp16 splits
// ---------------------------------------------------------------------------
__global__ void split2_kernel(const float* __restrict__ x,
                              __half* __restrict__ hi, __half* __restrict__ lo,
                              int n)
{
    int i = (blockIdx.x * blockDim.x + threadIdx.x) << 3;
    if (i >= n) return;
    float4 a = *(const float4*)(x + i);
    float4 b = *(const float4*)(x + i + 4);
    float v[8] = {a.x, a.y, a.z, a.w, b.x, b.y, b.z, b.w};
    float hf[8], lf[8];
#pragma unroll
    for (int j = 0; j < 8; j++) {
        __half h = __float2half_rn(v[j]);
        hf[j] = __half2float(h);
        lf[j] = v[j] - hf[j];
    }
    uint4 uh, ul;
    uh.x = pack2h(hf[0], hf[1]); uh.y = pack2h(hf[2], hf[3]);
    uh.z = pack2h(hf[4], hf[5]); uh.w = pack2h(hf[6], hf[7]);
    ul.x = pack2h(lf[0], lf[1]); ul.y = pack2h(lf[2], lf[3]);
    ul.z = pack2h(lf[4], lf[5]); ul.w = pack2h(lf[6], lf[7]);
    *(uint4*)(hi + i) = uh;
    *(uint4*)(lo + i) = ul;
}

__global__ void split1_kernel(const float* __restrict__ x,
                              __half* __restrict__ hi, int n)
{
    int i = (blockIdx.x * blockDim.x + threadIdx.x) << 3;
    if (i >= n) return;
    float4 a = *(const float4*)(x + i);
    float4 b = *(const float4*)(x + i + 4);
    uint4 uh;
    uh.x = pack2h(a.x, a.y); uh.y = pack2h(a.z, a.w);
    uh.z = pack2h(b.x, b.y); uh.w = pack2h(b.z, b.w);
    *(uint4*)(hi + i) = uh;
}

// ---------------------------------------------------------------------------
// Pipelined GEMM core (shared by both kernels, as a macro-style device func)
// Block tile 128x128, BK=32, 2-stage cp.async double buffering.
// smem stage layout: A at +0, Bh at +10240, Bl at +20480; stage stride 30720.
// ---------------------------------------------------------------------------
#define SSTR 40
#define STG_BYTES 30720
#define GSMEM_BYTES (2 * STG_BYTES)

struct GemmAcc { float a[2][8][4]; };

__device__ __forceinline__ void gemm_core(
    char* smem, const __half* Ah, const __half* Bh, const __half* Bl,
    int row0, int col0, int K, int tid, int wm, int wn, GemmAcc& A)
{
#pragma unroll
    for (int mt = 0; mt < 2; mt++)
#pragma unroll
        for (int nt = 0; nt < 8; nt++)
#pragma unroll
            for (int j = 0; j < 4; j++) A.a[mt][nt][j] = 0.0f;

    const int lane = tid & 31;
    const uint32_t sb = smem_u32(smem);
    const int a_r = wm + (lane & 7) + ((lane >> 3) & 1) * 8;
    const int a_c = (lane >> 4) * 8;
    const int b_r = wn + (lane & 7);
    const int b_c = ((lane >> 3) & 1) * 8;

    const int cr = (tid + 0) >> 2;          // chunk row for j=0
    const int cc = (tid & 3) * 8;           // chunk col
    const int cr1 = (tid + 256) >> 2;       // chunk row for j=1

    const int niter = K / 32;

    // prologue: stage 0
    {
        uint32_t s0 = sb;
        cp_async16(s0 + (cr * SSTR + cc) * 2,            Ah + (long)(row0 + cr) * K + cc);
        cp_async16(s0 + (cr1 * SSTR + cc) * 2,           Ah + (long)(row0 + cr1) * K + cc);
        cp_async16(s0 + 10240 + (cr * SSTR + cc) * 2,    Bh + (long)(col0 + cr) * K + cc);
        cp_async16(s0 + 10240 + (cr1 * SSTR + cc) * 2,   Bh + (long)(col0 + cr1) * K + cc);
        cp_async16(s0 + 20480 + (cr * SSTR + cc) * 2,    Bl + (long)(col0 + cr) * K + cc);
        cp_async16(s0 + 20480 + (cr1 * SSTR + cc) * 2,   Bl + (long)(col0 + cr1) * K + cc);
        cp_commit();
    }

    for (int kt = 0; kt < niter; kt++) {
        const uint32_t scur = sb + (kt & 1) * STG_BYTES;
        if (kt + 1 < niter) {
            const uint32_t snx = sb + ((kt + 1) & 1) * STG_BYTES;
            int kof = (kt + 1) * 32;
            cp_async16(snx + (cr * SSTR + cc) * 2,          Ah + (long)(row0 + cr) * K + kof + cc);
            cp_async16(snx + (cr1 * SSTR + cc) * 2,         Ah + (long)(row0 + cr1) * K + kof + cc);
            cp_async16(snx + 10240 + (cr * SSTR + cc) * 2,  Bh + (long)(col0 + cr) * K + kof + cc);
            cp_async16(snx + 10240 + (cr1 * SSTR + cc) * 2, Bh + (long)(col0 + cr1) * K + kof + cc);
            cp_async16(snx + 20480 + (cr * SSTR + cc) * 2,  Bl + (long)(col0 + cr) * K + kof + cc);
            cp_async16(snx + 20480 + (cr1 * SSTR + cc) * 2, Bl + (long)(col0 + cr1) * K + kof + cc);
            cp_commit();
            cp_wait<1>();
        } else {
            cp_wait<0>();
        }
        __syncthreads();

        const uint32_t aA = scur, aBh = scur + 10240, aBl = scur + 20480;
#pragma unroll
        for (int ks = 0; ks < 2; ks++) {
            uint32_t ah[2][4];
#pragma unroll
            for (int mt = 0; mt < 2; mt++) {
                uint32_t off = (uint32_t)((a_r + mt * 16) * SSTR + ks * 16 + a_c) * 2;
                ldsm_x4(ah[mt], aA + off);
            }
#pragma unroll
            for (int nt = 0; nt < 8; nt++) {
                uint32_t boff = (uint32_t)((b_r + nt * 8) * SSTR + ks * 16 + b_c) * 2;
                uint32_t bh[2], bl[2];
                ldsm_x2(bh, aBh + boff);
                ldsm_x2(bl, aBl + boff);
#pragma unroll
                for (int mt = 0; mt < 2; mt++) {
                    mma_f16(A.a[mt][nt], ah[mt], bh);
                    mma_f16(A.a[mt][nt], ah[mt], bl);
                }
            }
        }
        __syncthreads();
    }
}

// ---------------------------------------------------------------------------
// Fused QKV projection kernel. grid = (24, 32).
//  bx 0-15 : Q (N=2048), bias+RoPE+scale, fp16 hi only
//  bx 16-19: K (N=512),  bias+RoPE,       fp16 hi+lo
//  bx 20-23: V (N=512),  bias,            fp16 hi+lo
// ---------------------------------------------------------------------------
__global__ __launch_bounds__(256) void qkv_gemm_kernel(
    const __half* __restrict__ Ah,
    const __half* __restrict__ QWh, const __half* __restrict__ QWl,
    const __half* __restrict__ KWh, const __half* __restrict__ KWl,
    const __half* __restrict__ VWh, const __half* __restrict__ VWl,
    const float* __restrict__ q_b, const float* __restrict__ k_b,
    const float* __restrict__ v_b,
    __half* __restrict__ Qo, __half* __restrict__ Ko, __half* __restrict__ Kol,
    __half* __restrict__ Vo, __half* __restrict__ Vol,
    const float* __restrict__ cosp, const float* __restrict__ sinp)
{
    extern __shared__ __align__(16) char smem[];

    const int bx = blockIdx.x;
    const __half *Bh, *Bl;
    const float* bias;
    __half *Chi, *Clo;
    int N, col0, mode;
    float scale;
    if (bx < 16) {
        Bh = QWh; Bl = QWl; bias = q_b; Chi = Qo; Clo = nullptr;
        N = NH * HD; col0 = bx * 128; mode = 1; scale = SCALE_F;
    } else if (bx < 20) {
        Bh = KWh; Bl = KWl; bias = k_b; Chi = Ko; Clo = Kol;
        N = NKV * HD; col0 = (bx - 16) * 128; mode = 1; scale = 1.0f;
    } else {
        Bh = VWh; Bl = VWl; bias = v_b; Chi = Vo; Clo = Vol;
        N = NKV * HD; col0 = (bx - 20) * 128; mode = 2; scale = 1.0f;
    }

    const int tid  = threadIdx.x;
    const int wid  = tid >> 5;
    const int lane = tid & 31;
    const int wm   = (wid >> 1) * 32;
    const int wn   = (wid & 1) * 64;
    const int row0 = blockIdx.y * 128;

    GemmAcc A;
    gemm_core(smem, Ah, Bh, Bl, row0, col0, HH, tid, wm, wn, A);

    if (mode == 2) {
        const int em = row0 + wm + (lane >> 2);
        const int enl = wn + (lane & 3) * 2;
#pragma unroll
        for (int mt = 0; mt < 2; mt++) {
#pragma unroll
            for (int nt = 0; nt < 8; nt++) {
                int n = col0 + enl + nt * 8;
                float b0 = bias[n], b1 = bias[n + 1];
                float v00 = A.a[mt][nt][0] + b0, v01 = A.a[mt][nt][1] + b1;
                float v10 = A.a[mt][nt][2] + b0, v11 = A.a[mt][nt][3] + b1;
                long o0 = (long)(em + mt * 16) * N + n;
                long o1 = (long)(em + mt * 16 + 8) * N + n;
                __half h00 = __float2half_rn(v00), h01 = __float2half_rn(v01);
                __half h10 = __float2half_rn(v10), h11 = __float2half_rn(v11);
                *(uint32_t*)&Chi[o0] = pack2h(__half2float(h00), __half2float(h01));
                *(uint32_t*)&Chi[o1] = pack2h(__half2float(h10), __half2float(h11));
                *(uint32_t*)&Clo[o0] = pack2h(v00 - __half2float(h00), v01 - __half2float(h01));
                *(uint32_t*)&Clo[o1] = pack2h(v10 - __half2float(h10), v11 - __half2float(h11));
            }
        }
    } else {
        // bias + RoPE (+scale) via 64-row smem staging
        float* buf = (float*)smem;   // 64 x 132 fp32 = 33792 B
        const int r0l = lane >> 2;
        const int c0l = (lane & 3) * 2;
#pragma unroll
        for (int hf = 0; hf < 2; hf++) {
            __syncthreads();
            int slotA = (wid >> 1) * 16 + r0l;
#pragma unroll
            for (int nt = 0; nt < 8; nt++) {
                int cc2 = wn + nt * 8 + c0l;
                float b0 = bias[col0 + cc2];
                float b1 = bias[col0 + cc2 + 1];
                buf[slotA * 132 + cc2]           = A.a[hf][nt][0] + b0;
                buf[slotA * 132 + cc2 + 1]       = A.a[hf][nt][1] + b1;
                buf[(slotA + 8) * 132 + cc2]     = A.a[hf][nt][2] + b0;
                buf[(slotA + 8) * 132 + cc2 + 1] = A.a[hf][nt][3] + b1;
            }
            __syncthreads();
            for (int i = tid; i < 4096; i += 256) {
                int slot = i >> 6, d = i & 63;
                int grow = row0 + (slot >> 4) * 32 + hf * 16 + (slot & 15);
                float x1 = buf[slot * 132 + d];
                float x2 = buf[slot * 132 + d + 64];
                long cb = (long)grow * HD;
                float c1 = cosp[cb + d],      s1 = sinp[cb + d];
                float c2 = cosp[cb + d + 64], s2 = sinp[cb + d + 64];
                float y1 = (x1 * c1 - x2 * s1) * scale;
                float y2 = (x2 * c2 + x1 * s2) * scale;
                long o1 = (long)grow * N + col0 + d;
                long o2 = o1 + 64;
                __half h1 = __float2half_rn(y1);
                __half h2 = __float2half_rn(y2);
                Chi[o1] = h1; Chi[o2] = h2;
                if (Clo) {
                    Clo[o1] = __float2half_rn(y1 - __half2float(h1));
                    Clo[o2] = __float2half_rn(y2 - __half2float(h2));
                }
            }
        }
    }
}

// ---------------------------------------------------------------------------
// Output projection kernel: fp32 out, no bias. grid = (16, 32).
// ---------------------------------------------------------------------------
__global__ __launch_bounds__(256) void o_gemm_kernel(
    const __half* __restrict__ Ah,
    const __half* __restrict__ Bh, const __half* __restrict__ Bl,
    float* __restrict__ Cf, int M, int N, int K)
{
    extern __shared__ __align__(16) char smem[];
    const int tid  = threadIdx.x;
    const int wid  = tid >> 5;
    const int lane = tid & 31;
    const int wm   = (wid >> 1) * 32;
    const int wn   = (wid & 1) * 64;
    const int row0 = blockIdx.y * 128;
    const int col0 = blockIdx.x * 128;

    GemmAcc A;
    gemm_core(smem, Ah, Bh, Bl, row0, col0, K, tid, wm, wn, A);

    const int em = row0 + wm + (lane >> 2);
    const int en = col0 + wn + (lane & 3) * 2;
#pragma unroll
    for (int mt = 0; mt < 2; mt++) {
#pragma unroll
        for (int nt = 0; nt < 8; nt++) {
            int n = en + nt * 8;
            float2 v0, v1;
            v0.x = A.a[mt][nt][0]; v0.y = A.a[mt][nt][1];
            v1.x = A.a[mt][nt][2]; v1.y = A.a[mt][nt][3];
            *(float2*)&Cf[(long)(em + mt * 16) * N + n] = v0;
            *(float2*)&Cf[(long)(em + mt * 16 + 8) * N + n] = v1;
        }
    }
}

// ---------------------------------------------------------------------------
// fp16 tensor-core flash attention (unchanged from round 5)
// ---------------------------------------------------------------------------
#define FQSTR 136
#define FPSTR 72

#define OQH 0u
#define OKH 17408u
#define OKL 34816u
#define OVH 52224u
#define OVL 69632u
#define OPH 87040u
#define OPM 96256u
#define OPS 96768u
#define OMS 97280u
#define OLS 97536u
#define FSM_BYTES 97792u

__global__ __launch_bounds__(256) void flash_mma_kernel(
    const __half* __restrict__ Qh,
    const __half* __restrict__ Kh, const __half* __restrict__ Kl,
    const __half* __restrict__ Vh, const __half* __restrict__ Vl,
    __half* __restrict__ AOh)
{
    extern __shared__ char fsm2[];
    __half* sQh = (__half*)(fsm2 + OQH);
    __half* sKh = (__half*)(fsm2 + OKH);
    __half* sKl = (__half*)(fsm2 + OKL);
    __half* sVh = (__half*)(fsm2 + OVH);
    __half* sVl = (__half*)(fsm2 + OVL);
    __half* sPh = (__half*)(fsm2 + OPH);
    float* pm  = (float*)(fsm2 + OPM);
    float* ps  = (float*)(fsm2 + OPS);
    float* m_s = (float*)(fsm2 + OMS);
    float* l_s = (float*)(fsm2 + OLS);

    const uint32_t aQh = smem_u32(sQh);
    const uint32_t aKh = smem_u32(sKh), aKl = smem_u32(sKl);
    const uint32_t aVh = smem_u32(sVh), aVl = smem_u32(sVl);
    const uint32_t aPh = smem_u32(sPh);

    const int it = blockIdx.x;
    const int h  = blockIdx.y;
    const int b  = blockIdx.z;
    const int g  = h / NREP;
    const int tid  = threadIdx.x;
    const int wid  = tid >> 5;
    const int lane = tid & 31;
    const int wm   = (wid & 3) * 16;
    const int cg   = wid >> 2;
    const int i0 = it * 64;
    const int m0 = b * SS + i0;

    for (int i = tid; i < 1024; i += 256) {
        int r = i >> 4, c = (i & 15) * 8;
        long gi = (long)(m0 + r) * (NH * HD) + h * HD + c;
        *(uint4*)&sQh[r * FQSTR + c] = *(const uint4*)&Qh[gi];
    }
    if (tid < 64) { m_s[tid] = -1e30f; l_s[tid] = 0.0f; }

    float out[8][4];
#pragma unroll
    for (int nt = 0; nt < 8; nt++)
#pragma unroll
        for (int j = 0; j < 4; j++) out[nt][j] = 0.0f;

    const int r0    = lane >> 2;
    const int qcol2 = (lane & 3) * 2;
    const int a_r = (lane & 7) + ((lane >> 3) & 1) * 8;
    const int a_c = (lane >> 4) * 8;
    const int b_r = lane & 7;
    const int b_c = ((lane >> 3) & 1) * 8;
    const int v_k = (lane & 7) + ((lane >> 3) & 1) * 8;
    const int v_n = (lane >> 4) * 8;

    for (int jt = 0; jt <= it; jt++) {
        const int j0 = jt * 64;
        __syncthreads();

        for (int i = tid; i < 1024; i += 256) {
            int r = i >> 4, c = (i & 15) * 8;
            long gi = (long)(b * SS + j0 + r) * (NKV * HD) + g * HD + c;
            int off = r * FQSTR + c;
            *(uint4*)&sKh[off] = *(const uint4*)&Kh[gi];
            *(uint4*)&sKl[off] = *(const uint4*)&Kl[gi];
            *(uint4*)&sVh[off] = *(const uint4*)&Vh[gi];
            *(uint4*)&sVl[off] = *(const uint4*)&Vl[gi];
        }
        __syncthreads();

        float sc[4][4];
#pragma unroll
        for (int nt = 0; nt < 4; nt++)
#pragma unroll
            for (int j = 0; j < 4; j++) sc[nt][j] = 0.0f;

#pragma unroll
        for (int kg = 0; kg < 8; kg++) {
            uint32_t qh[4];
            uint32_t aoff = (uint32_t)((wm + a_r) * FQSTR + kg * 16 + a_c) * 2;
            ldsm_x4(qh, aQh + aoff);
#pragma unroll
            for (int nt = 0; nt < 4; nt++) {
                uint32_t boff =
                    (uint32_t)((cg * 32 + nt * 8 + b_r) * FQSTR + kg * 16 + b_c) * 2;
                uint32_t kh[2], kl[2];
                ldsm_x2(kh, aKh + boff);
                ldsm_x2(kl, aKl + boff);
                mma_f16(sc[nt], qh, kh);
                mma_f16(sc[nt], qh, kl);
            }
        }

        if (jt == it) {
#pragma unroll
            for (int nt = 0; nt < 4; nt++) {
                int colb = j0 + cg * 32 + nt * 8 + qcol2;
                int rowa = i0 + wm + r0;
#pragma unroll
                for (int j = 0; j < 4; j++) {
                    int col = colb + (j & 1);
                    int row = rowa + (j >= 2 ? 8 : 0);
                    if (col > row) sc[nt][j] = -1e30f;
                }
            }
        }

        float mx0 = -1e30f, mx1 = -1e30f;
#pragma unroll
        for (int nt = 0; nt < 4; nt++) {
            mx0 = fmaxf(mx0, fmaxf(sc[nt][0], sc[nt][1]));
            mx1 = fmaxf(mx1, fmaxf(sc[nt][2], sc[nt][3]));
        }
        mx0 = fmaxf(mx0, __shfl_xor_sync(0xffffffffu, mx0, 1));
        mx0 = fmaxf(mx0, __shfl_xor_sync(0xffffffffu, mx0, 2));
        mx1 = fmaxf(mx1, __shfl_xor_sync(0xffffffffu, mx1, 1));
        mx1 = fmaxf(mx1, __shfl_xor_sync(0xffffffffu, mx1, 2));
        if ((lane & 3) == 0) {
            pm[cg * 64 + wm + r0]     = mx0;
            pm[cg * 64 + wm + r0 + 8] = mx1;
        }
        __syncthreads();

        float mold0 = m_s[wm + r0], mold1 = m_s[wm + r0 + 8];
        float mn0 = fmaxf(mold0, fmaxf(pm[wm + r0], pm[64 + wm + r0]));
        float mn1 = fmaxf(mold1, fmaxf(pm[wm + r0 + 8], pm[64 + wm + r0 + 8]));
        float al0 = __expf(mold0 - mn0);
        float al1 = __expf(mold1 - mn1);
        float s0 = 0.0f, s1 = 0.0f;
#pragma unroll
        for (int nt = 0; nt < 4; nt++) {
            sc[nt][0] = __expf(sc[nt][0] - mn0);
            sc[nt][1] = __expf(sc[nt][1] - mn0);
            sc[nt][2] = __expf(sc[nt][2] - mn1);
            sc[nt][3] = __expf(sc[nt][3] - mn1);
            s0 += sc[nt][0] + sc[nt][1];
            s1 += sc[nt][2] + sc[nt][3];
        }
        s0 += __shfl_xor_sync(0xffffffffu, s0, 1);
        s0 += __shfl_xor_sync(0xffffffffu, s0, 2);
        s1 += __shfl_xor_sync(0xffffffffu, s1, 1);
        s1 += __shfl_xor_sync(0xffffffffu, s1, 2);
        if ((lane & 3) == 0) {
            ps[cg * 64 + wm + r0]     = s0;
            ps[cg * 64 + wm + r0 + 8] = s1;
        }

#pragma unroll
        for (int nt = 0; nt < 8; nt++) {
            out[nt][0] *= al0; out[nt][1] *= al0;
            out[nt][2] *= al1; out[nt][3] *= al1;
        }

#pragma unroll
        for (int nt = 0; nt < 4; nt++) {
            int col = cg * 32 + nt * 8 + qcol2;
            *(uint32_t*)&sPh[(wm + r0) * FPSTR + col]     = pack2h(sc[nt][0], sc[nt][1]);
            *(uint32_t*)&sPh[(wm + r0 + 8) * FPSTR + col] = pack2h(sc[nt][2], sc[nt][3]);
        }
        __syncthreads();

        if (cg == 0 && (lane & 3) == 0) {
            int rr = wm + r0;
            l_s[rr] = l_s[rr] * al0 + ps[rr] + ps[64 + rr];
            m_s[rr] = mn0;
            rr += 8;
            l_s[rr] = l_s[rr] * al1 + ps[rr] + ps[64 + rr];
            m_s[rr] = mn1;
        }

#pragma unroll
        for (int kg = 0; kg < 4; kg++) {
            uint32_t ph[4];
            uint32_t aoff = (uint32_t)((wm + a_r) * FPSTR + kg * 16 + a_c) * 2;
            ldsm_x4(ph, aPh + aoff);
#pragma unroll
            for (int ntp = 0; ntp < 4; ntp++) {
                int n0 = cg * 64 + ntp * 16;
                uint32_t voff = (uint32_t)((kg * 16 + v_k) * FQSTR + n0 + v_n) * 2;
                uint32_t vh[4], vl[4];
                ldsm_x4_t(vh, aVh + voff);
                ldsm_x4_t(vl, aVl + voff);
                mma_f16(out[2 * ntp],     ph, &vh[0]);
                mma_f16(out[2 * ntp],     ph, &vl[0]);
                mma_f16(out[2 * ntp + 1], ph, &vh[2]);
                mma_f16(out[2 * ntp + 1], ph, &vl[2]);
            }
        }
    }

    __syncthreads();
    float inv0 = 1.0f / l_s[wm + r0];
    float inv1 = 1.0f / l_s[wm + r0 + 8];
#pragma unroll
    for (int nt = 0; nt < 8; nt++) {
        int col = cg * 64 + nt * 8 + qcol2;
        long ra = (long)(m0 + wm + r0) * (NH * HD) + h * HD + col;
        long rb = (long)(m0 + wm + r0 + 8) * (NH * HD) + h * HD + col;
        *(uint32_t*)&AOh[ra] = pack2h(out[nt][0] * inv0, out[nt][1] * inv0);
        *(uint32_t*)&AOh[rb] = pack2h(out[nt][2] * inv1, out[nt][3] * inv1);
    }
}

// ---------------------------------------------------------------------------
// Launcher
// ---------------------------------------------------------------------------
extern "C" void kernel_launch(void* const* d_in, const int* in_sizes, int n_in,
                              void* d_out, int out_size)
{
    const float* hidden = (const float*)d_in[0];
    const float* cosp   = (const float*)d_in[1];
    const float* sinp   = (const float*)d_in[2];
    const float* q_w = (const float*)d_in[4];
    const float* q_b = (const float*)d_in[5];
    const float* k_w = (const float*)d_in[6];
    const float* k_b = (const float*)d_in[7];
    const float* v_w = (const float*)d_in[8];
    const float* v_b = (const float*)d_in[9];
    const float* o_w = (const float*)d_in[10];
    float* out = (float*)d_out;

    __half *h_h, *qw_h, *qw_l, *kw_h, *kw_l, *vw_h, *vw_l, *ow_h, *ow_l;
    __half *qh, *kh, *kl, *vh, *vl, *ao_h;
    cudaGetSymbolAddress((void**)&h_h, g_h_h);
    cudaGetSymbolAddress((void**)&qw_h, g_qw_h);
    cudaGetSymbolAddress((void**)&qw_l, g_qw_l);
    cudaGetSymbolAddress((void**)&kw_h, g_kw_h);
    cudaGetSymbolAddress((void**)&kw_l, g_kw_l);
    cudaGetSymbolAddress((void**)&vw_h, g_vw_h);
    cudaGetSymbolAddress((void**)&vw_l, g_vw_l);
    cudaGetSymbolAddress((void**)&ow_h, g_ow_h);
    cudaGetSymbolAddress((void**)&ow_l, g_ow_l);
    cudaGetSymbolAddress((void**)&qh, g_qh);
    cudaGetSymbolAddress((void**)&kh, g_kh);
    cudaGetSymbolAddress((void**)&kl, g_kl);
    cudaGetSymbolAddress((void**)&vh, g_vh);
    cudaGetSymbolAddress((void**)&vl, g_vl);
    cudaGetSymbolAddress((void**)&ao_h, g_ao_h);

    // Splits
    {
        int n;
        n = M_TOK * HH;
        split1_kernel<<<n / 8 / 256, 256>>>(hidden, h_h, n);
        n = NH * HD * HH;
        split2_kernel<<<n / 8 / 256, 256>>>(q_w, qw_h, qw_l, n);
        n = NKV * HD * HH;
        split2_kernel<<<n / 8 / 256, 256>>>(k_w, kw_h, kw_l, n);
        split2_kernel<<<n / 8 / 256, 256>>>(v_w, vw_h, vw_l, n);
        n = HH * NH * HD;
        split2_kernel<<<n / 8 / 256, 256>>>(o_w, ow_h, ow_l, n);
    }

    // Fused QKV projection
    cudaFuncSetAttribute(qkv_gemm_kernel,
                         cudaFuncAttributeMaxDynamicSharedMemorySize, GSMEM_BYTES);
    qkv_gemm_kernel<<<dim3(24, M_TOK / 128), 256, GSMEM_BYTES>>>(
        h_h, qw_h, qw_l, kw_h, kw_l, vw_h, vw_l,
        q_b, k_b, v_b, qh, kh, kl, vh, vl, cosp, sinp);

    // Flash attention
    cudaFuncSetAttribute(flash_mma_kernel,
                         cudaFuncAttributeMaxDynamicSharedMemorySize, FSM_BYTES);
    flash_mma_kernel<<<dim3(SS / 64, NH, BB), 256, FSM_BYTES>>>(
        qh, kh, kl, vh, vl, ao_h);

    // Output projection
    cudaFuncSetAttribute(o_gemm_kernel,
                         cudaFuncAttributeMaxDynamicSharedMemorySize, GSMEM_BYTES);
    o_gemm_kernel<<<dim3(HH / 128, M_TOK / 128), 256, GSMEM_BYTES>>>(
        ao_h, ow_h, ow_l, out, M_TOK, HH, NH * HD);
}

// round 7
// speedup vs baseline: 12.1905x; 1.5993x over previous
#include <cuda_runtime.h>
#include <cuda_fp16.h>
#include <math.h>
#include <stdint.h>

// Problem constants
#define BB 2
#define SS 2048
#define HH 2048
#define NH 16
#define NKV 4
#define HD 128
#define NREP (NH / NKV)
#define M_TOK (BB * SS)
#define SCALE_F 0.08838834764831845f

// ---------------------------------------------------------------------------
// Scratch (fp16 hi-only everywhere)
// ---------------------------------------------------------------------------
__device__ __half g_h_h[M_TOK * HH];
__device__ __half g_qw_h[NH * HD * HH];
__device__ __half g_kw_h[NKV * HD * HH];
__device__ __half g_vw_h[NKV * HD * HH];
__device__ __half g_ow_h[HH * NH * HD];
__device__ __half g_qh[M_TOK * NH * HD];
__device__ __half g_kh[M_TOK * NKV * HD];
__device__ __half g_vh[M_TOK * NKV * HD];
__device__ __half g_ao_h[M_TOK * NH * HD];

// ---------------------------------------------------------------------------
// Helpers
// ---------------------------------------------------------------------------
__device__ __forceinline__ uint32_t smem_u32(const void* p) {
    uint32_t a;
    asm("{ .reg .u64 t; cvta.to.shared.u64 t, %1; cvt.u32.u64 %0, t; }"
        : "=r"(a) : "l"(p));
    return a;
}
__device__ __forceinline__ void ldsm_x4(uint32_t* r, uint32_t addr) {
    asm volatile("ldmatrix.sync.aligned.m8n8.x4.shared.b16 {%0,%1,%2,%3}, [%4];"
                 : "=r"(r[0]), "=r"(r[1]), "=r"(r[2]), "=r"(r[3]) : "r"(addr));
}
__device__ __forceinline__ void ldsm_x4_t(uint32_t* r, uint32_t addr) {
    asm volatile("ldmatrix.sync.aligned.m8n8.x4.trans.shared.b16 {%0,%1,%2,%3}, [%4];"
                 : "=r"(r[0]), "=r"(r[1]), "=r"(r[2]), "=r"(r[3]) : "r"(addr));
}
__device__ __forceinline__ void mma_f16(float* c, const uint32_t* a, const uint32_t* b) {
    asm volatile(
        "mma.sync.aligned.m16n8k16.row.col.f32.f16.f16.f32 "
        "{%0,%1,%2,%3}, {%4,%5,%6,%7}, {%8,%9}, {%0,%1,%2,%3};"
        : "+f"(c[0]), "+f"(c[1]), "+f"(c[2]), "+f"(c[3])
        : "r"(a[0]), "r"(a[1]), "r"(a[2]), "r"(a[3]), "r"(b[0]), "r"(b[1]));
}
// B-fragment MMA using two regs picked from an x4 load
__device__ __forceinline__ void mma_f16_b2(float* c, const uint32_t* a,
                                           uint32_t b0, uint32_t b1) {
    uint32_t b[2] = {b0, b1};
    mma_f16(c, a, b);
}
__device__ __forceinline__ void cp_async16(uint32_t dst, const void* src) {
    asm volatile("cp.async.cg.shared.global [%0], [%1], 16;"
                 :: "r"(dst), "l"(src));
}
__device__ __forceinline__ void cp_commit() {
    asm volatile("cp.async.commit_group;" ::: "memory");
}
template <int N> __device__ __forceinline__ void cp_wait() {
    asm volatile("cp.async.wait_group %0;" :: "n"(N) : "memory");
}
__device__ __forceinline__ uint32_t pack2h(float a, float b) {
    __half2 t = __floats2half2_rn(a, b);
    return *(uint32_t*)&t;
}

// ---------------------------------------------------------------------------
// fp32 -> fp16 convert (16 elems/thread, 4 independent float4 loads)
// ---------------------------------------------------------------------------
__global__ void split1_kernel(const float* __restrict__ x,
                              __half* __restrict__ hi, int n)
{
    int i = (blockIdx.x * blockDim.x + threadIdx.x) << 4;
    if (i >= n) return;
    float4 a = *(const float4*)(x + i);
    float4 b = *(const float4*)(x + i + 4);
    float4 c = *(const float4*)(x + i + 8);
    float4 d = *(const float4*)(x + i + 12);
    uint4 u0, u1;
    u0.x = pack2h(a.x, a.y); u0.y = pack2h(a.z, a.w);
    u0.z = pack2h(b.x, b.y); u0.w = pack2h(b.z, b.w);
    u1.x = pack2h(c.x, c.y); u1.y = pack2h(c.z, c.w);
    u1.z = pack2h(d.x, d.y); u1.w = pack2h(d.z, d.w);
    *(uint4*)(hi + i) = u0;
    *(uint4*)(hi + i + 8) = u1;
}

// ---------------------------------------------------------------------------
// Pipelined 1-term fp16 GEMM core. Block tile 128x128, BK=32, 2-stage cp.async.
// Stage layout: A at +0 (10240 B), B at +10240 (10240 B). Stage stride 20480.
// ---------------------------------------------------------------------------
#define SSTR 40
#define STG_BYTES 20480
#define GSMEM_BYTES (2 * STG_BYTES)

struct GemmAcc { float a[2][8][4]; };

__device__ __forceinline__ void gemm_core(
    char* smem, const __half* Ah, const __half* Bh,
    int row0, int col0, int K, int tid, int wm, int wn, GemmAcc& A)
{
#pragma unroll
    for (int mt = 0; mt < 2; mt++)
#pragma unroll
        for (int nt = 0; nt < 8; nt++)
#pragma unroll
            for (int j = 0; j < 4; j++) A.a[mt][nt][j] = 0.0f;

    const int lane = tid & 31;
    const uint32_t sb = smem_u32(smem);
    // x4 ldsm addressing (shared by A and B): rows (lane&7)+((lane>>3)&1)*8, col (lane>>4)*8
    const int x4_r = (lane & 7) + ((lane >> 3) & 1) * 8;
    const int x4_c = (lane >> 4) * 8;

    const int cr  = tid >> 2;
    const int cc  = (tid & 3) * 8;
    const int cr1 = cr + 64;

    const int niter = K / 32;

    {
        uint32_t s0 = sb;
        cp_async16(s0 + (cr * SSTR + cc) * 2,          Ah + (long)(row0 + cr) * K + cc);
        cp_async16(s0 + (cr1 * SSTR + cc) * 2,         Ah + (long)(row0 + cr1) * K + cc);
        cp_async16(s0 + 10240 + (cr * SSTR + cc) * 2,  Bh + (long)(col0 + cr) * K + cc);
        cp_async16(s0 + 10240 + (cr1 * SSTR + cc) * 2, Bh + (long)(col0 + cr1) * K + cc);
        cp_commit();
    }

    for (int kt = 0; kt < niter; kt++) {
        const uint32_t scur = sb + (kt & 1) * STG_BYTES;
        if (kt + 1 < niter) {
            const uint32_t snx = sb + ((kt + 1) & 1) * STG_BYTES;
            int kof = (kt + 1) * 32;
            cp_async16(snx + (cr * SSTR + cc) * 2,          Ah + (long)(row0 + cr) * K + kof + cc);
            cp_async16(snx + (cr1 * SSTR + cc) * 2,         Ah + (long)(row0 + cr1) * K + kof + cc);
            cp_async16(snx + 10240 + (cr * SSTR + cc) * 2,  Bh + (long)(col0 + cr) * K + kof + cc);
            cp_async16(snx + 10240 + (cr1 * SSTR + cc) * 2, Bh + (long)(col0 + cr1) * K + kof + cc);
            cp_commit();
            cp_wait<1>();
        } else {
            cp_wait<0>();
        }
        __syncthreads();

        const uint32_t aA = scur, aB = scur + 10240;
#pragma unroll
        for (int ks = 0; ks < 2; ks++) {
            uint32_t ah[2][4];
#pragma unroll
            for (int mt = 0; mt < 2; mt++) {
                uint32_t off = (uint32_t)((wm + mt * 16 + x4_r) * SSTR + ks * 16 + x4_c) * 2;
                ldsm_x4(ah[mt], aA + off);
            }
#pragma unroll
            for (int nt2 = 0; nt2 < 4; nt2++) {
                uint32_t boff = (uint32_t)((wn + nt2 * 16 + x4_r) * SSTR + ks * 16 + x4_c) * 2;
                uint32_t bb[4];
                ldsm_x4(bb, aB + boff);
#pragma unroll
                for (int mt = 0; mt < 2; mt++) {
                    mma_f16_b2(A.a[mt][2 * nt2],     ah[mt], bb[0], bb[2]);
                    mma_f16_b2(A.a[mt][2 * nt2 + 1], ah[mt], bb[1], bb[3]);
                }
            }
        }
        __syncthreads();
    }
}

// ---------------------------------------------------------------------------
// Fused QKV projection. grid = (24, 32).
//  bx 0-15 : Q, bias+RoPE+scale  bx 16-19: K, bias+RoPE  bx 20-23: V, bias
// ---------------------------------------------------------------------------
__global__ __launch_bounds__(256) void qkv_gemm_kernel(
    const __half* __restrict__ Ah,
    const __half* __restrict__ QWh, const __half* __restrict__ KWh,
    const __half* __restrict__ VWh,
    const float* __restrict__ q_b, const float* __restrict__ k_b,
    const float* __restrict__ v_b,
    __half* __restrict__ Qo, __half* __restrict__ Ko, __half* __restrict__ Vo,
    const float* __restrict__ cosp, const float* __restrict__ sinp)
{
    extern __shared__ __align__(16) char smem[];

    const int bx = blockIdx.x;
    const __half* Bh;
    const float* bias;
    __half* Chi;
    int N, col0, mode;
    float scale;
    if (bx < 16) {
        Bh = QWh; bias = q_b; Chi = Qo;
        N = NH * HD; col0 = bx * 128; mode = 1; scale = SCALE_F;
    } else if (bx < 20) {
        Bh = KWh; bias = k_b; Chi = Ko;
        N = NKV * HD; col0 = (bx - 16) * 128; mode = 1; scale = 1.0f;
    } else {
        Bh = VWh; bias = v_b; Chi = Vo;
        N = NKV * HD; col0 = (bx - 20) * 128; mode = 2; scale = 1.0f;
    }

    const int tid  = threadIdx.x;
    const int wid  = tid >> 5;
    const int lane = tid & 31;
    const int wm   = (wid >> 1) * 32;
    const int wn   = (wid & 1) * 64;
    const int row0 = blockIdx.y * 128;

    GemmAcc A;
    gemm_core(smem, Ah, Bh, row0, col0, HH, tid, wm, wn, A);

    if (mode == 2) {
        const int em = row0 + wm + (lane >> 2);
        const int enl = wn + (lane & 3) * 2;
#pragma unroll
        for (int mt = 0; mt < 2; mt++) {
#pragma unroll
            for (int nt = 0; nt < 8; nt++) {
                int n = col0 + enl + nt * 8;
                float b0 = bias[n], b1 = bias[n + 1];
                long o0 = (long)(em + mt * 16) * N + n;
                long o1 = (long)(em + mt * 16 + 8) * N + n;
                *(uint32_t*)&Chi[o0] = pack2h(A.a[mt][nt][0] + b0, A.a[mt][nt][1] + b1);
                *(uint32_t*)&Chi[o1] = pack2h(A.a[mt][nt][2] + b0, A.a[mt][nt][3] + b1);
            }
        }
    } else {
        // bias + RoPE (+scale) via 64-row smem staging
        float* buf = (float*)smem;   // 64 x 132 fp32 = 33792 B (fits 40960)
        const int r0l = lane >> 2;
        const int c0l = (lane & 3) * 2;
#pragma unroll
        for (int hf = 0; hf < 2; hf++) {
            __syncthreads();
            int slotA = (wid >> 1) * 16 + r0l;
#pragma unroll
            for (int nt = 0; nt < 8; nt++) {
                int cc2 = wn + nt * 8 + c0l;
                float b0 = bias[col0 + cc2];
                float b1 = bias[col0 + cc2 + 1];
                buf[slotA * 132 + cc2]           = A.a[hf][nt][0] + b0;
                buf[slotA * 132 + cc2 + 1]       = A.a[hf][nt][1] + b1;
                buf[(slotA + 8) * 132 + cc2]     = A.a[hf][nt][2] + b0;
                buf[(slotA + 8) * 132 + cc2 + 1] = A.a[hf][nt][3] + b1;
            }
            __syncthreads();
            for (int i = tid; i < 4096; i += 256) {
                int slot = i >> 6, d = i & 63;
                int grow = row0 + (slot >> 4) * 32 + hf * 16 + (slot & 15);
                float x1 = buf[slot * 132 + d];
                float x2 = buf[slot * 132 + d + 64];
                long cb = (long)grow * HD;
                float c1 = cosp[cb + d],      s1 = sinp[cb + d];
                float c2 = cosp[cb + d + 64], s2 = sinp[cb + d + 64];
                float y1 = (x1 * c1 - x2 * s1) * scale;
                float y2 = (x2 * c2 + x1 * s2) * scale;
                long o1 = (long)grow * N + col0 + d;
                Chi[o1]      = __float2half_rn(y1);
                Chi[o1 + 64] = __float2half_rn(y2);
            }
        }
    }
}

// ---------------------------------------------------------------------------
// Output projection: fp32 out, no bias. grid = (16, 32).
// ---------------------------------------------------------------------------
__global__ __launch_bounds__(256) void o_gemm_kernel(
    const __half* __restrict__ Ah, const __half* __restrict__ Bh,
    float* __restrict__ Cf, int M, int N, int K)
{
    extern __shared__ __align__(16) char smem[];
    const int tid  = threadIdx.x;
    const int wid  = tid >> 5;
    const int lane = tid & 31;
    const int wm   = (wid >> 1) * 32;
    const int wn   = (wid & 1) * 64;
    const int row0 = blockIdx.y * 128;
    const int col0 = blockIdx.x * 128;

    GemmAcc A;
    gemm_core(smem, Ah, Bh, row0, col0, K, tid, wm, wn, A);

    const int em = row0 + wm + (lane >> 2);
    const int en = col0 + wn + (lane & 3) * 2;
#pragma unroll
    for (int mt = 0; mt < 2; mt++) {
#pragma unroll
        for (int nt = 0; nt < 8; nt++) {
            int n = en + nt * 8;
            float2 v0, v1;
            v0.x = A.a[mt][nt][0]; v0.y = A.a[mt][nt][1];
            v1.x = A.a[mt][nt][2]; v1.y = A.a[mt][nt][3];
            *(float2*)&Cf[(long)(em + mt * 16) * N + n] = v0;
            *(float2*)&Cf[(long)(em + mt * 16 + 8) * N + n] = v1;
        }
    }
}

// ---------------------------------------------------------------------------
// 1-term fp16 tensor-core flash attention (causal, GQA).
// Block = 256 threads (8 warps), BQ=BKV=64. smem 63 KB.
// ---------------------------------------------------------------------------
#define FQSTR 136
#define FPSTR 72

#define OQH 0u
#define OKH 17408u
#define OVH 34816u
#define OPH 52224u
#define OPM 61440u
#define OPS 61952u
#define OMS 62464u
#define OLS 62720u
#define FSM_BYTES 62976u

__global__ __launch_bounds__(256) void flash_mma_kernel(
    const __half* __restrict__ Qh, const __half* __restrict__ Kh,
    const __half* __restrict__ Vh, __half* __restrict__ AOh)
{
    extern __shared__ char fsm2[];
    __half* sQh = (__half*)(fsm2 + OQH);
    __half* sKh = (__half*)(fsm2 + OKH);
    __half* sVh = (__half*)(fsm2 + OVH);
    __half* sPh = (__half*)(fsm2 + OPH);
    float* pm  = (float*)(fsm2 + OPM);
    float* ps  = (float*)(fsm2 + OPS);
    float* m_s = (float*)(fsm2 + OMS);
    float* l_s = (float*)(fsm2 + OLS);

    const uint32_t aQh = smem_u32(sQh);
    const uint32_t aKh = smem_u32(sKh);
    const uint32_t aVh = smem_u32(sVh);
    const uint32_t aPh = smem_u32(sPh);

    const int it = blockIdx.x;
    const int h  = blockIdx.y;
    const int b  = blockIdx.z;
    const int g  = h / NREP;
    const int tid  = threadIdx.x;
    const int wid  = tid >> 5;
    const int lane = tid & 31;
    const int wm   = (wid & 3) * 16;
    const int cg   = wid >> 2;
    const int i0 = it * 64;
    const int m0 = b * SS + i0;

    for (int i = tid; i < 1024; i += 256) {
        int r = i >> 4, c = (i & 15) * 8;
        long gi = (long)(m0 + r) * (NH * HD) + h * HD + c;
        *(uint4*)&sQh[r * FQSTR + c] = *(const uint4*)&Qh[gi];
    }
    if (tid < 64) { m_s[tid] = -1e30f; l_s[tid] = 0.0f; }

    float out[8][4];
#pragma unroll
    for (int nt = 0; nt < 8; nt++)
#pragma unroll
        for (int j = 0; j < 4; j++) out[nt][j] = 0.0f;

    const int r0    = lane >> 2;
    const int qcol2 = (lane & 3) * 2;
    const int x4_r = (lane & 7) + ((lane >> 3) & 1) * 8;
    const int x4_c = (lane >> 4) * 8;

    for (int jt = 0; jt <= it; jt++) {
        const int j0 = jt * 64;
        __syncthreads();

        for (int i = tid; i < 1024; i += 256) {
            int r = i >> 4, c = (i & 15) * 8;
            long gi = (long)(b * SS + j0 + r) * (NKV * HD) + g * HD + c;
            int off = r * FQSTR + c;
            *(uint4*)&sKh[off] = *(const uint4*)&Kh[gi];
            *(uint4*)&sVh[off] = *(const uint4*)&Vh[gi];
        }
        __syncthreads();

        // ---- QK^T (1-term) ----
        float sc[4][4];
#pragma unroll
        for (int nt = 0; nt < 4; nt++)
#pragma unroll
            for (int j = 0; j < 4; j++) sc[nt][j] = 0.0f;

#pragma unroll
        for (int kg = 0; kg < 8; kg++) {
            uint32_t qh[4];
            uint32_t aoff = (uint32_t)((wm + x4_r) * FQSTR + kg * 16 + x4_c) * 2;
            ldsm_x4(qh, aQh + aoff);
#pragma unroll
            for (int nt2 = 0; nt2 < 2; nt2++) {
                uint32_t boff =
                    (uint32_t)((cg * 32 + nt2 * 16 + x4_r) * FQSTR + kg * 16 + x4_c) * 2;
                uint32_t kb[4];
                ldsm_x4(kb, aKh + boff);
                mma_f16_b2(sc[2 * nt2],     qh, kb[0], kb[2]);
                mma_f16_b2(sc[2 * nt2 + 1], qh, kb[1], kb[3]);
            }
        }

        if (jt == it) {
#pragma unroll
            for (int nt = 0; nt < 4; nt++) {
                int colb = j0 + cg * 32 + nt * 8 + qcol2;
                int rowa = i0 + wm + r0;
#pragma unroll
                for (int j = 0; j < 4; j++) {
                    int col = colb + (j & 1);
                    int row = rowa + (j >= 2 ? 8 : 0);
                    if (col > row) sc[nt][j] = -1e30f;
                }
            }
        }

        float mx0 = -1e30f, mx1 = -1e30f;
#pragma unroll
        for (int nt = 0; nt < 4; nt++) {
            mx0 = fmaxf(mx0, fmaxf(sc[nt][0], sc[nt][1]));
            mx1 = fmaxf(mx1, fmaxf(sc[nt][2], sc[nt][3]));
        }
        mx0 = fmaxf(mx0, __shfl_xor_sync(0xffffffffu, mx0, 1));
        mx0 = fmaxf(mx0, __shfl_xor_sync(0xffffffffu, mx0, 2));
        mx1 = fmaxf(mx1, __shfl_xor_sync(0xffffffffu, mx1, 1));
        mx1 = fmaxf(mx1, __shfl_xor_sync(0xffffffffu, mx1, 2));
        if ((lane & 3) == 0) {
            pm[cg * 64 + wm + r0]     = mx0;
            pm[cg * 64 + wm + r0 + 8] = mx1;
        }
        __syncthreads();

        float mold0 = m_s[wm + r0], mold1 = m_s[wm + r0 + 8];
        float mn0 = fmaxf(mold0, fmaxf(pm[wm + r0], pm[64 + wm + r0]));
        float mn1 = fmaxf(mold1, fmaxf(pm[wm + r0 + 8], pm[64 + wm + r0 + 8]));
        float al0 = __expf(mold0 - mn0);
        float al1 = __expf(mold1 - mn1);
        float s0 = 0.0f, s1 = 0.0f;
#pragma unroll
        for (int nt = 0; nt < 4; nt++) {
            sc[nt][0] = __expf(sc[nt][0] - mn0);
            sc[nt][1] = __expf(sc[nt][1] - mn0);
            sc[nt][2] = __expf(sc[nt][2] - mn1);
            sc[nt][3] = __expf(sc[nt][3] - mn1);
            s0 += sc[nt][0] + sc[nt][1];
            s1 += sc[nt][2] + sc[nt][3];
        }
        s0 += __shfl_xor_sync(0xffffffffu, s0, 1);
        s0 += __shfl_xor_sync(0xffffffffu, s0, 2);
        s1 += __shfl_xor_sync(0xffffffffu, s1, 1);
        s1 += __shfl_xor_sync(0xffffffffu, s1, 2);
        if ((lane & 3) == 0) {
            ps[cg * 64 + wm + r0]     = s0;
            ps[cg * 64 + wm + r0 + 8] = s1;
        }

#pragma unroll
        for (int nt = 0; nt < 8; nt++) {
            out[nt][0] *= al0; out[nt][1] *= al0;
            out[nt][2] *= al1; out[nt][3] *= al1;
        }

#pragma unroll
        for (int nt = 0; nt < 4; nt++) {
            int col = cg * 32 + nt * 8 + qcol2;
            *(uint32_t*)&sPh[(wm + r0) * FPSTR + col]     = pack2h(sc[nt][0], sc[nt][1]);
            *(uint32_t*)&sPh[(wm + r0 + 8) * FPSTR + col] = pack2h(sc[nt][2], sc[nt][3]);
        }
        __syncthreads();

        if (cg == 0 && (lane & 3) == 0) {
            int rr = wm + r0;
            l_s[rr] = l_s[rr] * al0 + ps[rr] + ps[64 + rr];
            m_s[rr] = mn0;
            rr += 8;
            l_s[rr] = l_s[rr] * al1 + ps[rr] + ps[64 + rr];
            m_s[rr] = mn1;
        }

        // ---- P @ V (1-term) ----
#pragma unroll
        for (int kg = 0; kg < 4; kg++) {
            uint32_t ph[4];
            uint32_t aoff = (uint32_t)((wm + x4_r) * FPSTR + kg * 16 + x4_c) * 2;
            ldsm_x4(ph, aPh + aoff);
#pragma unroll
            for (int ntp = 0; ntp < 4; ntp++) {
                int n0 = cg * 64 + ntp * 16;
                uint32_t voff = (uint32_t)((kg * 16 + x4_r) * FQSTR + n0 + x4_c) * 2;
                uint32_t vh[4];
                ldsm_x4_t(vh, aVh + voff);
                mma_f16(out[2 * ntp],     ph, &vh[0]);
                mma_f16(out[2 * ntp + 1], ph, &vh[2]);
            }
        }
    }

    __syncthreads();
    float inv0 = 1.0f / l_s[wm + r0];
    float inv1 = 1.0f / l_s[wm + r0 + 8];
#pragma unroll
    for (int nt = 0; nt < 8; nt++) {
        int col = cg * 64 + nt * 8 + qcol2;
        long ra = (long)(m0 + wm + r0) * (NH * HD) + h * HD + col;
        long rb = (long)(m0 + wm + r0 + 8) * (NH * HD) + h * HD + col;
        *(uint32_t*)&AOh[ra] = pack2h(out[nt][0] * inv0, out[nt][1] * inv0);
        *(uint32_t*)&AOh[rb] = pack2h(out[nt][2] * inv1, out[nt][3] * inv1);
    }
}

// ---------------------------------------------------------------------------
// Launcher
// ---------------------------------------------------------------------------
extern "C" void kernel_launch(void* const* d_in, const int* in_sizes, int n_in,
                              void* d_out, int out_size)
{
    const float* hidden = (const float*)d_in[0];
    const float* cosp   = (const float*)d_in[1];
    const float* sinp   = (const float*)d_in[2];
    const float* q_w = (const float*)d_in[4];
    const float* q_b = (const float*)d_in[5];
    const float* k_w = (const float*)d_in[6];
    const float* k_b = (const float*)d_in[7];
    const float* v_w = (const float*)d_in[8];
    const float* v_b = (const float*)d_in[9];
    const float* o_w = (const float*)d_in[10];
    float* out = (float*)d_out;

    __half *h_h, *qw_h, *kw_h, *vw_h, *ow_h, *qh, *kh, *vh, *ao_h;
    cudaGetSymbolAddress((void**)&h_h, g_h_h);
    cudaGetSymbolAddress((void**)&qw_h, g_qw_h);
    cudaGetSymbolAddress((void**)&kw_h, g_kw_h);
    cudaGetSymbolAddress((void**)&vw_h, g_vw_h);
    cudaGetSymbolAddress((void**)&ow_h, g_ow_h);
    cudaGetSymbolAddress((void**)&qh, g_qh);
    cudaGetSymbolAddress((void**)&kh, g_kh);
    cudaGetSymbolAddress((void**)&vh, g_vh);
    cudaGetSymbolAddress((void**)&ao_h, g_ao_h);

    // Converts
    {
        int n;
        n = M_TOK * HH;
        split1_kernel<<<n / 16 / 256, 256>>>(hidden, h_h, n);
        n = NH * HD * HH;
        split1_kernel<<<n / 16 / 256, 256>>>(q_w, qw_h, n);
        n = NKV * HD * HH;
        split1_kernel<<<n / 16 / 256, 256>>>(k_w, kw_h, n);
        split1_kernel<<<n / 16 / 256, 256>>>(v_w, vw_h, n);
        n = HH * NH * HD;
        split1_kernel<<<n / 16 / 256, 256>>>(o_w, ow_h, n);
    }

    // Fused QKV projection
    cudaFuncSetAttribute(qkv_gemm_kernel,
                         cudaFuncAttributeMaxDynamicSharedMemorySize, GSMEM_BYTES);
    qkv_gemm_kernel<<<dim3(24, M_TOK / 128), 256, GSMEM_BYTES>>>(
        h_h, qw_h, kw_h, vw_h, q_b, k_b, v_b, qh, kh, vh, cosp, sinp);

    // Flash attention
    cudaFuncSetAttribute(flash_mma_kernel,
                         cudaFuncAttributeMaxDynamicSharedMemorySize, FSM_BYTES);
    flash_mma_kernel<<<dim3(SS / 64, NH, BB), 256, FSM_BYTES>>>(
        qh, kh, vh, ao_h);

    // Output projection
    cudaFuncSetAttribute(o_gemm_kernel,
                         cudaFuncAttributeMaxDynamicSharedMemorySize, GSMEM_BYTES);
    o_gemm_kernel<<<dim3(HH / 128, M_TOK / 128), 256, GSMEM_BYTES>>>(
        ao_h, ow_h, out, M_TOK, HH, NH * HD);
}

// round 10
// speedup vs baseline: 13.2478x; 1.0867x over previous
#include <cuda_runtime.h>
#include <cuda_fp16.h>
#include <math.h>
#include <stdint.h>

// Problem constants
#define BB 2
#define SS 2048
#define HH 2048
#define NH 16
#define NKV 4
#define HD 128
#define NREP (NH / NKV)
#define M_TOK (BB * SS)
#define SCALE_F 0.08838834764831845f

// ---------------------------------------------------------------------------
// Scratch (fp16 hi-only)
// ---------------------------------------------------------------------------
__device__ __half g_h_h[M_TOK * HH];
__device__ __half g_qw_h[NH * HD * HH];
__device__ __half g_kw_h[NKV * HD * HH];
__device__ __half g_vw_h[NKV * HD * HH];
__device__ __half g_ow_h[HH * NH * HD];
__device__ __half g_qh[M_TOK * NH * HD];
__device__ __half g_kh[M_TOK * NKV * HD];
__device__ __half g_vh[M_TOK * NKV * HD];
__device__ __half g_ao_h[M_TOK * NH * HD];

// ---------------------------------------------------------------------------
// Helpers
// ---------------------------------------------------------------------------
__device__ __forceinline__ uint32_t smem_u32(const void* p) {
    uint32_t a;
    asm("{ .reg .u64 t; cvta.to.shared.u64 t, %1; cvt.u32.u64 %0, t; }"
        : "=r"(a) : "l"(p));
    return a;
}
__device__ __forceinline__ void ldsm_x4(uint32_t* r, uint32_t addr) {
    asm volatile("ldmatrix.sync.aligned.m8n8.x4.shared.b16 {%0,%1,%2,%3}, [%4];"
                 : "=r"(r[0]), "=r"(r[1]), "=r"(r[2]), "=r"(r[3]) : "r"(addr));
}
__device__ __forceinline__ void ldsm_x4_t(uint32_t* r, uint32_t addr) {
    asm volatile("ldmatrix.sync.aligned.m8n8.x4.trans.shared.b16 {%0,%1,%2,%3}, [%4];"
                 : "=r"(r[0]), "=r"(r[1]), "=r"(r[2]), "=r"(r[3]) : "r"(addr));
}
__device__ __forceinline__ void mma_f16(float* c, const uint32_t* a, const uint32_t* b) {
    asm volatile(
        "mma.sync.aligned.m16n8k16.row.col.f32.f16.f16.f32 "
        "{%0,%1,%2,%3}, {%4,%5,%6,%7}, {%8,%9}, {%0,%1,%2,%3};"
        : "+f"(c[0]), "+f"(c[1]), "+f"(c[2]), "+f"(c[3])
        : "r"(a[0]), "r"(a[1]), "r"(a[2]), "r"(a[3]), "r"(b[0]), "r"(b[1]));
}
__device__ __forceinline__ void mma_f16_b2(float* c, const uint32_t* a,
                                           uint32_t b0, uint32_t b1) {
    uint32_t b[2] = {b0, b1};
    mma_f16(c, a, b);
}
__device__ __forceinline__ void cp_async16(uint32_t dst, const void* src) {
    asm volatile("cp.async.cg.shared.global [%0], [%1], 16;"
                 :: "r"(dst), "l"(src));
}
__device__ __forceinline__ void cp_commit() {
    asm volatile("cp.async.commit_group;" ::: "memory");
}
template <int N> __device__ __forceinline__ void cp_wait() {
    asm volatile("cp.async.wait_group %0;" :: "n"(N) : "memory");
}
__device__ __forceinline__ uint32_t pack2h(float a, float b) {
    __half2 t = __floats2half2_rn(a, b);
    return *(uint32_t*)&t;
}

// ---------------------------------------------------------------------------
// Merged fp32 -> fp16 convert for all 5 tensors. 4096 elems per block.
// Block ranges: hidden 2048, q_w 1024, k_w 256, v_w 256, o_w 1024 = 4608.
// ---------------------------------------------------------------------------
__global__ void convert_all_kernel(
    const float* __restrict__ hidden, __half* __restrict__ h_h,
    const float* __restrict__ q_w, __half* __restrict__ qw_h,
    const float* __restrict__ k_w, __half* __restrict__ kw_h,
    const float* __restrict__ v_w, __half* __restrict__ vw_h,
    const float* __restrict__ o_w, __half* __restrict__ ow_h)
{
    int blk = blockIdx.x;
    const float* x; __half* y; int base;
    if (blk < 2048)      { x = hidden; y = h_h;  base = blk; }
    else if (blk < 3072) { x = q_w;    y = qw_h; base = blk - 2048; }
    else if (blk < 3328) { x = k_w;    y = kw_h; base = blk - 3072; }
    else if (blk < 3584) { x = v_w;    y = vw_h; base = blk - 3328; }
    else                 { x = o_w;    y = ow_h; base = blk - 3584; }
    long i = ((long)base * 256 + threadIdx.x) << 4;
    float4 a = *(const float4*)(x + i);
    float4 b = *(const float4*)(x + i + 4);
    float4 c = *(const float4*)(x + i + 8);
    float4 d = *(const float4*)(x + i + 12);
    uint4 u0, u1;
    u0.x = pack2h(a.x, a.y); u0.y = pack2h(a.z, a.w);
    u0.z = pack2h(b.x, b.y); u0.w = pack2h(b.z, b.w);
    u1.x = pack2h(c.x, c.y); u1.y = pack2h(c.z, c.w);
    u1.z = pack2h(d.x, d.y); u1.w = pack2h(d.z, d.w);
    *(uint4*)(y + i) = u0;
    *(uint4*)(y + i + 8) = u1;
}

// ---------------------------------------------------------------------------
// Pipelined 1-term fp16 GEMM core
// ---------------------------------------------------------------------------
#define SSTR 40
#define STG_BYTES 20480
#define GSMEM_BYTES (2 * STG_BYTES)

struct GemmAcc { float a[2][8][4]; };

__device__ __forceinline__ void gemm_core(
    char* smem, const __half* Ah, const __half* Bh,
    int row0, int col0, int K, int tid, int wm, int wn, GemmAcc& A)
{
#pragma unroll
    for (int mt = 0; mt < 2; mt++)
#pragma unroll
        for (int nt = 0; nt < 8; nt++)
#pragma unroll
            for (int j = 0; j < 4; j++) A.a[mt][nt][j] = 0.0f;

    const int lane = tid & 31;
    const uint32_t sb = smem_u32(smem);
    const int x4_r = (lane & 7) + ((lane >> 3) & 1) * 8;
    const int x4_c = (lane >> 4) * 8;

    const int cr  = tid >> 2;
    const int cc  = (tid & 3) * 8;
    const int cr1 = cr + 64;

    const int niter = K / 32;

    {
        uint32_t s0 = sb;
        cp_async16(s0 + (cr * SSTR + cc) * 2,          Ah + (long)(row0 + cr) * K + cc);
        cp_async16(s0 + (cr1 * SSTR + cc) * 2,         Ah + (long)(row0 + cr1) * K + cc);
        cp_async16(s0 + 10240 + (cr * SSTR + cc) * 2,  Bh + (long)(col0 + cr) * K + cc);
        cp_async16(s0 + 10240 + (cr1 * SSTR + cc) * 2, Bh + (long)(col0 + cr1) * K + cc);
        cp_commit();
    }

    for (int kt = 0; kt < niter; kt++) {
        const uint32_t scur = sb + (kt & 1) * STG_BYTES;
        if (kt + 1 < niter) {
            const uint32_t snx = sb + ((kt + 1) & 1) * STG_BYTES;
            int kof = (kt + 1) * 32;
            cp_async16(snx + (cr * SSTR + cc) * 2,          Ah + (long)(row0 + cr) * K + kof + cc);
            cp_async16(snx + (cr1 * SSTR + cc) * 2,         Ah + (long)(row0 + cr1) * K + kof + cc);
            cp_async16(snx + 10240 + (cr * SSTR + cc) * 2,  Bh + (long)(col0 + cr) * K + kof + cc);
            cp_async16(snx + 10240 + (cr1 * SSTR + cc) * 2, Bh + (long)(col0 + cr1) * K + kof + cc);
            cp_commit();
            cp_wait<1>();
        } else {
            cp_wait<0>();
        }
        __syncthreads();

        const uint32_t aA = scur, aB = scur + 10240;
#pragma unroll
        for (int ks = 0; ks < 2; ks++) {
            uint32_t ah[2][4];
#pragma unroll
            for (int mt = 0; mt < 2; mt++) {
                uint32_t off = (uint32_t)((wm + mt * 16 + x4_r) * SSTR + ks * 16 + x4_c) * 2;
                ldsm_x4(ah[mt], aA + off);
            }
#pragma unroll
            for (int nt2 = 0; nt2 < 4; nt2++) {
                uint32_t boff = (uint32_t)((wn + nt2 * 16 + x4_r) * SSTR + ks * 16 + x4_c) * 2;
                uint32_t bb[4];
                ldsm_x4(bb, aB + boff);
#pragma unroll
                for (int mt = 0; mt < 2; mt++) {
                    mma_f16_b2(A.a[mt][2 * nt2],     ah[mt], bb[0], bb[2]);
                    mma_f16_b2(A.a[mt][2 * nt2 + 1], ah[mt], bb[1], bb[3]);
                }
            }
        }
        __syncthreads();
    }
}

// ---------------------------------------------------------------------------
// Fused QKV projection. grid = (24, 32).
// ---------------------------------------------------------------------------
__global__ __launch_bounds__(256) void qkv_gemm_kernel(
    const __half* __restrict__ Ah,
    const __half* __restrict__ QWh, const __half* __restrict__ KWh,
    const __half* __restrict__ VWh,
    const float* __restrict__ q_b, const float* __restrict__ k_b,
    const float* __restrict__ v_b,
    __half* __restrict__ Qo, __half* __restrict__ Ko, __half* __restrict__ Vo,
    const float* __restrict__ cosp, const float* __restrict__ sinp)
{
    extern __shared__ __align__(16) char smem[];

    const int bx = blockIdx.x;
    const __half* Bh;
    const float* bias;
    __half* Chi;
    int N, col0, mode;
    float scale;
    if (bx < 16) {
        Bh = QWh; bias = q_b; Chi = Qo;
        N = NH * HD; col0 = bx * 128; mode = 1; scale = SCALE_F;
    } else if (bx < 20) {
        Bh = KWh; bias = k_b; Chi = Ko;
        N = NKV * HD; col0 = (bx - 16) * 128; mode = 1; scale = 1.0f;
    } else {
        Bh = VWh; bias = v_b; Chi = Vo;
        N = NKV * HD; col0 = (bx - 20) * 128; mode = 2; scale = 1.0f;
    }

    const int tid  = threadIdx.x;
    const int wid  = tid >> 5;
    const int lane = tid & 31;
    const int wm   = (wid >> 1) * 32;
    const int wn   = (wid & 1) * 64;
    const int row0 = blockIdx.y * 128;

    GemmAcc A;
    gemm_core(smem, Ah, Bh, row0, col0, HH, tid, wm, wn, A);

    if (mode == 2) {
        const int em = row0 + wm + (lane >> 2);
        const int enl = wn + (lane & 3) * 2;
#pragma unroll
        for (int mt = 0; mt < 2; mt++) {
#pragma unroll
            for (int nt = 0; nt < 8; nt++) {
                int n = col0 + enl + nt * 8;
                float b0 = bias[n], b1 = bias[n + 1];
                long o0 = (long)(em + mt * 16) * N + n;
                long o1 = (long)(em + mt * 16 + 8) * N + n;
                *(uint32_t*)&Chi[o0] = pack2h(A.a[mt][nt][0] + b0, A.a[mt][nt][1] + b1);
                *(uint32_t*)&Chi[o1] = pack2h(A.a[mt][nt][2] + b0, A.a[mt][nt][3] + b1);
            }
        }
    } else {
        float* buf = (float*)smem;
        const int r0l = lane >> 2;
        const int c0l = (lane & 3) * 2;
#pragma unroll
        for (int hf = 0; hf < 2; hf++) {
            __syncthreads();
            int slotA = (wid >> 1) * 16 + r0l;
#pragma unroll
            for (int nt = 0; nt < 8; nt++) {
                int cc2 = wn + nt * 8 + c0l;
                float b0 = bias[col0 + cc2];
                float b1 = bias[col0 + cc2 + 1];
                buf[slotA * 132 + cc2]           = A.a[hf][nt][0] + b0;
                buf[slotA * 132 + cc2 + 1]       = A.a[hf][nt][1] + b1;
                buf[(slotA + 8) * 132 + cc2]     = A.a[hf][nt][2] + b0;
                buf[(slotA + 8) * 132 + cc2 + 1] = A.a[hf][nt][3] + b1;
            }
            __syncthreads();
            for (int i = tid; i < 4096; i += 256) {
                int slot = i >> 6, d = i & 63;
                int grow = row0 + (slot >> 4) * 32 + hf * 16 + (slot & 15);
                float x1 = buf[slot * 132 + d];
                float x2 = buf[slot * 132 + d + 64];
                long cb = (long)grow * HD;
                float c1 = cosp[cb + d],      s1 = sinp[cb + d];
                float c2 = cosp[cb + d + 64], s2 = sinp[cb + d + 64];
                float y1 = (x1 * c1 - x2 * s1) * scale;
                float y2 = (x2 * c2 + x1 * s2) * scale;
                long o1 = (long)grow * N + col0 + d;
                Chi[o1]      = __float2half_rn(y1);
                Chi[o1 + 64] = __float2half_rn(y2);
            }
        }
    }
}

// ---------------------------------------------------------------------------
// Output projection: fp32 out, no bias. grid = (16, 32).
// ---------------------------------------------------------------------------
__global__ __launch_bounds__(256) void o_gemm_kernel(
    const __half* __restrict__ Ah, const __half* __restrict__ Bh,
    float* __restrict__ Cf, int M, int N, int K)
{
    extern __shared__ __align__(16) char smem[];
    const int tid  = threadIdx.x;
    const int wid  = tid >> 5;
    const int lane = tid & 31;
    const int wm   = (wid >> 1) * 32;
    const int wn   = (wid & 1) * 64;
    const int row0 = blockIdx.y * 128;
    const int col0 = blockIdx.x * 128;

    GemmAcc A;
    gemm_core(smem, Ah, Bh, row0, col0, K, tid, wm, wn, A);

    const int em = row0 + wm + (lane >> 2);
    const int en = col0 + wn + (lane & 3) * 2;
#pragma unroll
    for (int mt = 0; mt < 2; mt++) {
#pragma unroll
        for (int nt = 0; nt < 8; nt++) {
            int n = en + nt * 8;
            float2 v0, v1;
            v0.x = A.a[mt][nt][0]; v0.y = A.a[mt][nt][1];
            v1.x = A.a[mt][nt][2]; v1.y = A.a[mt][nt][3];
            *(float2*)&Cf[(long)(em + mt * 16) * N + n] = v0;
            *(float2*)&Cf[(long)(em + mt * 16 + 8) * N + n] = v1;
        }
    }
}

// ---------------------------------------------------------------------------
// FA2-style flash attention: BQ=128, warp-owns-16-rows, register-resident P,
// warp-local softmax, cp.async double-buffered K/V. One sync per KV tile.
// smem map (bytes): Q [0,34816) | stage0 K [34816,52224) V [52224,69632)
//                   | stage1 K [69632,87040) V [87040,104448).
// Stage stride = FKVB = 34816 (one K+V pair).  Total = 104448 B.
// ---------------------------------------------------------------------------
#define FQSTR 136
#define FOQ 0u
#define FOK 34816u
#define FKVB 34816u    // K+V pair size per stage (stage stride)
#define FOV 52224u
#define FSM_BYTES 104448u

__global__ __launch_bounds__(256) void flash_mma_kernel(
    const __half* __restrict__ Qh, const __half* __restrict__ Kh,
    const __half* __restrict__ Vh, __half* __restrict__ AOh)
{
    extern __shared__ char fsm2[];
    const uint32_t sb = smem_u32(fsm2);
    const uint32_t aQ = sb + FOQ;

    const int it = (int)gridDim.x - 1 - (int)blockIdx.x;   // heavy tiles first
    const int h  = blockIdx.y;
    const int b  = blockIdx.z;
    const int g  = h / NREP;
    const int tid  = threadIdx.x;
    const int wid  = tid >> 5;
    const int lane = tid & 31;
    const int wq   = wid * 16;          // warp's row block within the 128
    const int i0 = it * 128;
    const int m0 = b * SS + i0;

    // Q tile: 128 rows x 128 cols fp16
    for (int i = tid; i < 2048; i += 256) {
        int r = i >> 4, c = (i & 15) * 8;
        long gi = (long)(m0 + r) * (NH * HD) + h * HD + c;
        *(uint4*)(fsm2 + FOQ + (r * FQSTR + c) * 2) = *(const uint4*)&Qh[gi];
    }

    const int ntiles = 2 * it + 2;

    // prologue: cp.async K/V tile 0 into stage 0
    {
        uint32_t kd = sb + FOK, vd = sb + FOV;
        for (int i = tid; i < 1024; i += 256) {
            int r = i >> 4, c = (i & 15) * 8;
            long gi = (long)(b * SS + r) * (NKV * HD) + g * HD + c;
            cp_async16(kd + (r * FQSTR + c) * 2, Kh + gi);
            cp_async16(vd + (r * FQSTR + c) * 2, Vh + gi);
        }
        cp_commit();
    }

    float out[16][4];
#pragma unroll
    for (int nt = 0; nt < 16; nt++)
#pragma unroll
        for (int j = 0; j < 4; j++) out[nt][j] = 0.0f;
    float m0r = -1e30f, m1r = -1e30f, l0 = 0.0f, l1 = 0.0f;

    const int r0    = lane >> 2;
    const int qcol2 = (lane & 3) * 2;
    const int x4_r = (lane & 7) + ((lane >> 3) & 1) * 8;
    const int x4_c = (lane >> 4) * 8;

    for (int jt = 0; jt < ntiles; jt++) {
        const int j0 = jt * 64;
        const uint32_t aK = sb + FOK + (uint32_t)(jt & 1) * FKVB;
        const uint32_t aV = sb + FOV + (uint32_t)(jt & 1) * FKVB;

        cp_wait<0>();
        __syncthreads();   // stage (jt&1) ready; stage (jt+1)&1 free

        if (jt + 1 < ntiles) {
            uint32_t kd = sb + FOK + (uint32_t)((jt + 1) & 1) * FKVB;
            uint32_t vd = sb + FOV + (uint32_t)((jt + 1) & 1) * FKVB;
            int jn = (jt + 1) * 64;
            for (int i = tid; i < 1024; i += 256) {
                int r = i >> 4, c = (i & 15) * 8;
                long gi = (long)(b * SS + jn + r) * (NKV * HD) + g * HD + c;
                cp_async16(kd + (r * FQSTR + c) * 2, Kh + gi);
                cp_async16(vd + (r * FQSTR + c) * 2, Vh + gi);
            }
            cp_commit();
        }

        // ---- QK^T: warp's 16 rows x 64 cols ----
        float sc[8][4];
#pragma unroll
        for (int nt = 0; nt < 8; nt++)
#pragma unroll
            for (int j = 0; j < 4; j++) sc[nt][j] = 0.0f;

#pragma unroll
        for (int kg = 0; kg < 8; kg++) {
            uint32_t qh[4];
            ldsm_x4(qh, aQ + (uint32_t)((wq + x4_r) * FQSTR + kg * 16 + x4_c) * 2);
#pragma unroll
            for (int nt2 = 0; nt2 < 4; nt2++) {
                uint32_t kb[4];
                ldsm_x4(kb, aK + (uint32_t)((nt2 * 16 + x4_r) * FQSTR + kg * 16 + x4_c) * 2);
                mma_f16_b2(sc[2 * nt2],     qh, kb[0], kb[2]);
                mma_f16_b2(sc[2 * nt2 + 1], qh, kb[1], kb[3]);
            }
        }

        // causal mask (only the last tiles can clip this warp's rows)
        if (j0 + 63 > i0 + wq) {
#pragma unroll
            for (int nt = 0; nt < 8; nt++) {
                int colb = j0 + nt * 8 + qcol2;
                int rowa = i0 + wq + r0;
#pragma unroll
                for (int j = 0; j < 4; j++) {
                    int col = colb + (j & 1);
                    int row = rowa + (j >= 2 ? 8 : 0);
                    if (col > row) sc[nt][j] = -1e30f;
                }
            }
        }

        // ---- warp-local online softmax (rows r0, r0+8 per lane quad) ----
        float mx0 = -1e30f, mx1 = -1e30f;
#pragma unroll
        for (int nt = 0; nt < 8; nt++) {
            mx0 = fmaxf(mx0, fmaxf(sc[nt][0], sc[nt][1]));
            mx1 = fmaxf(mx1, fmaxf(sc[nt][2], sc[nt][3]));
        }
        mx0 = fmaxf(mx0, __shfl_xor_sync(0xffffffffu, mx0, 1));
        mx0 = fmaxf(mx0, __shfl_xor_sync(0xffffffffu, mx0, 2));
        mx1 = fmaxf(mx1, __shfl_xor_sync(0xffffffffu, mx1, 1));
        mx1 = fmaxf(mx1, __shfl_xor_sync(0xffffffffu, mx1, 2));

        float mn0 = fmaxf(m0r, mx0);
        float mn1 = fmaxf(m1r, mx1);
        float al0 = __expf(m0r - mn0);
        float al1 = __expf(m1r - mn1);
        m0r = mn0; m1r = mn1;

        float s0 = 0.0f, s1 = 0.0f;
#pragma unroll
        for (int nt = 0; nt < 8; nt++) {
            sc[nt][0] = __expf(sc[nt][0] - mn0);
            sc[nt][1] = __expf(sc[nt][1] - mn0);
            sc[nt][2] = __expf(sc[nt][2] - mn1);
            sc[nt][3] = __expf(sc[nt][3] - mn1);
            s0 += sc[nt][0] + sc[nt][1];
            s1 += sc[nt][2] + sc[nt][3];
        }
        s0 += __shfl_xor_sync(0xffffffffu, s0, 1);
        s0 += __shfl_xor_sync(0xffffffffu, s0, 2);
        s1 += __shfl_xor_sync(0xffffffffu, s1, 1);
        s1 += __shfl_xor_sync(0xffffffffu, s1, 2);
        l0 = l0 * al0 + s0;
        l1 = l1 * al1 + s1;

#pragma unroll
        for (int nt = 0; nt < 16; nt++) {
            out[nt][0] *= al0; out[nt][1] *= al0;
            out[nt][2] *= al1; out[nt][3] *= al1;
        }

        // ---- P @ V: P fragments straight from score registers ----
#pragma unroll
        for (int kg = 0; kg < 4; kg++) {
            uint32_t pa[4];
            pa[0] = pack2h(sc[2 * kg][0],     sc[2 * kg][1]);
            pa[1] = pack2h(sc[2 * kg][2],     sc[2 * kg][3]);
            pa[2] = pack2h(sc[2 * kg + 1][0], sc[2 * kg + 1][1]);
            pa[3] = pack2h(sc[2 * kg + 1][2], sc[2 * kg + 1][3]);
#pragma unroll
            for (int ntp = 0; ntp < 8; ntp++) {
                uint32_t vh4[4];
                ldsm_x4_t(vh4, aV + (uint32_t)((kg * 16 + x4_r) * FQSTR + ntp * 16 + x4_c) * 2);
                mma_f16(out[2 * ntp],     pa, &vh4[0]);
                mma_f16(out[2 * ntp + 1], pa, &vh4[2]);
            }
        }
    }

    float inv0 = 1.0f / l0;
    float inv1 = 1.0f / l1;
#pragma unroll
    for (int nt = 0; nt < 16; nt++) {
        int col = nt * 8 + qcol2;
        long ra = (long)(m0 + wq + r0) * (NH * HD) + h * HD + col;
        long rb = (long)(m0 + wq + r0 + 8) * (NH * HD) + h * HD + col;
        *(uint32_t*)&AOh[ra] = pack2h(out[nt][0] * inv0, out[nt][1] * inv0);
        *(uint32_t*)&AOh[rb] = pack2h(out[nt][2] * inv1, out[nt][3] * inv1);
    }
}

// ---------------------------------------------------------------------------
// Launcher
// ---------------------------------------------------------------------------
extern "C" void kernel_launch(void* const* d_in, const int* in_sizes, int n_in,
                              void* d_out, int out_size)
{
    const float* hidden = (const float*)d_in[0];
    const float* cosp   = (const float*)d_in[1];
    const float* sinp   = (const float*)d_in[2];
    const float* q_w = (const float*)d_in[4];
    const float* q_b = (const float*)d_in[5];
    const float* k_w = (const float*)d_in[6];
    const float* k_b = (const float*)d_in[7];
    const float* v_w = (const float*)d_in[8];
    const float* v_b = (const float*)d_in[9];
    const float* o_w = (const float*)d_in[10];
    float* out = (float*)d_out;

    __half *h_h, *qw_h, *kw_h, *vw_h, *ow_h, *qh, *kh, *vh, *ao_h;
    cudaGetSymbolAddress((void**)&h_h, g_h_h);
    cudaGetSymbolAddress((void**)&qw_h, g_qw_h);
    cudaGetSymbolAddress((void**)&kw_h, g_kw_h);
    cudaGetSymbolAddress((void**)&vw_h, g_vw_h);
    cudaGetSymbolAddress((void**)&ow_h, g_ow_h);
    cudaGetSymbolAddress((void**)&qh, g_qh);
    cudaGetSymbolAddress((void**)&kh, g_kh);
    cudaGetSymbolAddress((void**)&vh, g_vh);
    cudaGetSymbolAddress((void**)&ao_h, g_ao_h);

    // One merged convert launch
    convert_all_kernel<<<4608, 256>>>(hidden, h_h, q_w, qw_h, k_w, kw_h,
                                      v_w, vw_h, o_w, ow_h);

    // Fused QKV projection
    cudaFuncSetAttribute(qkv_gemm_kernel,
                         cudaFuncAttributeMaxDynamicSharedMemorySize, GSMEM_BYTES);
    qkv_gemm_kernel<<<dim3(24, M_TOK / 128), 256, GSMEM_BYTES>>>(
        h_h, qw_h, kw_h, vw_h, q_b, k_b, v_b, qh, kh, vh, cosp, sinp);

    // Flash attention (FA2-style)
    cudaFuncSetAttribute(flash_mma_kernel,
                         cudaFuncAttributeMaxDynamicSharedMemorySize, FSM_BYTES);
    flash_mma_kernel<<<dim3(SS / 128, NH, BB), 256, FSM_BYTES>>>(
        qh, kh, vh, ao_h);

    // Output projection
    cudaFuncSetAttribute(o_gemm_kernel,
                         cudaFuncAttributeMaxDynamicSharedMemorySize, GSMEM_BYTES);
    o_gemm_kernel<<<dim3(HH / 128, M_TOK / 128), 256, GSMEM_BYTES>>>(
        ao_h, ow_h, out, M_TOK, HH, NH * HD);
}

// round 11
// speedup vs baseline: 14.5255x; 1.0964x over previous
#include <cuda_runtime.h>
#include <cuda_fp16.h>
#include <math.h>
#include <stdint.h>

// Problem constants
#define BB 2
#define SS 2048
#define HH 2048
#define NH 16
#define NKV 4
#define HD 128
#define NREP (NH / NKV)
#define M_TOK (BB * SS)
#define SCALE_F 0.08838834764831845f

// ---------------------------------------------------------------------------
// Scratch (fp16 hi-only)
// ---------------------------------------------------------------------------
__device__ __half g_h_h[M_TOK * HH];
__device__ __half g_qw_h[NH * HD * HH];
__device__ __half g_kw_h[NKV * HD * HH];
__device__ __half g_vw_h[NKV * HD * HH];
__device__ __half g_ow_h[HH * NH * HD];
__device__ __half g_qh[M_TOK * NH * HD];
__device__ __half g_kh[M_TOK * NKV * HD];
__device__ __half g_vh[M_TOK * NKV * HD];
__device__ __half g_ao_h[M_TOK * NH * HD];

// ---------------------------------------------------------------------------
// Helpers
// ---------------------------------------------------------------------------
__device__ __forceinline__ uint32_t smem_u32(const void* p) {
    uint32_t a;
    asm("{ .reg .u64 t; cvta.to.shared.u64 t, %1; cvt.u32.u64 %0, t; }"
        : "=r"(a) : "l"(p));
    return a;
}
__device__ __forceinline__ void ldsm_x4(uint32_t* r, uint32_t addr) {
    asm volatile("ldmatrix.sync.aligned.m8n8.x4.shared.b16 {%0,%1,%2,%3}, [%4];"
                 : "=r"(r[0]), "=r"(r[1]), "=r"(r[2]), "=r"(r[3]) : "r"(addr));
}
__device__ __forceinline__ void ldsm_x4_t(uint32_t* r, uint32_t addr) {
    asm volatile("ldmatrix.sync.aligned.m8n8.x4.trans.shared.b16 {%0,%1,%2,%3}, [%4];"
                 : "=r"(r[0]), "=r"(r[1]), "=r"(r[2]), "=r"(r[3]) : "r"(addr));
}
__device__ __forceinline__ void mma_f16(float* c, const uint32_t* a, const uint32_t* b) {
    asm volatile(
        "mma.sync.aligned.m16n8k16.row.col.f32.f16.f16.f32 "
        "{%0,%1,%2,%3}, {%4,%5,%6,%7}, {%8,%9}, {%0,%1,%2,%3};"
        : "+f"(c[0]), "+f"(c[1]), "+f"(c[2]), "+f"(c[3])
        : "r"(a[0]), "r"(a[1]), "r"(a[2]), "r"(a[3]), "r"(b[0]), "r"(b[1]));
}
__device__ __forceinline__ void mma_f16_b2(float* c, const uint32_t* a,
                                           uint32_t b0, uint32_t b1) {
    uint32_t b[2] = {b0, b1};
    mma_f16(c, a, b);
}
__device__ __forceinline__ void cp_async16(uint32_t dst, const void* src) {
    asm volatile("cp.async.cg.shared.global [%0], [%1], 16;"
                 :: "r"(dst), "l"(src));
}
__device__ __forceinline__ void cp_commit() {
    asm volatile("cp.async.commit_group;" ::: "memory");
}
template <int N> __device__ __forceinline__ void cp_wait() {
    asm volatile("cp.async.wait_group %0;" :: "n"(N) : "memory");
}
__device__ __forceinline__ uint32_t pack2h(float a, float b) {
    __half2 t = __floats2half2_rn(a, b);
    return *(uint32_t*)&t;
}

// ---------------------------------------------------------------------------
// Merged fp32 -> fp16 convert for all 5 tensors.
// ---------------------------------------------------------------------------
__global__ void convert_all_kernel(
    const float* __restrict__ hidden, __half* __restrict__ h_h,
    const float* __restrict__ q_w, __half* __restrict__ qw_h,
    const float* __restrict__ k_w, __half* __restrict__ kw_h,
    const float* __restrict__ v_w, __half* __restrict__ vw_h,
    const float* __restrict__ o_w, __half* __restrict__ ow_h)
{
    int blk = blockIdx.x;
    const float* x; __half* y; int base;
    if (blk < 2048)      { x = hidden; y = h_h;  base = blk; }
    else if (blk < 3072) { x = q_w;    y = qw_h; base = blk - 2048; }
    else if (blk < 3328) { x = k_w;    y = kw_h; base = blk - 3072; }
    else if (blk < 3584) { x = v_w;    y = vw_h; base = blk - 3328; }
    else                 { x = o_w;    y = ow_h; base = blk - 3584; }
    long i = ((long)base * 256 + threadIdx.x) << 4;
    float4 a = *(const float4*)(x + i);
    float4 b = *(const float4*)(x + i + 4);
    float4 c = *(const float4*)(x + i + 8);
    float4 d = *(const float4*)(x + i + 12);
    uint4 u0, u1;
    u0.x = pack2h(a.x, a.y); u0.y = pack2h(a.z, a.w);
    u0.z = pack2h(b.x, b.y); u0.w = pack2h(b.z, b.w);
    u1.x = pack2h(c.x, c.y); u1.y = pack2h(c.z, c.w);
    u1.z = pack2h(d.x, d.y); u1.w = pack2h(d.z, d.w);
    *(uint4*)(y + i) = u0;
    *(uint4*)(y + i + 8) = u1;
}

// ---------------------------------------------------------------------------
// Pipelined 1-term fp16 GEMM core. Block tile 128x128, BK=64, 2-stage
// cp.async, ONE __syncthreads per K-tile (flash-style ordering).
// Stage layout: A [0,18432), B [18432,36864). Stage stride 36864.
// ---------------------------------------------------------------------------
#define SSTR 72                       // smem row stride (halves) for 64-wide tile
#define MAT_BYTES 18432               // 128 * 72 * 2
#define STG_BYTES 36864               // A + B per stage
#define GSMEM_BYTES (2 * STG_BYTES)   // 73728

struct GemmAcc { float a[2][8][4]; };

__device__ __forceinline__ void gemm_stage_load(
    uint32_t sdst, const __half* Ah, const __half* Bh,
    int row0, int col0, int K, int kof, int tid)
{
    // 1024 chunks (16B) per matrix; 4 per thread. row = i>>3, col = (i&7)*8 halves
#pragma unroll
    for (int j = 0; j < 4; j++) {
        int i = tid + j * 256;
        int r = i >> 3, c = (i & 7) * 8;
        uint32_t so = (uint32_t)(r * SSTR + c) * 2;
        cp_async16(sdst + so,             Ah + (long)(row0 + r) * K + kof + c);
        cp_async16(sdst + MAT_BYTES + so, Bh + (long)(col0 + r) * K + kof + c);
    }
    cp_commit();
}

__device__ __forceinline__ void gemm_core(
    char* smem, const __half* Ah, const __half* Bh,
    int row0, int col0, int K, int tid, int wm, int wn, GemmAcc& A)
{
#pragma unroll
    for (int mt = 0; mt < 2; mt++)
#pragma unroll
        for (int nt = 0; nt < 8; nt++)
#pragma unroll
            for (int j = 0; j < 4; j++) A.a[mt][nt][j] = 0.0f;

    const int lane = tid & 31;
    const uint32_t sb = smem_u32(smem);
    const int x4_r = (lane & 7) + ((lane >> 3) & 1) * 8;
    const int x4_c = (lane >> 4) * 8;

    const int niter = K / 64;

    gemm_stage_load(sb, Ah, Bh, row0, col0, K, 0, tid);

    for (int kt = 0; kt < niter; kt++) {
        cp_wait<0>();
        __syncthreads();   // stage kt ready; all reads of the other stage done

        if (kt + 1 < niter) {
            gemm_stage_load(sb + (uint32_t)((kt + 1) & 1) * STG_BYTES,
                            Ah, Bh, row0, col0, K, (kt + 1) * 64, tid);
        }

        const uint32_t aA = sb + (uint32_t)(kt & 1) * STG_BYTES;
        const uint32_t aB = aA + MAT_BYTES;
#pragma unroll
        for (int ks = 0; ks < 4; ks++) {
            uint32_t ah[2][4];
#pragma unroll
            for (int mt = 0; mt < 2; mt++) {
                uint32_t off = (uint32_t)((wm + mt * 16 + x4_r) * SSTR + ks * 16 + x4_c) * 2;
                ldsm_x4(ah[mt], aA + off);
            }
#pragma unroll
            for (int nt2 = 0; nt2 < 4; nt2++) {
                uint32_t boff = (uint32_t)((wn + nt2 * 16 + x4_r) * SSTR + ks * 16 + x4_c) * 2;
                uint32_t bb[4];
                ldsm_x4(bb, aB + boff);
#pragma unroll
                for (int mt = 0; mt < 2; mt++) {
                    mma_f16_b2(A.a[mt][2 * nt2],     ah[mt], bb[0], bb[2]);
                    mma_f16_b2(A.a[mt][2 * nt2 + 1], ah[mt], bb[1], bb[3]);
                }
            }
        }
    }
    // NOTE: no trailing sync — epilogues that reuse smem must sync first.
}

// ---------------------------------------------------------------------------
// Fused QKV projection. grid = (24, 32).
// ---------------------------------------------------------------------------
__global__ __launch_bounds__(256) void qkv_gemm_kernel(
    const __half* __restrict__ Ah,
    const __half* __restrict__ QWh, const __half* __restrict__ KWh,
    const __half* __restrict__ VWh,
    const float* __restrict__ q_b, const float* __restrict__ k_b,
    const float* __restrict__ v_b,
    __half* __restrict__ Qo, __half* __restrict__ Ko, __half* __restrict__ Vo,
    const float* __restrict__ cosp, const float* __restrict__ sinp)
{
    extern __shared__ __align__(16) char smem[];

    const int bx = blockIdx.x;
    const __half* Bh;
    const float* bias;
    __half* Chi;
    int N, col0, mode;
    float scale;
    if (bx < 16) {
        Bh = QWh; bias = q_b; Chi = Qo;
        N = NH * HD; col0 = bx * 128; mode = 1; scale = SCALE_F;
    } else if (bx < 20) {
        Bh = KWh; bias = k_b; Chi = Ko;
        N = NKV * HD; col0 = (bx - 16) * 128; mode = 1; scale = 1.0f;
    } else {
        Bh = VWh; bias = v_b; Chi = Vo;
        N = NKV * HD; col0 = (bx - 20) * 128; mode = 2; scale = 1.0f;
    }

    const int tid  = threadIdx.x;
    const int wid  = tid >> 5;
    const int lane = tid & 31;
    const int wm   = (wid >> 1) * 32;
    const int wn   = (wid & 1) * 64;
    const int row0 = blockIdx.y * 128;

    GemmAcc A;
    gemm_core(smem, Ah, Bh, row0, col0, HH, tid, wm, wn, A);

    if (mode == 2) {
        const int em = row0 + wm + (lane >> 2);
        const int enl = wn + (lane & 3) * 2;
#pragma unroll
        for (int mt = 0; mt < 2; mt++) {
#pragma unroll
            for (int nt = 0; nt < 8; nt++) {
                int n = col0 + enl + nt * 8;
                float b0 = bias[n], b1 = bias[n + 1];
                long o0 = (long)(em + mt * 16) * N + n;
                long o1 = (long)(em + mt * 16 + 8) * N + n;
                *(uint32_t*)&Chi[o0] = pack2h(A.a[mt][nt][0] + b0, A.a[mt][nt][1] + b1);
                *(uint32_t*)&Chi[o1] = pack2h(A.a[mt][nt][2] + b0, A.a[mt][nt][3] + b1);
            }
        }
    } else {
        float* buf = (float*)smem;   // 64 x 132 fp32 = 33792 B (< 73728)
        const int r0l = lane >> 2;
        const int c0l = (lane & 3) * 2;
#pragma unroll
        for (int hf = 0; hf < 2; hf++) {
            __syncthreads();   // also covers mainloop exit before smem reuse
            int slotA = (wid >> 1) * 16 + r0l;
#pragma unroll
            for (int nt = 0; nt < 8; nt++) {
                int cc2 = wn + nt * 8 + c0l;
                float b0 = bias[col0 + cc2];
                float b1 = bias[col0 + cc2 + 1];
                buf[slotA * 132 + cc2]           = A.a[hf][nt][0] + b0;
                buf[slotA * 132 + cc2 + 1]       = A.a[hf][nt][1] + b1;
                buf[(slotA + 8) * 132 + cc2]     = A.a[hf][nt][2] + b0;
                buf[(slotA + 8) * 132 + cc2 + 1] = A.a[hf][nt][3] + b1;
            }
            __syncthreads();
            for (int i = tid; i < 4096; i += 256) {
                int slot = i >> 6, d = i & 63;
                int grow = row0 + (slot >> 4) * 32 + hf * 16 + (slot & 15);
                float x1 = buf[slot * 132 + d];
                float x2 = buf[slot * 132 + d + 64];
                long cb = (long)grow * HD;
                float c1 = cosp[cb + d],      s1 = sinp[cb + d];
                float c2 = cosp[cb + d + 64], s2 = sinp[cb + d + 64];
                float y1 = (x1 * c1 - x2 * s1) * scale;
                float y2 = (x2 * c2 + x1 * s2) * scale;
                long o1 = (long)grow * N + col0 + d;
                Chi[o1]      = __float2half_rn(y1);
                Chi[o1 + 64] = __float2half_rn(y2);
            }
        }
    }
}

// ---------------------------------------------------------------------------
// Output projection: fp32 out, no bias. grid = (16, 32).
// ---------------------------------------------------------------------------
__global__ __launch_bounds__(256) void o_gemm_kernel(
    const __half* __restrict__ Ah, const __half* __restrict__ Bh,
    float* __restrict__ Cf, int M, int N, int K)
{
    extern __shared__ __align__(16) char smem[];
    const int tid  = threadIdx.x;
    const int wid  = tid >> 5;
    const int lane = tid & 31;
    const int wm   = (wid >> 1) * 32;
    const int wn   = (wid & 1) * 64;
    const int row0 = blockIdx.y * 128;
    const int col0 = blockIdx.x * 128;

    GemmAcc A;
    gemm_core(smem, Ah, Bh, row0, col0, K, tid, wm, wn, A);

    const int em = row0 + wm + (lane >> 2);
    const int en = col0 + wn + (lane & 3) * 2;
#pragma unroll
    for (int mt = 0; mt < 2; mt++) {
#pragma unroll
        for (int nt = 0; nt < 8; nt++) {
            int n = en + nt * 8;
            float2 v0, v1;
            v0.x = A.a[mt][nt][0]; v0.y = A.a[mt][nt][1];
            v1.x = A.a[mt][nt][2]; v1.y = A.a[mt][nt][3];
            *(float2*)&Cf[(long)(em + mt * 16) * N + n] = v0;
            *(float2*)&Cf[(long)(em + mt * 16 + 8) * N + n] = v1;
        }
    }
}

// ---------------------------------------------------------------------------
// FA2-style flash attention (unchanged from R10 — WIN config).
// smem map: Q [0,34816) | st0 K [34816,52224) V [52224,69632)
//           | st1 K [69632,87040) V [87040,104448). Stage stride 34816.
// ---------------------------------------------------------------------------
#define FQSTR 136
#define FOQ 0u
#define FOK 34816u
#define FKVB 34816u
#define FOV 52224u
#define FSM_BYTES 104448u

__global__ __launch_bounds__(256) void flash_mma_kernel(
    const __half* __restrict__ Qh, const __half* __restrict__ Kh,
    const __half* __restrict__ Vh, __half* __restrict__ AOh)
{
    extern __shared__ char fsm2[];
    const uint32_t sb = smem_u32(fsm2);
    const uint32_t aQ = sb + FOQ;

    const int it = (int)gridDim.x - 1 - (int)blockIdx.x;
    const int h  = blockIdx.y;
    const int b  = blockIdx.z;
    const int g  = h / NREP;
    const int tid  = threadIdx.x;
    const int wid  = tid >> 5;
    const int lane = tid & 31;
    const int wq   = wid * 16;
    const int i0 = it * 128;
    const int m0 = b * SS + i0;

    for (int i = tid; i < 2048; i += 256) {
        int r = i >> 4, c = (i & 15) * 8;
        long gi = (long)(m0 + r) * (NH * HD) + h * HD + c;
        *(uint4*)(fsm2 + FOQ + (r * FQSTR + c) * 2) = *(const uint4*)&Qh[gi];
    }

    const int ntiles = 2 * it + 2;

    {
        uint32_t kd = sb + FOK, vd = sb + FOV;
        for (int i = tid; i < 1024; i += 256) {
            int r = i >> 4, c = (i & 15) * 8;
            long gi = (long)(b * SS + r) * (NKV * HD) + g * HD + c;
            cp_async16(kd + (r * FQSTR + c) * 2, Kh + gi);
            cp_async16(vd + (r * FQSTR + c) * 2, Vh + gi);
        }
        cp_commit();
    }

    float out[16][4];
#pragma unroll
    for (int nt = 0; nt < 16; nt++)
#pragma unroll
        for (int j = 0; j < 4; j++) out[nt][j] = 0.0f;
    float m0r = -1e30f, m1r = -1e30f, l0 = 0.0f, l1 = 0.0f;

    const int r0    = lane >> 2;
    const int qcol2 = (lane & 3) * 2;
    const int x4_r = (lane & 7) + ((lane >> 3) & 1) * 8;
    const int x4_c = (lane >> 4) * 8;

    for (int jt = 0; jt < ntiles; jt++) {
        const int j0 = jt * 64;
        const uint32_t aK = sb + FOK + (uint32_t)(jt & 1) * FKVB;
        const uint32_t aV = sb + FOV + (uint32_t)(jt & 1) * FKVB;

        cp_wait<0>();
        __syncthreads();

        if (jt + 1 < ntiles) {
            uint32_t kd = sb + FOK + (uint32_t)((jt + 1) & 1) * FKVB;
            uint32_t vd = sb + FOV + (uint32_t)((jt + 1) & 1) * FKVB;
            int jn = (jt + 1) * 64;
            for (int i = tid; i < 1024; i += 256) {
                int r = i >> 4, c = (i & 15) * 8;
                long gi = (long)(b * SS + jn + r) * (NKV * HD) + g * HD + c;
                cp_async16(kd + (r * FQSTR + c) * 2, Kh + gi);
                cp_async16(vd + (r * FQSTR + c) * 2, Vh + gi);
            }
            cp_commit();
        }

        float sc[8][4];
#pragma unroll
        for (int nt = 0; nt < 8; nt++)
#pragma unroll
            for (int j = 0; j < 4; j++) sc[nt][j] = 0.0f;

#pragma unroll
        for (int kg = 0; kg < 8; kg++) {
            uint32_t qh[4];
            ldsm_x4(qh, aQ + (uint32_t)((wq + x4_r) * FQSTR + kg * 16 + x4_c) * 2);
#pragma unroll
            for (int nt2 = 0; nt2 < 4; nt2++) {
                uint32_t kb[4];
                ldsm_x4(kb, aK + (uint32_t)((nt2 * 16 + x4_r) * FQSTR + kg * 16 + x4_c) * 2);
                mma_f16_b2(sc[2 * nt2],     qh, kb[0], kb[2]);
                mma_f16_b2(sc[2 * nt2 + 1], qh, kb[1], kb[3]);
            }
        }

        if (j0 + 63 > i0 + wq) {
#pragma unroll
            for (int nt = 0; nt < 8; nt++) {
                int colb = j0 + nt * 8 + qcol2;
                int rowa = i0 + wq + r0;
#pragma unroll
                for (int j = 0; j < 4; j++) {
                    int col = colb + (j & 1);
                    int row = rowa + (j >= 2 ? 8 : 0);
                    if (col > row) sc[nt][j] = -1e30f;
                }
            }
        }

        float mx0 = -1e30f, mx1 = -1e30f;
#pragma unroll
        for (int nt = 0; nt < 8; nt++) {
            mx0 = fmaxf(mx0, fmaxf(sc[nt][0], sc[nt][1]));
            mx1 = fmaxf(mx1, fmaxf(sc[nt][2], sc[nt][3]));
        }
        mx0 = fmaxf(mx0, __shfl_xor_sync(0xffffffffu, mx0, 1));
        mx0 = fmaxf(mx0, __shfl_xor_sync(0xffffffffu, mx0, 2));
        mx1 = fmaxf(mx1, __shfl_xor_sync(0xffffffffu, mx1, 1));
        mx1 = fmaxf(mx1, __shfl_xor_sync(0xffffffffu, mx1, 2));

        float mn0 = fmaxf(m0r, mx0);
        float mn1 = fmaxf(m1r, mx1);
        float al0 = __expf(m0r - mn0);
        float al1 = __expf(m1r - mn1);
        m0r = mn0; m1r = mn1;

        float s0 = 0.0f, s1 = 0.0f;
#pragma unroll
        for (int nt = 0; nt < 8; nt++) {
            sc[nt][0] = __expf(sc[nt][0] - mn0);
            sc[nt][1] = __expf(sc[nt][1] - mn0);
            sc[nt][2] = __expf(sc[nt][2] - mn1);
            sc[nt][3] = __expf(sc[nt][3] - mn1);
            s0 += sc[nt][0] + sc[nt][1];
            s1 += sc[nt][2] + sc[nt][3];
        }
        s0 += __shfl_xor_sync(0xffffffffu, s0, 1);
        s0 += __shfl_xor_sync(0xffffffffu, s0, 2);
        s1 += __shfl_xor_sync(0xffffffffu, s1, 1);
        s1 += __shfl_xor_sync(0xffffffffu, s1, 2);
        l0 = l0 * al0 + s0;
        l1 = l1 * al1 + s1;

#pragma unroll
        for (int nt = 0; nt < 16; nt++) {
            out[nt][0] *= al0; out[nt][1] *= al0;
            out[nt][2] *= al1; out[nt][3] *= al1;
        }

#pragma unroll
        for (int kg = 0; kg < 4; kg++) {
            uint32_t pa[4];
            pa[0] = pack2h(sc[2 * kg][0],     sc[2 * kg][1]);
            pa[1] = pack2h(sc[2 * kg][2],     sc[2 * kg][3]);
            pa[2] = pack2h(sc[2 * kg + 1][0], sc[2 * kg + 1][1]);
            pa[3] = pack2h(sc[2 * kg + 1][2], sc[2 * kg + 1][3]);
#pragma unroll
            for (int ntp = 0; ntp < 8; ntp++) {
                uint32_t vh4[4];
                ldsm_x4_t(vh4, aV + (uint32_t)((kg * 16 + x4_r) * FQSTR + ntp * 16 + x4_c) * 2);
                mma_f16(out[2 * ntp],     pa, &vh4[0]);
                mma_f16(out[2 * ntp + 1], pa, &vh4[2]);
            }
        }
    }

    float inv0 = 1.0f / l0;
    float inv1 = 1.0f / l1;
#pragma unroll
    for (int nt = 0; nt < 16; nt++) {
        int col = nt * 8 + qcol2;
        long ra = (long)(m0 + wq + r0) * (NH * HD) + h * HD + col;
        long rb = (long)(m0 + wq + r0 + 8) * (NH * HD) + h * HD + col;
        *(uint32_t*)&AOh[ra] = pack2h(out[nt][0] * inv0, out[nt][1] * inv0);
        *(uint32_t*)&AOh[rb] = pack2h(out[nt][2] * inv1, out[nt][3] * inv1);
    }
}

// ---------------------------------------------------------------------------
// Launcher
// ---------------------------------------------------------------------------
extern "C" void kernel_launch(void* const* d_in, const int* in_sizes, int n_in,
                              void* d_out, int out_size)
{
    const float* hidden = (const float*)d_in[0];
    const float* cosp   = (const float*)d_in[1];
    const float* sinp   = (const float*)d_in[2];
    const float* q_w = (const float*)d_in[4];
    const float* q_b = (const float*)d_in[5];
    const float* k_w = (const float*)d_in[6];
    const float* k_b = (const float*)d_in[7];
    const float* v_w = (const float*)d_in[8];
    const float* v_b = (const float*)d_in[9];
    const float* o_w = (const float*)d_in[10];
    float* out = (float*)d_out;

    __half *h_h, *qw_h, *kw_h, *vw_h, *ow_h, *qh, *kh, *vh, *ao_h;
    cudaGetSymbolAddress((void**)&h_h, g_h_h);
    cudaGetSymbolAddress((void**)&qw_h, g_qw_h);
    cudaGetSymbolAddress((void**)&kw_h, g_kw_h);
    cudaGetSymbolAddress((void**)&vw_h, g_vw_h);
    cudaGetSymbolAddress((void**)&ow_h, g_ow_h);
    cudaGetSymbolAddress((void**)&qh, g_qh);
    cudaGetSymbolAddress((void**)&kh, g_kh);
    cudaGetSymbolAddress((void**)&vh, g_vh);
    cudaGetSymbolAddress((void**)&ao_h, g_ao_h);

    // One merged convert launch
    convert_all_kernel<<<4608, 256>>>(hidden, h_h, q_w, qw_h, k_w, kw_h,
                                      v_w, vw_h, o_w, ow_h);

    // Fused QKV projection
    cudaFuncSetAttribute(qkv_gemm_kernel,
                         cudaFuncAttributeMaxDynamicSharedMemorySize, GSMEM_BYTES);
    qkv_gemm_kernel<<<dim3(24, M_TOK / 128), 256, GSMEM_BYTES>>>(
        h_h, qw_h, kw_h, vw_h, q_b, k_b, v_b, qh, kh, vh, cosp, sinp);

    // Flash attention
    cudaFuncSetAttribute(flash_mma_kernel,
                         cudaFuncAttributeMaxDynamicSharedMemorySize, FSM_BYTES);
    flash_mma_kernel<<<dim3(SS / 128, NH, BB), 256, FSM_BYTES>>>(
        qh, kh, vh, ao_h);

    // Output projection
    cudaFuncSetAttribute(o_gemm_kernel,
                         cudaFuncAttributeMaxDynamicSharedMemorySize, GSMEM_BYTES);
    o_gemm_kernel<<<dim3(HH / 128, M_TOK / 128), 256, GSMEM_BYTES>>>(
        ao_h, ow_h, out, M_TOK, HH, NH * HD);
}

// round 12
// speedup vs baseline: 14.6355x; 1.0076x over previous
#include <cuda_runtime.h>
#include <cuda_fp16.h>
#include <math.h>
#include <stdint.h>

// Problem constants
#define BB 2
#define SS 2048
#define HH 2048
#define NH 16
#define NKV 4
#define HD 128
#define NREP (NH / NKV)
#define M_TOK (BB * SS)
#define SCALE_F 0.08838834764831845f

// ---------------------------------------------------------------------------
// Scratch (fp16 hi-only)
// ---------------------------------------------------------------------------
__device__ __half g_h_h[M_TOK * HH];
__device__ __half g_qw_h[NH * HD * HH];
__device__ __half g_kw_h[NKV * HD * HH];
__device__ __half g_vw_h[NKV * HD * HH];
__device__ __half g_ow_h[HH * NH * HD];
__device__ __half g_qh[M_TOK * NH * HD];
__device__ __half g_kh[M_TOK * NKV * HD];
__device__ __half g_vh[M_TOK * NKV * HD];
__device__ __half g_ao_h[M_TOK * NH * HD];

// ---------------------------------------------------------------------------
// Helpers
// ---------------------------------------------------------------------------
__device__ __forceinline__ uint32_t smem_u32(const void* p) {
    uint32_t a;
    asm("{ .reg .u64 t; cvta.to.shared.u64 t, %1; cvt.u32.u64 %0, t; }"
        : "=r"(a) : "l"(p));
    return a;
}
__device__ __forceinline__ void ldsm_x4(uint32_t* r, uint32_t addr) {
    asm volatile("ldmatrix.sync.aligned.m8n8.x4.shared.b16 {%0,%1,%2,%3}, [%4];"
                 : "=r"(r[0]), "=r"(r[1]), "=r"(r[2]), "=r"(r[3]) : "r"(addr));
}
__device__ __forceinline__ void ldsm_x4_t(uint32_t* r, uint32_t addr) {
    asm volatile("ldmatrix.sync.aligned.m8n8.x4.trans.shared.b16 {%0,%1,%2,%3}, [%4];"
                 : "=r"(r[0]), "=r"(r[1]), "=r"(r[2]), "=r"(r[3]) : "r"(addr));
}
__device__ __forceinline__ void mma_f16(float* c, const uint32_t* a, const uint32_t* b) {
    asm volatile(
        "mma.sync.aligned.m16n8k16.row.col.f32.f16.f16.f32 "
        "{%0,%1,%2,%3}, {%4,%5,%6,%7}, {%8,%9}, {%0,%1,%2,%3};"
        : "+f"(c[0]), "+f"(c[1]), "+f"(c[2]), "+f"(c[3])
        : "r"(a[0]), "r"(a[1]), "r"(a[2]), "r"(a[3]), "r"(b[0]), "r"(b[1]));
}
__device__ __forceinline__ void mma_f16_b2(float* c, const uint32_t* a,
                                           uint32_t b0, uint32_t b1) {
    uint32_t b[2] = {b0, b1};
    mma_f16(c, a, b);
}
__device__ __forceinline__ void cp_async16(uint32_t dst, const void* src) {
    asm volatile("cp.async.cg.shared.global [%0], [%1], 16;"
                 :: "r"(dst), "l"(src));
}
__device__ __forceinline__ void cp_commit() {
    asm volatile("cp.async.commit_group;" ::: "memory");
}
template <int N> __device__ __forceinline__ void cp_wait() {
    asm volatile("cp.async.wait_group %0;" :: "n"(N) : "memory");
}
__device__ __forceinline__ uint32_t pack2h(float a, float b) {
    __half2 t = __floats2half2_rn(a, b);
    return *(uint32_t*)&t;
}

// ---------------------------------------------------------------------------
// Merged fp32 -> fp16 convert for all 5 tensors.
// ---------------------------------------------------------------------------
__global__ void convert_all_kernel(
    const float* __restrict__ hidden, __half* __restrict__ h_h,
    const float* __restrict__ q_w, __half* __restrict__ qw_h,
    const float* __restrict__ k_w, __half* __restrict__ kw_h,
    const float* __restrict__ v_w, __half* __restrict__ vw_h,
    const float* __restrict__ o_w, __half* __restrict__ ow_h)
{
    int blk = blockIdx.x;
    const float* x; __half* y; int base;
    if (blk < 2048)      { x = hidden; y = h_h;  base = blk; }
    else if (blk < 3072) { x = q_w;    y = qw_h; base = blk - 2048; }
    else if (blk < 3328) { x = k_w;    y = kw_h; base = blk - 3072; }
    else if (blk < 3584) { x = v_w;    y = vw_h; base = blk - 3328; }
    else                 { x = o_w;    y = ow_h; base = blk - 3584; }
    long i = ((long)base * 256 + threadIdx.x) << 4;
    float4 a = *(const float4*)(x + i);
    float4 b = *(const float4*)(x + i + 4);
    float4 c = *(const float4*)(x + i + 8);
    float4 d = *(const float4*)(x + i + 12);
    uint4 u0, u1;
    u0.x = pack2h(a.x, a.y); u0.y = pack2h(a.z, a.w);
    u0.z = pack2h(b.x, b.y); u0.w = pack2h(b.z, b.w);
    u1.x = pack2h(c.x, c.y); u1.y = pack2h(c.z, c.w);
    u1.z = pack2h(d.x, d.y); u1.w = pack2h(d.z, d.w);
    *(uint4*)(y + i) = u0;
    *(uint4*)(y + i + 8) = u1;
}

// ---------------------------------------------------------------------------
// Pipelined 1-term fp16 GEMM core. Block tile 128x128, BK=64, 2-stage
// cp.async, ONE __syncthreads per K-tile, B-fragments double-buffered
// across ks-steps for ldsm->MMA latency hiding.
// Stage layout: A [0,18432), B [18432,36864). Stage stride 36864.
// ---------------------------------------------------------------------------
#define SSTR 72
#define MAT_BYTES 18432
#define STG_BYTES 36864
#define GSMEM_BYTES (2 * STG_BYTES)   // 73728

struct GemmAcc { float a[2][8][4]; };

__device__ __forceinline__ void gemm_stage_load(
    uint32_t sdst, const __half* Ah, const __half* Bh,
    int row0, int col0, int K, int kof, int tid)
{
#pragma unroll
    for (int j = 0; j < 4; j++) {
        int i = tid + j * 256;
        int r = i >> 3, c = (i & 7) * 8;
        uint32_t so = (uint32_t)(r * SSTR + c) * 2;
        cp_async16(sdst + so,             Ah + (long)(row0 + r) * K + kof + c);
        cp_async16(sdst + MAT_BYTES + so, Bh + (long)(col0 + r) * K + kof + c);
    }
    cp_commit();
}

__device__ __forceinline__ void gemm_core(
    char* smem, const __half* Ah, const __half* Bh,
    int row0, int col0, int K, int tid, int wm, int wn, GemmAcc& A)
{
#pragma unroll
    for (int mt = 0; mt < 2; mt++)
#pragma unroll
        for (int nt = 0; nt < 8; nt++)
#pragma unroll
            for (int j = 0; j < 4; j++) A.a[mt][nt][j] = 0.0f;

    const int lane = tid & 31;
    const uint32_t sb = smem_u32(smem);
    const int x4_r = (lane & 7) + ((lane >> 3) & 1) * 8;
    const int x4_c = (lane >> 4) * 8;

    const int niter = K / 64;

    gemm_stage_load(sb, Ah, Bh, row0, col0, K, 0, tid);

    uint32_t bb[2][4][4];   // B fragments, double-buffered across ks

    for (int kt = 0; kt < niter; kt++) {
        cp_wait<0>();
        __syncthreads();   // stage kt ready; all reads of the other stage done

        if (kt + 1 < niter) {
            gemm_stage_load(sb + (uint32_t)((kt + 1) & 1) * STG_BYTES,
                            Ah, Bh, row0, col0, K, (kt + 1) * 64, tid);
        }

        const uint32_t aA = sb + (uint32_t)(kt & 1) * STG_BYTES;
        const uint32_t aB = aA + MAT_BYTES;

        // preload B fragments for ks = 0
#pragma unroll
        for (int nt2 = 0; nt2 < 4; nt2++) {
            uint32_t boff = (uint32_t)((wn + nt2 * 16 + x4_r) * SSTR + x4_c) * 2;
            ldsm_x4(bb[0][nt2], aB + boff);
        }

#pragma unroll
        for (int ks = 0; ks < 4; ks++) {
            uint32_t ah[2][4];
#pragma unroll
            for (int mt = 0; mt < 2; mt++) {
                uint32_t off = (uint32_t)((wm + mt * 16 + x4_r) * SSTR + ks * 16 + x4_c) * 2;
                ldsm_x4(ah[mt], aA + off);
            }
            // prefetch next ks's B fragments before issuing MMAs
            if (ks < 3) {
#pragma unroll
                for (int nt2 = 0; nt2 < 4; nt2++) {
                    uint32_t boff = (uint32_t)((wn + nt2 * 16 + x4_r) * SSTR
                                               + (ks + 1) * 16 + x4_c) * 2;
                    ldsm_x4(bb[(ks + 1) & 1][nt2], aB + boff);
                }
            }
            const uint32_t (*bc)[4] = bb[ks & 1];
#pragma unroll
            for (int nt2 = 0; nt2 < 4; nt2++) {
#pragma unroll
                for (int mt = 0; mt < 2; mt++) {
                    mma_f16_b2(A.a[mt][2 * nt2],     ah[mt], bc[nt2][0], bc[nt2][2]);
                    mma_f16_b2(A.a[mt][2 * nt2 + 1], ah[mt], bc[nt2][1], bc[nt2][3]);
                }
            }
        }
    }
    // NOTE: no trailing sync — epilogues that reuse smem must sync first.
}

// ---------------------------------------------------------------------------
// Fused QKV projection. grid = (24, 32).
// ---------------------------------------------------------------------------
__global__ __launch_bounds__(256, 2) void qkv_gemm_kernel(
    const __half* __restrict__ Ah,
    const __half* __restrict__ QWh, const __half* __restrict__ KWh,
    const __half* __restrict__ VWh,
    const float* __restrict__ q_b, const float* __restrict__ k_b,
    const float* __restrict__ v_b,
    __half* __restrict__ Qo, __half* __restrict__ Ko, __half* __restrict__ Vo,
    const float* __restrict__ cosp, const float* __restrict__ sinp)
{
    extern __shared__ __align__(16) char smem[];

    const int bx = blockIdx.x;
    const __half* Bh;
    const float* bias;
    __half* Chi;
    int N, col0, mode;
    float scale;
    if (bx < 16) {
        Bh = QWh; bias = q_b; Chi = Qo;
        N = NH * HD; col0 = bx * 128; mode = 1; scale = SCALE_F;
    } else if (bx < 20) {
        Bh = KWh; bias = k_b; Chi = Ko;
        N = NKV * HD; col0 = (bx - 16) * 128; mode = 1; scale = 1.0f;
    } else {
        Bh = VWh; bias = v_b; Chi = Vo;
        N = NKV * HD; col0 = (bx - 20) * 128; mode = 2; scale = 1.0f;
    }

    const int tid  = threadIdx.x;
    const int wid  = tid >> 5;
    const int lane = tid & 31;
    const int wm   = (wid >> 1) * 32;
    const int wn   = (wid & 1) * 64;
    const int row0 = blockIdx.y * 128;

    GemmAcc A;
    gemm_core(smem, Ah, Bh, row0, col0, HH, tid, wm, wn, A);

    if (mode == 2) {
        const int em = row0 + wm + (lane >> 2);
        const int enl = wn + (lane & 3) * 2;
#pragma unroll
        for (int mt = 0; mt < 2; mt++) {
#pragma unroll
            for (int nt = 0; nt < 8; nt++) {
                int n = col0 + enl + nt * 8;
                float b0 = bias[n], b1 = bias[n + 1];
                long o0 = (long)(em + mt * 16) * N + n;
                long o1 = (long)(em + mt * 16 + 8) * N + n;
                *(uint32_t*)&Chi[o0] = pack2h(A.a[mt][nt][0] + b0, A.a[mt][nt][1] + b1);
                *(uint32_t*)&Chi[o1] = pack2h(A.a[mt][nt][2] + b0, A.a[mt][nt][3] + b1);
            }
        }
    } else {
        float* buf = (float*)smem;
        const int r0l = lane >> 2;
        const int c0l = (lane & 3) * 2;
#pragma unroll
        for (int hf = 0; hf < 2; hf++) {
            __syncthreads();
            int slotA = (wid >> 1) * 16 + r0l;
#pragma unroll
            for (int nt = 0; nt < 8; nt++) {
                int cc2 = wn + nt * 8 + c0l;
                float b0 = bias[col0 + cc2];
                float b1 = bias[col0 + cc2 + 1];
                buf[slotA * 132 + cc2]           = A.a[hf][nt][0] + b0;
                buf[slotA * 132 + cc2 + 1]       = A.a[hf][nt][1] + b1;
                buf[(slotA + 8) * 132 + cc2]     = A.a[hf][nt][2] + b0;
                buf[(slotA + 8) * 132 + cc2 + 1] = A.a[hf][nt][3] + b1;
            }
            __syncthreads();
            for (int i = tid; i < 4096; i += 256) {
                int slot = i >> 6, d = i & 63;
                int grow = row0 + (slot >> 4) * 32 + hf * 16 + (slot & 15);
                float x1 = buf[slot * 132 + d];
                float x2 = buf[slot * 132 + d + 64];
                long cb = (long)grow * HD;
                float c1 = cosp[cb + d],      s1 = sinp[cb + d];
                float c2 = cosp[cb + d + 64], s2 = sinp[cb + d + 64];
                float y1 = (x1 * c1 - x2 * s1) * scale;
                float y2 = (x2 * c2 + x1 * s2) * scale;
                long o1 = (long)grow * N + col0 + d;
                Chi[o1]      = __float2half_rn(y1);
                Chi[o1 + 64] = __float2half_rn(y2);
            }
        }
    }
}

// ---------------------------------------------------------------------------
// Output projection: fp32 out, no bias. grid = (16, 32).
// ---------------------------------------------------------------------------
__global__ __launch_bounds__(256, 2) void o_gemm_kernel(
    const __half* __restrict__ Ah, const __half* __restrict__ Bh,
    float* __restrict__ Cf, int M, int N, int K)
{
    extern __shared__ __align__(16) char smem[];
    const int tid  = threadIdx.x;
    const int wid  = tid >> 5;
    const int lane = tid & 31;
    const int wm   = (wid >> 1) * 32;
    const int wn   = (wid & 1) * 64;
    const int row0 = blockIdx.y * 128;
    const int col0 = blockIdx.x * 128;

    GemmAcc A;
    gemm_core(smem, Ah, Bh, row0, col0, K, tid, wm, wn, A);

    const int em = row0 + wm + (lane >> 2);
    const int en = col0 + wn + (lane & 3) * 2;
#pragma unroll
    for (int mt = 0; mt < 2; mt++) {
#pragma unroll
        for (int nt = 0; nt < 8; nt++) {
            int n = en + nt * 8;
            float2 v0, v1;
            v0.x = A.a[mt][nt][0]; v0.y = A.a[mt][nt][1];
            v1.x = A.a[mt][nt][2]; v1.y = A.a[mt][nt][3];
            *(float2*)&Cf[(long)(em + mt * 16) * N + n] = v0;
            *(float2*)&Cf[(long)(em + mt * 16 + 8) * N + n] = v1;
        }
    }
}

// ---------------------------------------------------------------------------
// FA2-style flash attention (unchanged — R10/R11 WIN config).
// smem map: Q [0,34816) | st0 K [34816,52224) V [52224,69632)
//           | st1 K [69632,87040) V [87040,104448). Stage stride 34816.
// ---------------------------------------------------------------------------
#define FQSTR 136
#define FOQ 0u
#define FOK 34816u
#define FKVB 34816u
#define FOV 52224u
#define FSM_BYTES 104448u

__global__ __launch_bounds__(256) void flash_mma_kernel(
    const __half* __restrict__ Qh, const __half* __restrict__ Kh,
    const __half* __restrict__ Vh, __half* __restrict__ AOh)
{
    extern __shared__ char fsm2[];
    const uint32_t sb = smem_u32(fsm2);
    const uint32_t aQ = sb + FOQ;

    const int it = (int)gridDim.x - 1 - (int)blockIdx.x;
    const int h  = blockIdx.y;
    const int b  = blockIdx.z;
    const int g  = h / NREP;
    const int tid  = threadIdx.x;
    const int wid  = tid >> 5;
    const int lane = tid & 31;
    const int wq   = wid * 16;
    const int i0 = it * 128;
    const int m0 = b * SS + i0;

    for (int i = tid; i < 2048; i += 256) {
        int r = i >> 4, c = (i & 15) * 8;
        long gi = (long)(m0 + r) * (NH * HD) + h * HD + c;
        *(uint4*)(fsm2 + FOQ + (r * FQSTR + c) * 2) = *(const uint4*)&Qh[gi];
    }

    const int ntiles = 2 * it + 2;

    {
        uint32_t kd = sb + FOK, vd = sb + FOV;
        for (int i = tid; i < 1024; i += 256) {
            int r = i >> 4, c = (i & 15) * 8;
            long gi = (long)(b * SS + r) * (NKV * HD) + g * HD + c;
            cp_async16(kd + (r * FQSTR + c) * 2, Kh + gi);
            cp_async16(vd + (r * FQSTR + c) * 2, Vh + gi);
        }
        cp_commit();
    }

    float out[16][4];
#pragma unroll
    for (int nt = 0; nt < 16; nt++)
#pragma unroll
        for (int j = 0; j < 4; j++) out[nt][j] = 0.0f;
    float m0r = -1e30f, m1r = -1e30f, l0 = 0.0f, l1 = 0.0f;

    const int r0    = lane >> 2;
    const int qcol2 = (lane & 3) * 2;
    const int x4_r = (lane & 7) + ((lane >> 3) & 1) * 8;
    const int x4_c = (lane >> 4) * 8;

    for (int jt = 0; jt < ntiles; jt++) {
        const int j0 = jt * 64;
        const uint32_t aK = sb + FOK + (uint32_t)(jt & 1) * FKVB;
        const uint32_t aV = sb + FOV + (uint32_t)(jt & 1) * FKVB;

        cp_wait<0>();
        __syncthreads();

        if (jt + 1 < ntiles) {
            uint32_t kd = sb + FOK + (uint32_t)((jt + 1) & 1) * FKVB;
            uint32_t vd = sb + FOV + (uint32_t)((jt + 1) & 1) * FKVB;
            int jn = (jt + 1) * 64;
            for (int i = tid; i < 1024; i += 256) {
                int r = i >> 4, c = (i & 15) * 8;
                long gi = (long)(b * SS + jn + r) * (NKV * HD) + g * HD + c;
                cp_async16(kd + (r * FQSTR + c) * 2, Kh + gi);
                cp_async16(vd + (r * FQSTR + c) * 2, Vh + gi);
            }
            cp_commit();
        }

        float sc[8][4];
#pragma unroll
        for (int nt = 0; nt < 8; nt++)
#pragma unroll
            for (int j = 0; j < 4; j++) sc[nt][j] = 0.0f;

#pragma unroll
        for (int kg = 0; kg < 8; kg++) {
            uint32_t qh[4];
            ldsm_x4(qh, aQ + (uint32_t)((wq + x4_r) * FQSTR + kg * 16 + x4_c) * 2);
#pragma unroll
            for (int nt2 = 0; nt2 < 4; nt2++) {
                uint32_t kb[4];
                ldsm_x4(kb, aK + (uint32_t)((nt2 * 16 + x4_r) * FQSTR + kg * 16 + x4_c) * 2);
                mma_f16_b2(sc[2 * nt2],     qh, kb[0], kb[2]);
                mma_f16_b2(sc[2 * nt2 + 1], qh, kb[1], kb[3]);
            }
        }

        if (j0 + 63 > i0 + wq) {
#pragma unroll
            for (int nt = 0; nt < 8; nt++) {
                int colb = j0 + nt * 8 + qcol2;
                int rowa = i0 + wq + r0;
#pragma unroll
                for (int j = 0; j < 4; j++) {
                    int col = colb + (j & 1);
                    int row = rowa + (j >= 2 ? 8 : 0);
                    if (col > row) sc[nt][j] = -1e30f;
                }
            }
        }

        float mx0 = -1e30f, mx1 = -1e30f;
#pragma unroll
        for (int nt = 0; nt < 8; nt++) {
            mx0 = fmaxf(mx0, fmaxf(sc[nt][0], sc[nt][1]));
            mx1 = fmaxf(mx1, fmaxf(sc[nt][2], sc[nt][3]));
        }
        mx0 = fmaxf(mx0, __shfl_xor_sync(0xffffffffu, mx0, 1));
        mx0 = fmaxf(mx0, __shfl_xor_sync(0xffffffffu, mx0, 2));
        mx1 = fmaxf(mx1, __shfl_xor_sync(0xffffffffu, mx1, 1));
        mx1 = fmaxf(mx1, __shfl_xor_sync(0xffffffffu, mx1, 2));

        float mn0 = fmaxf(m0r, mx0);
        float mn1 = fmaxf(m1r, mx1);
        float al0 = __expf(m0r - mn0);
        float al1 = __expf(m1r - mn1);
        m0r = mn0; m1r = mn1;

        float s0 = 0.0f, s1 = 0.0f;
#pragma unroll
        for (int nt = 0; nt < 8; nt++) {
            sc[nt][0] = __expf(sc[nt][0] - mn0);
            sc[nt][1] = __expf(sc[nt][1] - mn0);
            sc[nt][2] = __expf(sc[nt][2] - mn1);
            sc[nt][3] = __expf(sc[nt][3] - mn1);
            s0 += sc[nt][0] + sc[nt][1];
            s1 += sc[nt][2] + sc[nt][3];
        }
        s0 += __shfl_xor_sync(0xffffffffu, s0, 1);
        s0 += __shfl_xor_sync(0xffffffffu, s0, 2);
        s1 += __shfl_xor_sync(0xffffffffu, s1, 1);
        s1 += __shfl_xor_sync(0xffffffffu, s1, 2);
        l0 = l0 * al0 + s0;
        l1 = l1 * al1 + s1;

#pragma unroll
        for (int nt = 0; nt < 16; nt++) {
            out[nt][0] *= al0; out[nt][1] *= al0;
            out[nt][2] *= al1; out[nt][3] *= al1;
        }

#pragma unroll
        for (int kg = 0; kg < 4; kg++) {
            uint32_t pa[4];
            pa[0] = pack2h(sc[2 * kg][0],     sc[2 * kg][1]);
            pa[1] = pack2h(sc[2 * kg][2],     sc[2 * kg][3]);
            pa[2] = pack2h(sc[2 * kg + 1][0], sc[2 * kg + 1][1]);
            pa[3] = pack2h(sc[2 * kg + 1][2], sc[2 * kg + 1][3]);
#pragma unroll
            for (int ntp = 0; ntp < 8; ntp++) {
                uint32_t vh4[4];
                ldsm_x4_t(vh4, aV + (uint32_t)((kg * 16 + x4_r) * FQSTR + ntp * 16 + x4_c) * 2);
                mma_f16(out[2 * ntp],     pa, &vh4[0]);
                mma_f16(out[2 * ntp + 1], pa, &vh4[2]);
            }
        }
    }

    float inv0 = 1.0f / l0;
    float inv1 = 1.0f / l1;
#pragma unroll
    for (int nt = 0; nt < 16; nt++) {
        int col = nt * 8 + qcol2;
        long ra = (long)(m0 + wq + r0) * (NH * HD) + h * HD + col;
        long rb = (long)(m0 + wq + r0 + 8) * (NH * HD) + h * HD + col;
        *(uint32_t*)&AOh[ra] = pack2h(out[nt][0] * inv0, out[nt][1] * inv0);
        *(uint32_t*)&AOh[rb] = pack2h(out[nt][2] * inv1, out[nt][3] * inv1);
    }
}

// ---------------------------------------------------------------------------
// Launcher
// ---------------------------------------------------------------------------
extern "C" void kernel_launch(void* const* d_in, const int* in_sizes, int n_in,
                              void* d_out, int out_size)
{
    const float* hidden = (const float*)d_in[0];
    const float* cosp   = (const float*)d_in[1];
    const float* sinp   = (const float*)d_in[2];
    const float* q_w = (const float*)d_in[4];
    const float* q_b = (const float*)d_in[5];
    const float* k_w = (const float*)d_in[6];
    const float* k_b = (const float*)d_in[7];
    const float* v_w = (const float*)d_in[8];
    const float* v_b = (const float*)d_in[9];
    const float* o_w = (const float*)d_in[10];
    float* out = (float*)d_out;

    __half *h_h, *qw_h, *kw_h, *vw_h, *ow_h, *qh, *kh, *vh, *ao_h;
    cudaGetSymbolAddress((void**)&h_h, g_h_h);
    cudaGetSymbolAddress((void**)&qw_h, g_qw_h);
    cudaGetSymbolAddress((void**)&kw_h, g_kw_h);
    cudaGetSymbolAddress((void**)&vw_h, g_vw_h);
    cudaGetSymbolAddress((void**)&ow_h, g_ow_h);
    cudaGetSymbolAddress((void**)&qh, g_qh);
    cudaGetSymbolAddress((void**)&kh, g_kh);
    cudaGetSymbolAddress((void**)&vh, g_vh);
    cudaGetSymbolAddress((void**)&ao_h, g_ao_h);

    // One merged convert launch
    convert_all_kernel<<<4608, 256>>>(hidden, h_h, q_w, qw_h, k_w, kw_h,
                                      v_w, vw_h, o_w, ow_h);

    // Fused QKV projection
    cudaFuncSetAttribute(qkv_gemm_kernel,
                         cudaFuncAttributeMaxDynamicSharedMemorySize, GSMEM_BYTES);
    qkv_gemm_kernel<<<dim3(24, M_TOK / 128), 256, GSMEM_BYTES>>>(
        h_h, qw_h, kw_h, vw_h, q_b, k_b, v_b, qh, kh, vh, cosp, sinp);

    // Flash attention
    cudaFuncSetAttribute(flash_mma_kernel,
                         cudaFuncAttributeMaxDynamicSharedMemorySize, FSM_BYTES);
    flash_mma_kernel<<<dim3(SS / 128, NH, BB), 256, FSM_BYTES>>>(
        qh, kh, vh, ao_h);

    // Output projection
    cudaFuncSetAttribute(o_gemm_kernel,
                         cudaFuncAttributeMaxDynamicSharedMemorySize, GSMEM_BYTES);
    o_gemm_kernel<<<dim3(HH / 128, M_TOK / 128), 256, GSMEM_BYTES>>>(
        ao_h, ow_h, out, M_TOK, HH, NH * HD);
}